// round 1
// baseline (speedup 1.0000x reference)
#include <cuda_runtime.h>
#include <cuda_bf16.h>
#include <math.h>

#define Tn   2048   // tokens = B*S
#define Dm   1024   // model dim
#define Ne   64     // routed experts
#define TOPK 8
#define Hh   256    // routed inter dim
#define ESn  2      // shared experts
#define HSn  2048   // shared inter dim

// ---------------- static scratch (allocation-free rule) ----------------
__device__ float g_topw[Tn * TOPK];
__device__ int   g_topi[Tn * TOPK];
__device__ int   g_slot2pair[Tn * TOPK];
__device__ int   g_count[Ne];
__device__ int   g_offset[Ne];
__device__ int   g_cursor[Ne];
__device__ int   g_pair_token[Tn * TOPK];
__device__ float g_pair_w[Tn * TOPK];
__device__ float g_H[(size_t)Tn * TOPK * Hh];          // 16.8 MB
__device__ float g_pairout[(size_t)Tn * TOPK * Dm];    // 67 MB
__device__ float g_Hs[(size_t)ESn * Tn * HSn];         // 33.6 MB
__device__ float g_sharedout[(size_t)ESn * Tn * Dm];   // 16.8 MB

__device__ __forceinline__ float silu_f(float c) {
    return c / (1.0f + __expf(-c));
}

// ---------------- K0: zero expert counts ----------------
__global__ void zero_counts_kernel() {
    if (threadIdx.x < Ne) g_count[threadIdx.x] = 0;
}

// ---------------- K1: router (logits GEMM + top-8 + softmax) ----------------
// block = 256 threads handles 32 tokens x 64 experts
__global__ void __launch_bounds__(256) router_kernel(
    const float* __restrict__ x, const float* __restrict__ rw,
    const float* __restrict__ rb)
{
    __shared__ float xs[64][33];   // [dd][token]
    __shared__ float ws[64][65];   // [dd][expert]
    __shared__ float lg[32][65];   // [token][expert]
    int tid = threadIdx.x;
    int tbase = blockIdx.x * 32;
    int e  = tid & 63;
    int tg = tid >> 6;             // 0..3

    float acc[8];
#pragma unroll
    for (int i = 0; i < 8; i++) acc[i] = 0.0f;

    for (int d0 = 0; d0 < Dm; d0 += 64) {
#pragma unroll
        for (int q = 0; q < 8; q++) {      // 32x64 x-tile
            int idx = tid + q * 256;
            int t = idx >> 6, dd = idx & 63;
            xs[dd][t] = x[(size_t)(tbase + t) * Dm + d0 + dd];
        }
#pragma unroll
        for (int q = 0; q < 16; q++) {     // 64x64 w-tile
            int idx = tid + q * 256;
            int dd = idx >> 6, ee = idx & 63;
            ws[dd][ee] = rw[(size_t)(d0 + dd) * Ne + ee];
        }
        __syncthreads();
#pragma unroll
        for (int dd = 0; dd < 64; dd++) {
            float wv = ws[dd][e];
#pragma unroll
            for (int i = 0; i < 8; i++) acc[i] += xs[dd][tg + 4 * i] * wv;
        }
        __syncthreads();
    }
#pragma unroll
    for (int i = 0; i < 8; i++) lg[tg + 4 * i][e] = acc[i] + rb[e];
    __syncthreads();

    if (tid < 32) {
        int t = tid;
        float vals[TOPK]; int idxs[TOPK];
#pragma unroll
        for (int p = 0; p < TOPK; p++) {
            float best = -1e30f; int bi = 0;
            for (int ee = 0; ee < Ne; ee++) {
                float v = lg[t][ee];
                if (v > best) { best = v; bi = ee; }
            }
            vals[p] = best; idxs[p] = bi; lg[t][bi] = -1e30f;
        }
        // softmax over the 8 kept logits == renormalized top-k of full softmax
        float m = vals[0];
        float w[TOPK], s = 0.0f;
#pragma unroll
        for (int p = 0; p < TOPK; p++) { w[p] = __expf(vals[p] - m); s += w[p]; }
        float inv = 1.0f / s;
        int gt = tbase + t;
#pragma unroll
        for (int p = 0; p < TOPK; p++) {
            g_topw[gt * TOPK + p] = w[p] * inv;
            g_topi[gt * TOPK + p] = idxs[p];
            atomicAdd(&g_count[idxs[p]], 1);
        }
    }
}

// ---------------- K2: exclusive scan over 64 counts ----------------
__global__ void scan_kernel() {
    if (threadIdx.x == 0) {
        int run = 0;
        for (int e = 0; e < Ne; e++) {
            g_offset[e] = run; g_cursor[e] = run; run += g_count[e];
        }
    }
}

// ---------------- K3: compact (token, weight) pairs per expert ----------------
__global__ void fill_kernel() {
    int t = blockIdx.x * 256 + threadIdx.x;
    if (t < Tn) {
#pragma unroll
        for (int j = 0; j < TOPK; j++) {
            int e = g_topi[t * TOPK + j];
            int pos = atomicAdd(&g_cursor[e], 1);
            g_pair_token[pos] = t;
            g_pair_w[pos] = g_topw[t * TOPK + j];
            g_slot2pair[t * TOPK + j] = pos;
        }
    }
}

// 4x4 micro-tile FMA
#define FMA16(av, bv)                                                   \
    acc[0][0] += av.x * bv.x; acc[0][1] += av.x * bv.y;                 \
    acc[0][2] += av.x * bv.z; acc[0][3] += av.x * bv.w;                 \
    acc[1][0] += av.y * bv.x; acc[1][1] += av.y * bv.y;                 \
    acc[1][2] += av.y * bv.z; acc[1][3] += av.y * bv.w;                 \
    acc[2][0] += av.z * bv.x; acc[2][1] += av.z * bv.y;                 \
    acc[2][2] += av.z * bv.z; acc[2][3] += av.z * bv.w;                 \
    acc[3][0] += av.w * bv.x; acc[3][1] += av.w * bv.y;                 \
    acc[3][2] += av.w * bv.z; acc[3][3] += av.w * bv.w;

// ---------------- K4: routed GEMM1  H = silu(Xg @ W1[e] + b1[e]) ----------------
// grid: (pairTiles=32, Hh/64=4, Ne)
__global__ void __launch_bounds__(256) gemm1_routed(
    const float* __restrict__ x, const float* __restrict__ w1,
    const float* __restrict__ b1)
{
    int e = blockIdx.z;
    int cnt = g_count[e];
    int rowBase = blockIdx.x * 64;
    if (rowBase >= cnt) return;
    int off = g_offset[e];
    int h0 = blockIdx.y * 64;
    const float* W = w1 + (size_t)e * Dm * Hh;

    __shared__ float As[16][68];
    __shared__ float Bs[16][68];
    __shared__ int   toks[64];
    int tid = threadIdx.x;
    if (tid < 64) {
        int r = rowBase + tid;
        toks[tid] = (r < cnt) ? g_pair_token[off + r] : -1;
    }
    __syncthreads();

    float acc[4][4] = {};
    int tr = tid >> 4, tc = tid & 15;
    int lr = tid >> 2, lk = (tid & 3) * 4;
    int bd = tid >> 4, bn = (tid & 15) * 4;
    int tokA = toks[lr];

    for (int k0 = 0; k0 < Dm; k0 += 16) {
        float4 a = make_float4(0.f, 0.f, 0.f, 0.f);
        if (tokA >= 0) a = *(const float4*)(x + (size_t)tokA * Dm + k0 + lk);
        float4 b = *(const float4*)(W + (size_t)(k0 + bd) * Hh + h0 + bn);
        As[lk + 0][lr] = a.x; As[lk + 1][lr] = a.y;
        As[lk + 2][lr] = a.z; As[lk + 3][lr] = a.w;
        *(float4*)&Bs[bd][bn] = b;
        __syncthreads();
#pragma unroll
        for (int kk = 0; kk < 16; kk++) {
            float4 av = *(const float4*)&As[kk][tr * 4];
            float4 bv = *(const float4*)&Bs[kk][tc * 4];
            FMA16(av, bv);
        }
        __syncthreads();
    }
    float4 bb = *(const float4*)(b1 + e * Hh + h0 + tc * 4);
#pragma unroll
    for (int i = 0; i < 4; i++) {
        int r = rowBase + tr * 4 + i;
        if (r < cnt) {
            float4 o;
            o.x = silu_f(acc[i][0] + bb.x);
            o.y = silu_f(acc[i][1] + bb.y);
            o.z = silu_f(acc[i][2] + bb.z);
            o.w = silu_f(acc[i][3] + bb.w);
            *(float4*)(g_H + (size_t)(off + r) * Hh + h0 + tc * 4) = o;
        }
    }
}

// ---------------- K5: routed GEMM2  pairout = w * (H @ W2[e] + b2[e]) ----------------
// grid: (32, Dm/64=16, Ne)
__global__ void __launch_bounds__(256) gemm2_routed(
    const float* __restrict__ w2, const float* __restrict__ b2)
{
    int e = blockIdx.z;
    int cnt = g_count[e];
    int rowBase = blockIdx.x * 64;
    if (rowBase >= cnt) return;
    int off = g_offset[e];
    int n0 = blockIdx.y * 64;
    const float* W = w2 + (size_t)e * Hh * Dm;

    __shared__ float As[16][68];
    __shared__ float Bs[16][68];
    __shared__ float wts[64];
    int tid = threadIdx.x;
    if (tid < 64) {
        int r = rowBase + tid;
        wts[tid] = (r < cnt) ? g_pair_w[off + r] : 0.0f;
    }
    __syncthreads();

    float acc[4][4] = {};
    int tr = tid >> 4, tc = tid & 15;
    int lr = tid >> 2, lk = (tid & 3) * 4;
    int bd = tid >> 4, bn = (tid & 15) * 4;
    bool rowOK = (rowBase + lr) < cnt;

    for (int k0 = 0; k0 < Hh; k0 += 16) {
        float4 a = make_float4(0.f, 0.f, 0.f, 0.f);
        if (rowOK) a = *(const float4*)(g_H + (size_t)(off + rowBase + lr) * Hh + k0 + lk);
        float4 b = *(const float4*)(W + (size_t)(k0 + bd) * Dm + n0 + bn);
        As[lk + 0][lr] = a.x; As[lk + 1][lr] = a.y;
        As[lk + 2][lr] = a.z; As[lk + 3][lr] = a.w;
        *(float4*)&Bs[bd][bn] = b;
        __syncthreads();
#pragma unroll
        for (int kk = 0; kk < 16; kk++) {
            float4 av = *(const float4*)&As[kk][tr * 4];
            float4 bv = *(const float4*)&Bs[kk][tc * 4];
            FMA16(av, bv);
        }
        __syncthreads();
    }
    float4 bb = *(const float4*)(b2 + (size_t)e * Dm + n0 + tc * 4);
#pragma unroll
    for (int i = 0; i < 4; i++) {
        int r = rowBase + tr * 4 + i;
        if (r < cnt) {
            float wv = wts[tr * 4 + i];
            float4 o;
            o.x = (acc[i][0] + bb.x) * wv;
            o.y = (acc[i][1] + bb.y) * wv;
            o.z = (acc[i][2] + bb.z) * wv;
            o.w = (acc[i][3] + bb.w) * wv;
            *(float4*)(g_pairout + (size_t)(off + r) * Dm + n0 + tc * 4) = o;
        }
    }
}

// ---------------- K6: shared GEMM1  Hs = silu(X @ sw1[es] + sb1[es]) ----------------
// grid: (Tn/64=32, HSn/64=32, ESn)
__global__ void __launch_bounds__(256) gemm1_shared(
    const float* __restrict__ x, const float* __restrict__ sw1,
    const float* __restrict__ sb1)
{
    int es = blockIdx.z;
    int row0 = blockIdx.x * 64;
    int n0 = blockIdx.y * 64;
    const float* W = sw1 + (size_t)es * Dm * HSn;

    __shared__ float As[16][68];
    __shared__ float Bs[16][68];
    int tid = threadIdx.x;
    float acc[4][4] = {};
    int tr = tid >> 4, tc = tid & 15;
    int lr = tid >> 2, lk = (tid & 3) * 4;
    int bd = tid >> 4, bn = (tid & 15) * 4;

    for (int k0 = 0; k0 < Dm; k0 += 16) {
        float4 a = *(const float4*)(x + (size_t)(row0 + lr) * Dm + k0 + lk);
        float4 b = *(const float4*)(W + (size_t)(k0 + bd) * HSn + n0 + bn);
        As[lk + 0][lr] = a.x; As[lk + 1][lr] = a.y;
        As[lk + 2][lr] = a.z; As[lk + 3][lr] = a.w;
        *(float4*)&Bs[bd][bn] = b;
        __syncthreads();
#pragma unroll
        for (int kk = 0; kk < 16; kk++) {
            float4 av = *(const float4*)&As[kk][tr * 4];
            float4 bv = *(const float4*)&Bs[kk][tc * 4];
            FMA16(av, bv);
        }
        __syncthreads();
    }
    float4 bb = *(const float4*)(sb1 + (size_t)es * HSn + n0 + tc * 4);
#pragma unroll
    for (int i = 0; i < 4; i++) {
        int r = row0 + tr * 4 + i;
        float4 o;
        o.x = silu_f(acc[i][0] + bb.x);
        o.y = silu_f(acc[i][1] + bb.y);
        o.z = silu_f(acc[i][2] + bb.z);
        o.w = silu_f(acc[i][3] + bb.w);
        *(float4*)(g_Hs + (size_t)es * Tn * HSn + (size_t)r * HSn + n0 + tc * 4) = o;
    }
}

// ---------------- K7: shared GEMM2  sharedout = Hs @ sw2[es] + sb2[es] ----------------
// grid: (32, Dm/64=16, ESn)
__global__ void __launch_bounds__(256) gemm2_shared(
    const float* __restrict__ sw2, const float* __restrict__ sb2)
{
    int es = blockIdx.z;
    int row0 = blockIdx.x * 64;
    int n0 = blockIdx.y * 64;
    const float* W = sw2 + (size_t)es * HSn * Dm;
    const float* A = g_Hs + (size_t)es * Tn * HSn;

    __shared__ float As[16][68];
    __shared__ float Bs[16][68];
    int tid = threadIdx.x;
    float acc[4][4] = {};
    int tr = tid >> 4, tc = tid & 15;
    int lr = tid >> 2, lk = (tid & 3) * 4;
    int bd = tid >> 4, bn = (tid & 15) * 4;

    for (int k0 = 0; k0 < HSn; k0 += 16) {
        float4 a = *(const float4*)(A + (size_t)(row0 + lr) * HSn + k0 + lk);
        float4 b = *(const float4*)(W + (size_t)(k0 + bd) * Dm + n0 + bn);
        As[lk + 0][lr] = a.x; As[lk + 1][lr] = a.y;
        As[lk + 2][lr] = a.z; As[lk + 3][lr] = a.w;
        *(float4*)&Bs[bd][bn] = b;
        __syncthreads();
#pragma unroll
        for (int kk = 0; kk < 16; kk++) {
            float4 av = *(const float4*)&As[kk][tr * 4];
            float4 bv = *(const float4*)&Bs[kk][tc * 4];
            FMA16(av, bv);
        }
        __syncthreads();
    }
    float4 bb = *(const float4*)(sb2 + (size_t)es * Dm + n0 + tc * 4);
#pragma unroll
    for (int i = 0; i < 4; i++) {
        int r = row0 + tr * 4 + i;
        float4 o;
        o.x = acc[i][0] + bb.x;
        o.y = acc[i][1] + bb.y;
        o.z = acc[i][2] + bb.z;
        o.w = acc[i][3] + bb.w;
        *(float4*)(g_sharedout + (size_t)es * Tn * Dm + (size_t)r * Dm + n0 + tc * 4) = o;
    }
}

// ---------------- K8: combine (deterministic fixed-order sum) ----------------
// one block per token, 256 threads = 256 float4 columns
__global__ void __launch_bounds__(256) combine_kernel(float* __restrict__ out) {
    int t = blockIdx.x;
    int tid = threadIdx.x;
    __shared__ int sp[TOPK];
    if (tid < TOPK) sp[tid] = g_slot2pair[t * TOPK + tid];
    __syncthreads();

    float4 a = *(const float4*)(g_sharedout + (size_t)t * Dm + tid * 4);
    float4 b = *(const float4*)(g_sharedout + (size_t)Tn * Dm + (size_t)t * Dm + tid * 4);
    float4 acc;
    acc.x = a.x + b.x; acc.y = a.y + b.y; acc.z = a.z + b.z; acc.w = a.w + b.w;
#pragma unroll
    for (int j = 0; j < TOPK; j++) {
        float4 p = *(const float4*)(g_pairout + (size_t)sp[j] * Dm + tid * 4);
        acc.x += p.x; acc.y += p.y; acc.z += p.z; acc.w += p.w;
    }
    *(float4*)(out + (size_t)t * Dm + tid * 4) = acc;
}

// ---------------- launch ----------------
extern "C" void kernel_launch(void* const* d_in, const int* in_sizes, int n_in,
                              void* d_out, int out_size)
{
    const float* x   = (const float*)d_in[0];
    const float* rw  = (const float*)d_in[1];
    const float* rb  = (const float*)d_in[2];
    const float* w1  = (const float*)d_in[3];
    const float* b1  = (const float*)d_in[4];
    const float* w2  = (const float*)d_in[5];
    const float* b2  = (const float*)d_in[6];
    const float* sw1 = (const float*)d_in[7];
    const float* sb1 = (const float*)d_in[8];
    const float* sw2 = (const float*)d_in[9];
    const float* sb2 = (const float*)d_in[10];
    float* out = (float*)d_out;

    zero_counts_kernel<<<1, 64>>>();
    router_kernel<<<Tn / 32, 256>>>(x, rw, rb);
    scan_kernel<<<1, 32>>>();
    fill_kernel<<<(Tn + 255) / 256, 256>>>();
    gemm1_routed<<<dim3(32, Hh / 64, Ne), 256>>>(x, w1, b1);
    gemm2_routed<<<dim3(32, Dm / 64, Ne), 256>>>(w2, b2);
    gemm1_shared<<<dim3(Tn / 64, HSn / 64, ESn), 256>>>(x, sw1, sb1);
    gemm2_shared<<<dim3(Tn / 64, Dm / 64, ESn), 256>>>(sw2, sb2);
    combine_kernel<<<Tn, 256>>>(out);
}

// round 3
// speedup vs baseline: 1.4728x; 1.4728x over previous
#include <cuda_runtime.h>
#include <cuda_bf16.h>
#include <cstdint>
#include <math.h>

#define Tn   2048
#define Dm   1024
#define Ne   64
#define TOPK 8
#define Hh   256
#define ESn  2
#define HSn  2048
#define MAXP (Tn * TOPK)
#define MAXTILES 256

// ---------------- static scratch ----------------
__device__ float g_topw[MAXP];
__device__ int   g_topi[MAXP];
__device__ int   g_slot2pair[MAXP];
__device__ int   g_count[Ne];
__device__ int   g_offset[Ne];
__device__ int   g_cursor[Ne];
__device__ int   g_pair_token[MAXP];
__device__ float g_pair_w[MAXP];
__device__ int   g_ntiles;
__device__ int   g_tile_e[MAXTILES];
__device__ int   g_tile_row[MAXTILES];
__device__ float g_H[(size_t)MAXP * Hh];
__device__ float g_pairout[(size_t)MAXP * Dm];
__device__ float g_Hs[(size_t)ESn * Tn * HSn];
__device__ float g_sharedout[(size_t)ESn * Tn * Dm];

__device__ __forceinline__ float to_tf32(float x) {
    float r; asm("cvt.rna.tf32.f32 %0, %1;" : "=f"(r) : "f"(x)); return r;
}
__device__ __forceinline__ float silu_f(float c) { return c / (1.0f + __expf(-c)); }

__device__ __forceinline__ void mma_tf32(float* d, const float* a, float b0, float b1) {
    asm volatile(
        "mma.sync.aligned.m16n8k8.row.col.f32.tf32.tf32.f32 "
        "{%0,%1,%2,%3}, {%4,%5,%6,%7}, {%8,%9}, {%0,%1,%2,%3};"
        : "+f"(d[0]), "+f"(d[1]), "+f"(d[2]), "+f"(d[3])
        : "r"(__float_as_uint(a[0])), "r"(__float_as_uint(a[1])),
          "r"(__float_as_uint(a[2])), "r"(__float_as_uint(a[3])),
          "r"(__float_as_uint(b0)), "r"(__float_as_uint(b1)));
}

// ---------------- generic 128x128 tf32 mma.sync GEMM tile ----------------
struct GemmArgs {
    const float* A; int lda; const int* gather; int valid;
    const float* W; int ldw; int n0;
    int K;
    const float* bias;
    const float* rowScale;   // nullable
    float* out; int ldo;     // pre-offset to tile row start
    bool silu;
};

// smem layout (floats):
//  [0..127]    rows_s (int)
//  [128..255]  scale_s
//  A0 @256  (128 x pitch36 = 4608)
//  A1 @4864
//  B0 @9472 (32 x pitch136 = 4352)
//  B1 @13824
//  stage reuses @256 (pitch 68)
#define PA 36
#define PB 136
#define SM_FLOATS 18176
#define SM_BYTES  (SM_FLOATS * 4)

__device__ void gemm128(const GemmArgs g) {
    extern __shared__ float sm[];
    int*   rows_s  = (int*)sm;
    float* scale_s = sm + 128;
    float* Abuf[2] = { sm + 256, sm + 4864 };
    float* Bbuf[2] = { sm + 9472, sm + 13824 };
    float* stage   = sm + 256;

    int tid = threadIdx.x;
    int lane = tid & 31, w = tid >> 5;
    int mw = w & 3, nw = w >> 2;
    int gg = lane >> 2, cc = lane & 3;

    if (tid < 128) {
        bool v = tid < g.valid;
        rows_s[tid]  = g.gather ? (v ? g.gather[tid] : -1) : (v ? tid : -1);
        scale_s[tid] = (g.rowScale && v) ? g.rowScale[tid] : 1.0f;
    }
    __syncthreads();

    float acc[2][8][4];
#pragma unroll
    for (int i = 0; i < 2; i++)
#pragma unroll
        for (int j = 0; j < 8; j++)
#pragma unroll
            for (int q = 0; q < 4; q++) acc[i][j][q] = 0.0f;

    const int nch = g.K >> 5;
    float4 pa[4], pb[4];

    // prefetch chunk 0
    {
        int k0 = 0;
#pragma unroll
        for (int i = 0; i < 4; i++) {
            int q = i * 256 + tid; int r = q >> 3, c4 = q & 7;
            int gr = rows_s[r];
            pa[i] = (gr >= 0) ? *(const float4*)(g.A + (size_t)gr * g.lda + k0 + c4 * 4)
                              : make_float4(0.f, 0.f, 0.f, 0.f);
        }
#pragma unroll
        for (int i = 0; i < 4; i++) {
            int q = i * 256 + tid; int k = q >> 5, c4 = q & 31;
            pb[i] = *(const float4*)(g.W + (size_t)(k0 + k) * g.ldw + g.n0 + c4 * 4);
        }
#pragma unroll
        for (int i = 0; i < 4; i++) {
            int q = i * 256 + tid; int r = q >> 3, c4 = q & 7;
            float4 v = pa[i];
            v.x = to_tf32(v.x); v.y = to_tf32(v.y); v.z = to_tf32(v.z); v.w = to_tf32(v.w);
            *(float4*)(Abuf[0] + r * PA + c4 * 4) = v;
        }
#pragma unroll
        for (int i = 0; i < 4; i++) {
            int q = i * 256 + tid; int k = q >> 5, c4 = q & 31;
            float4 v = pb[i];
            v.x = to_tf32(v.x); v.y = to_tf32(v.y); v.z = to_tf32(v.z); v.w = to_tf32(v.w);
            *(float4*)(Bbuf[0] + k * PB + c4 * 4) = v;
        }
    }
    __syncthreads();

    for (int c = 0; c < nch; c++) {
        const float* Ab = Abuf[c & 1];
        const float* Bb = Bbuf[c & 1];
        bool more = (c + 1) < nch;
        if (more) {
            int k0 = (c + 1) << 5;
#pragma unroll
            for (int i = 0; i < 4; i++) {
                int q = i * 256 + tid; int r = q >> 3, c4 = q & 7;
                int gr = rows_s[r];
                pa[i] = (gr >= 0) ? *(const float4*)(g.A + (size_t)gr * g.lda + k0 + c4 * 4)
                                  : make_float4(0.f, 0.f, 0.f, 0.f);
            }
#pragma unroll
            for (int i = 0; i < 4; i++) {
                int q = i * 256 + tid; int k = q >> 5, c4 = q & 31;
                pb[i] = *(const float4*)(g.W + (size_t)(k0 + k) * g.ldw + g.n0 + c4 * 4);
            }
        }
#pragma unroll
        for (int ks = 0; ks < 4; ks++) {
            float a[2][4];
#pragma unroll
            for (int ma = 0; ma < 2; ma++) {
                int r0 = (mw * 32 + ma * 16 + gg) * PA + ks * 8 + cc;
                a[ma][0] = Ab[r0];
                a[ma][1] = Ab[r0 + 8 * PA];
                a[ma][2] = Ab[r0 + 4];
                a[ma][3] = Ab[r0 + 8 * PA + 4];
            }
#pragma unroll
            for (int na = 0; na < 8; na++) {
                int bo = (ks * 8 + cc) * PB + nw * 64 + na * 8 + gg;
                float b0 = Bb[bo];
                float b1 = Bb[bo + 4 * PB];
                mma_tf32(acc[0][na], a[0], b0, b1);
                mma_tf32(acc[1][na], a[1], b0, b1);
            }
        }
        if (more) {
            float* An = Abuf[(c + 1) & 1];
            float* Bn = Bbuf[(c + 1) & 1];
#pragma unroll
            for (int i = 0; i < 4; i++) {
                int q = i * 256 + tid; int r = q >> 3, c4 = q & 7;
                float4 v = pa[i];
                v.x = to_tf32(v.x); v.y = to_tf32(v.y); v.z = to_tf32(v.z); v.w = to_tf32(v.w);
                *(float4*)(An + r * PA + c4 * 4) = v;
            }
#pragma unroll
            for (int i = 0; i < 4; i++) {
                int q = i * 256 + tid; int k = q >> 5, c4 = q & 31;
                float4 v = pb[i];
                v.x = to_tf32(v.x); v.y = to_tf32(v.y); v.z = to_tf32(v.z); v.w = to_tf32(v.w);
                *(float4*)(Bn + k * PB + c4 * 4) = v;
            }
        }
        __syncthreads();
    }

    // epilogue: regs -> (bias, silu, scale) -> smem stage -> coalesced STG
#pragma unroll
    for (int slab = 0; slab < 2; slab++) {
        if (nw == slab) {
#pragma unroll
            for (int ma = 0; ma < 2; ma++) {
#pragma unroll
                for (int na = 0; na < 8; na++) {
                    int r0 = mw * 32 + ma * 16 + gg, r1 = r0 + 8;
                    int col = na * 8 + cc * 2;
                    int n = g.n0 + slab * 64 + col;
                    float bv0 = g.bias[n], bv1 = g.bias[n + 1];
                    float f00 = acc[ma][na][0] + bv0;
                    float f01 = acc[ma][na][1] + bv1;
                    float f10 = acc[ma][na][2] + bv0;
                    float f11 = acc[ma][na][3] + bv1;
                    if (g.silu) {
                        f00 = silu_f(f00); f01 = silu_f(f01);
                        f10 = silu_f(f10); f11 = silu_f(f11);
                    }
                    float s0 = scale_s[r0], s1 = scale_s[r1];
                    *(float2*)(stage + r0 * 68 + col) = make_float2(f00 * s0, f01 * s0);
                    *(float2*)(stage + r1 * 68 + col) = make_float2(f10 * s1, f11 * s1);
                }
            }
        }
        __syncthreads();
        for (int q = tid; q < 128 * 16; q += 256) {
            int r = q >> 4, c4 = q & 15;
            if (r < g.valid) {
                float4 v = *(float4*)(stage + r * 68 + c4 * 4);
                *(float4*)(g.out + (size_t)r * g.ldo + g.n0 + slab * 64 + c4 * 4) = v;
            }
        }
        __syncthreads();
    }
}

// ---------------- GEMM kernel wrappers ----------------
__global__ void __launch_bounds__(256, 1) k_g1_routed(const float* x, const float* w1, const float* b1) {
    int t = blockIdx.x;
    if (t >= g_ntiles) return;
    int e = g_tile_e[t], rb = g_tile_row[t];
    int cnt = g_count[e], off = g_offset[e];
    GemmArgs a;
    a.A = x; a.lda = Dm; a.gather = g_pair_token + off + rb; a.valid = min(128, cnt - rb);
    a.W = w1 + (size_t)e * Dm * Hh; a.ldw = Hh; a.n0 = blockIdx.y * 128;
    a.K = Dm; a.bias = b1 + e * Hh; a.rowScale = nullptr;
    a.out = g_H + (size_t)(off + rb) * Hh; a.ldo = Hh; a.silu = true;
    gemm128(a);
}
__global__ void __launch_bounds__(256, 1) k_g2_routed(const float* w2, const float* b2) {
    int t = blockIdx.x;
    if (t >= g_ntiles) return;
    int e = g_tile_e[t], rb = g_tile_row[t];
    int cnt = g_count[e], off = g_offset[e];
    GemmArgs a;
    a.A = g_H + (size_t)(off + rb) * Hh; a.lda = Hh; a.gather = nullptr; a.valid = min(128, cnt - rb);
    a.W = w2 + (size_t)e * Hh * Dm; a.ldw = Dm; a.n0 = blockIdx.y * 128;
    a.K = Hh; a.bias = b2 + (size_t)e * Dm; a.rowScale = g_pair_w + off + rb;
    a.out = g_pairout + (size_t)(off + rb) * Dm; a.ldo = Dm; a.silu = false;
    gemm128(a);
}
__global__ void __launch_bounds__(256, 1) k_g1_shared(const float* x, const float* sw1, const float* sb1) {
    int es = blockIdx.z, row0 = blockIdx.x * 128;
    GemmArgs a;
    a.A = x + (size_t)row0 * Dm; a.lda = Dm; a.gather = nullptr; a.valid = 128;
    a.W = sw1 + (size_t)es * Dm * HSn; a.ldw = HSn; a.n0 = blockIdx.y * 128;
    a.K = Dm; a.bias = sb1 + (size_t)es * HSn; a.rowScale = nullptr;
    a.out = g_Hs + (size_t)es * Tn * HSn + (size_t)row0 * HSn; a.ldo = HSn; a.silu = true;
    gemm128(a);
}
__global__ void __launch_bounds__(256, 1) k_g2_shared(const float* sw2, const float* sb2) {
    int es = blockIdx.z, row0 = blockIdx.x * 128;
    GemmArgs a;
    a.A = g_Hs + (size_t)es * Tn * HSn + (size_t)row0 * HSn; a.lda = HSn; a.gather = nullptr; a.valid = 128;
    a.W = sw2 + (size_t)es * HSn * Dm; a.ldw = Dm; a.n0 = blockIdx.y * 128;
    a.K = HSn; a.bias = sb2 + (size_t)es * Dm; a.rowScale = nullptr;
    a.out = g_sharedout + (size_t)es * Tn * Dm + (size_t)row0 * Dm; a.ldo = Dm; a.silu = false;
    gemm128(a);
}

// ---------------- routing bookkeeping ----------------
__global__ void zero_counts_kernel() {
    if (threadIdx.x < Ne) g_count[threadIdx.x] = 0;
}

__global__ void __launch_bounds__(256) router_kernel(
    const float* __restrict__ x, const float* __restrict__ rw, const float* __restrict__ rb)
{
    __shared__ float xs[64][33];
    __shared__ float ws[64][65];
    __shared__ float lg[32][65];
    int tid = threadIdx.x;
    int tbase = blockIdx.x * 32;
    int e = tid & 63, tg = tid >> 6;
    float acc[8];
#pragma unroll
    for (int i = 0; i < 8; i++) acc[i] = 0.0f;
    for (int d0 = 0; d0 < Dm; d0 += 64) {
#pragma unroll
        for (int q = 0; q < 8; q++) {
            int idx = tid + q * 256; int t = idx >> 6, dd = idx & 63;
            xs[dd][t] = x[(size_t)(tbase + t) * Dm + d0 + dd];
        }
#pragma unroll
        for (int q = 0; q < 16; q++) {
            int idx = tid + q * 256; int dd = idx >> 6, ee = idx & 63;
            ws[dd][ee] = rw[(size_t)(d0 + dd) * Ne + ee];
        }
        __syncthreads();
#pragma unroll
        for (int dd = 0; dd < 64; dd++) {
            float wv = ws[dd][e];
#pragma unroll
            for (int i = 0; i < 8; i++) acc[i] += xs[dd][tg + 4 * i] * wv;
        }
        __syncthreads();
    }
#pragma unroll
    for (int i = 0; i < 8; i++) lg[tg + 4 * i][e] = acc[i] + rb[e];
    __syncthreads();
    if (tid < 32) {
        int t = tid;
        float vals[TOPK]; int idxs[TOPK];
#pragma unroll
        for (int p = 0; p < TOPK; p++) {
            float best = -1e30f; int bi = 0;
            for (int ee = 0; ee < Ne; ee++) {
                float v = lg[t][ee];
                if (v > best) { best = v; bi = ee; }
            }
            vals[p] = best; idxs[p] = bi; lg[t][bi] = -1e30f;
        }
        float m = vals[0], wv[TOPK], s = 0.0f;
#pragma unroll
        for (int p = 0; p < TOPK; p++) { wv[p] = __expf(vals[p] - m); s += wv[p]; }
        float inv = 1.0f / s;
        int gt = tbase + t;
#pragma unroll
        for (int p = 0; p < TOPK; p++) {
            g_topw[gt * TOPK + p] = wv[p] * inv;
            g_topi[gt * TOPK + p] = idxs[p];
            atomicAdd(&g_count[idxs[p]], 1);
        }
    }
}

__global__ void scan_kernel() {
    if (threadIdx.x == 0) {
        int run = 0, nt = 0;
        for (int e = 0; e < Ne; e++) {
            g_offset[e] = run; g_cursor[e] = run;
            int c = g_count[e];
            int tiles = (c + 127) >> 7;
            for (int i = 0; i < tiles; i++) { g_tile_e[nt] = e; g_tile_row[nt] = i * 128; nt++; }
            run += c;
        }
        g_ntiles = nt;
    }
}

__global__ void fill_kernel() {
    int t = blockIdx.x * 256 + threadIdx.x;
    if (t < Tn) {
#pragma unroll
        for (int j = 0; j < TOPK; j++) {
            int e = g_topi[t * TOPK + j];
            int pos = atomicAdd(&g_cursor[e], 1);
            g_pair_token[pos] = t;
            g_pair_w[pos] = g_topw[t * TOPK + j];
            g_slot2pair[t * TOPK + j] = pos;
        }
    }
}

// ---------------- combine ----------------
__global__ void __launch_bounds__(256) combine_kernel(float* __restrict__ out) {
    int t = blockIdx.x, tid = threadIdx.x;
    __shared__ int sp[TOPK];
    if (tid < TOPK) sp[tid] = g_slot2pair[t * TOPK + tid];
    __syncthreads();
    float4 a = *(const float4*)(g_sharedout + (size_t)t * Dm + tid * 4);
    float4 b = *(const float4*)(g_sharedout + (size_t)Tn * Dm + (size_t)t * Dm + tid * 4);
    float4 acc;
    acc.x = a.x + b.x; acc.y = a.y + b.y; acc.z = a.z + b.z; acc.w = a.w + b.w;
#pragma unroll
    for (int j = 0; j < TOPK; j++) {
        float4 p = *(const float4*)(g_pairout + (size_t)sp[j] * Dm + tid * 4);
        acc.x += p.x; acc.y += p.y; acc.z += p.z; acc.w += p.w;
    }
    *(float4*)(out + (size_t)t * Dm + tid * 4) = acc;
}

// ---------------- launch ----------------
extern "C" void kernel_launch(void* const* d_in, const int* in_sizes, int n_in,
                              void* d_out, int out_size)
{
    const float* x   = (const float*)d_in[0];
    const float* rw  = (const float*)d_in[1];
    const float* rb  = (const float*)d_in[2];
    const float* w1  = (const float*)d_in[3];
    const float* b1  = (const float*)d_in[4];
    const float* w2  = (const float*)d_in[5];
    const float* b2  = (const float*)d_in[6];
    const float* sw1 = (const float*)d_in[7];
    const float* sb1 = (const float*)d_in[8];
    const float* sw2 = (const float*)d_in[9];
    const float* sb2 = (const float*)d_in[10];
    float* out = (float*)d_out;

    cudaFuncSetAttribute(k_g1_routed, cudaFuncAttributeMaxDynamicSharedMemorySize, SM_BYTES);
    cudaFuncSetAttribute(k_g2_routed, cudaFuncAttributeMaxDynamicSharedMemorySize, SM_BYTES);
    cudaFuncSetAttribute(k_g1_shared, cudaFuncAttributeMaxDynamicSharedMemorySize, SM_BYTES);
    cudaFuncSetAttribute(k_g2_shared, cudaFuncAttributeMaxDynamicSharedMemorySize, SM_BYTES);

    zero_counts_kernel<<<1, 64>>>();
    router_kernel<<<Tn / 32, 256>>>(x, rw, rb);
    scan_kernel<<<1, 32>>>();
    fill_kernel<<<(Tn + 255) / 256, 256>>>();
    k_g1_routed<<<dim3(MAXTILES, Hh / 128),  256, SM_BYTES>>>(x, w1, b1);
    k_g2_routed<<<dim3(MAXTILES, Dm / 128),  256, SM_BYTES>>>(w2, b2);
    k_g1_shared<<<dim3(Tn / 128, HSn / 128, ESn), 256, SM_BYTES>>>(x, sw1, sb1);
    k_g2_shared<<<dim3(Tn / 128, Dm / 128, ESn),  256, SM_BYTES>>>(sw2, sb2);
    combine_kernel<<<Tn, 256>>>(out);
}

// round 5
// speedup vs baseline: 2.7119x; 1.8413x over previous
#include <cuda_runtime.h>
#include <cuda_fp16.h>
#include <cstdint>
#include <math.h>

#define Tn   2048
#define Dm   1024
#define Ne   64
#define TOPK 8
#define Hh   256
#define ESn  2
#define HSn  2048
#define MAXP (Tn * TOPK)
#define MAXTILES 256

// ---------------- static scratch ----------------
__device__ float g_topw[MAXP];
__device__ int   g_topi[MAXP];
__device__ int   g_slot2pair[MAXP];
__device__ int   g_count[Ne];
__device__ int   g_offset[Ne];
__device__ int   g_cursor[Ne];
__device__ int   g_pair_token[MAXP];
__device__ float g_pair_w[MAXP];
__device__ int   g_ntiles;
__device__ int   g_tile_e[MAXTILES];
__device__ int   g_tile_row[MAXTILES];
__device__ float g_pairout[(size_t)MAXP * Dm];
__device__ float g_sharedout[(size_t)ESn * Tn * Dm];
// fp16 operand copies
__device__ __half g_x16[(size_t)Tn * Dm];
__device__ __half g_w116[(size_t)Ne * Dm * Hh];
__device__ __half g_w216[(size_t)Ne * Hh * Dm];
__device__ __half g_sw116[(size_t)ESn * Dm * HSn];
__device__ __half g_sw216[(size_t)ESn * HSn * Dm];
__device__ __half g_H16[(size_t)MAXP * Hh];
__device__ __half g_Hs16[(size_t)ESn * Tn * HSn];

__device__ __forceinline__ uint32_t smem_u32(const void* p) {
    uint32_t a;
    asm("{ .reg .u64 t; cvta.to.shared.u64 t, %1; cvt.u32.u64 %0, t; }" : "=r"(a) : "l"(p));
    return a;
}
__device__ __forceinline__ float silu_f(float c) { return c / (1.0f + __expf(-c)); }

__device__ __forceinline__ void ldsm_x4(uint32_t* r, uint32_t addr) {
    asm volatile("ldmatrix.sync.aligned.m8n8.x4.shared.b16 {%0,%1,%2,%3}, [%4];"
        : "=r"(r[0]), "=r"(r[1]), "=r"(r[2]), "=r"(r[3]) : "r"(addr));
}
__device__ __forceinline__ void ldsm_x4_trans(uint32_t* r, uint32_t addr) {
    asm volatile("ldmatrix.sync.aligned.m8n8.x4.trans.shared.b16 {%0,%1,%2,%3}, [%4];"
        : "=r"(r[0]), "=r"(r[1]), "=r"(r[2]), "=r"(r[3]) : "r"(addr));
}
__device__ __forceinline__ void mma_fp16(float* d, const uint32_t* a, uint32_t b0, uint32_t b1) {
    asm volatile(
        "mma.sync.aligned.m16n8k16.row.col.f32.f16.f16.f32 "
        "{%0,%1,%2,%3}, {%4,%5,%6,%7}, {%8,%9}, {%0,%1,%2,%3};"
        : "+f"(d[0]), "+f"(d[1]), "+f"(d[2]), "+f"(d[3])
        : "r"(a[0]), "r"(a[1]), "r"(a[2]), "r"(a[3]), "r"(b0), "r"(b1));
}

// smem layout (bytes):
//  [0,512)      rows_s (128 ints)
//  [512,1024)   scale_s (128 floats)
//  A0 @1024  (128 rows x 80B)       = 10240
//  A1 @11264
//  B0 @21504 (32 k-rows x 272B)     = 8704
//  B1 @30208  ... end 38912
//  stage (epilogue) reuses @1024: 128 x 68 floats = 34816
#define SMEM_TOT 38912
#define PA_B 80
#define PB_B 272

struct GemmArgs {
    const __half* A; int lda; const int* gather; int valid;
    const __half* W; int ldw; int n0;
    int K;
    const float* bias;
    const float* rowScale;   // nullable
    float*  outF;            // one of outF/outH non-null
    __half* outH;
    int ldo;
    bool silu;
};

__device__ void gemm128(const GemmArgs g) {
    __shared__ char smc[SMEM_TOT];
    int*   rows_s  = (int*)smc;
    float* scale_s = (float*)(smc + 512);
    float* stage   = (float*)(smc + 1024);

    const uint32_t sbase = smem_u32(smc);
    const uint32_t sA[2] = { sbase + 1024u, sbase + 11264u };
    const uint32_t sB[2] = { sbase + 21504u, sbase + 30208u };
    char* pAc[2] = { smc + 1024, smc + 11264 };
    char* pBc[2] = { smc + 21504, smc + 30208 };

    const int tid = threadIdx.x;
    const int lane = tid & 31, w = tid >> 5;
    const int mw = w & 1, nw = w >> 1;
    const int gg = lane >> 2, cc = lane & 3;
    const int arow = (lane & 7) + ((lane >> 3) & 1) * 8;
    const int kh = (lane >> 4) & 1;

    {
        bool v = tid < g.valid;
        rows_s[tid]  = g.gather ? (v ? g.gather[tid] : -1) : (v ? tid : -1);
        scale_s[tid] = (g.rowScale && v) ? g.rowScale[tid] : 1.0f;
    }
    // preload bias for this warp's 64 output columns
    float bias_r[8][2];
#pragma unroll
    for (int nb = 0; nb < 8; nb++) {
        int n = g.n0 + nw * 64 + nb * 8 + cc * 2;
        bias_r[nb][0] = g.bias[n];
        bias_r[nb][1] = g.bias[n + 1];
    }
    __syncthreads();

    float acc[4][8][4];
#pragma unroll
    for (int i = 0; i < 4; i++)
#pragma unroll
        for (int j = 0; j < 8; j++)
#pragma unroll
            for (int q = 0; q < 4; q++) acc[i][j][q] = 0.0f;

    const int nch = g.K >> 5;
    uint4 pa[4], pb[4];
    const uint4 zero4 = make_uint4(0u, 0u, 0u, 0u);

    // prefetch chunk 0
#pragma unroll
    for (int i = 0; i < 4; i++) {
        int q = tid + i * 128; int r = q >> 2, c = q & 3;
        int gr = rows_s[r];
        pa[i] = (gr >= 0) ? *(const uint4*)(g.A + (size_t)gr * g.lda + c * 8) : zero4;
    }
#pragma unroll
    for (int i = 0; i < 4; i++) {
        int q = tid + i * 128; int k = q >> 4, c = q & 15;
        pb[i] = *(const uint4*)(g.W + (size_t)k * g.ldw + g.n0 + c * 8);
    }
#pragma unroll
    for (int i = 0; i < 4; i++) {
        int q = tid + i * 128; int r = q >> 2, c = q & 3;
        *(uint4*)(pAc[0] + r * PA_B + c * 16) = pa[i];
    }
#pragma unroll
    for (int i = 0; i < 4; i++) {
        int q = tid + i * 128; int k = q >> 4, c = q & 15;
        *(uint4*)(pBc[0] + k * PB_B + c * 16) = pb[i];
    }
    __syncthreads();

    for (int c = 0; c < nch; c++) {
        const int cur = c & 1, nxt = cur ^ 1;
        const bool more = (c + 1) < nch;
        if (more) {
            int k0 = (c + 1) << 5;
#pragma unroll
            for (int i = 0; i < 4; i++) {
                int q = tid + i * 128; int r = q >> 2, cq = q & 3;
                int gr = rows_s[r];
                pa[i] = (gr >= 0) ? *(const uint4*)(g.A + (size_t)gr * g.lda + k0 + cq * 8) : zero4;
            }
#pragma unroll
            for (int i = 0; i < 4; i++) {
                int q = tid + i * 128; int k = q >> 4, cq = q & 15;
                pb[i] = *(const uint4*)(g.W + (size_t)(k0 + k) * g.ldw + g.n0 + cq * 8);
            }
        }
        // consume buffer cur: 2 k-steps of 16
        const uint32_t Ab = sA[cur], Bb = sB[cur];
#pragma unroll
        for (int ks = 0; ks < 2; ks++) {
            uint32_t a[4][4], bf[8][2];
#pragma unroll
            for (int ma = 0; ma < 4; ma++) {
                uint32_t addr = Ab + (uint32_t)((mw * 64 + ma * 16 + arow) * PA_B + ks * 32 + kh * 16);
                ldsm_x4(a[ma], addr);
            }
#pragma unroll
            for (int p = 0; p < 4; p++) {
                uint32_t r4[4];
                uint32_t addr = Bb + (uint32_t)((ks * 16 + arow) * PB_B + (nw * 64 + p * 16 + kh * 8) * 2);
                ldsm_x4_trans(r4, addr);
                bf[2 * p][0] = r4[0]; bf[2 * p][1] = r4[1];
                bf[2 * p + 1][0] = r4[2]; bf[2 * p + 1][1] = r4[3];
            }
#pragma unroll
            for (int ma = 0; ma < 4; ma++)
#pragma unroll
                for (int nb = 0; nb < 8; nb++)
                    mma_fp16(acc[ma][nb], a[ma], bf[nb][0], bf[nb][1]);
        }
        if (more) {
#pragma unroll
            for (int i = 0; i < 4; i++) {
                int q = tid + i * 128; int r = q >> 2, cq = q & 3;
                *(uint4*)(pAc[nxt] + r * PA_B + cq * 16) = pa[i];
            }
#pragma unroll
            for (int i = 0; i < 4; i++) {
                int q = tid + i * 128; int k = q >> 4, cq = q & 15;
                *(uint4*)(pBc[nxt] + k * PB_B + cq * 16) = pb[i];
            }
        }
        __syncthreads();
    }

    // epilogue: two 64-col slabs via smem stage
#pragma unroll
    for (int slab = 0; slab < 2; slab++) {
        if (nw == slab) {
#pragma unroll
            for (int ma = 0; ma < 4; ma++) {
                int r0 = mw * 64 + ma * 16 + gg, r1 = r0 + 8;
                float s0 = scale_s[r0], s1 = scale_s[r1];
#pragma unroll
                for (int nb = 0; nb < 8; nb++) {
                    int col = nb * 8 + cc * 2;
                    float f0 = acc[ma][nb][0] + bias_r[nb][0];
                    float f1 = acc[ma][nb][1] + bias_r[nb][1];
                    float f2 = acc[ma][nb][2] + bias_r[nb][0];
                    float f3 = acc[ma][nb][3] + bias_r[nb][1];
                    if (g.silu) { f0 = silu_f(f0); f1 = silu_f(f1); f2 = silu_f(f2); f3 = silu_f(f3); }
                    *(float2*)(stage + r0 * 68 + col) = make_float2(f0 * s0, f1 * s0);
                    *(float2*)(stage + r1 * 68 + col) = make_float2(f2 * s1, f3 * s1);
                }
            }
        }
        __syncthreads();
        if (g.outF) {
            for (int q = tid; q < 128 * 16; q += 128) {
                int r = q >> 4, c4 = q & 15;
                if (r < g.valid) {
                    float4 v = *(float4*)(stage + r * 68 + c4 * 4);
                    *(float4*)(g.outF + (size_t)r * g.ldo + g.n0 + slab * 64 + c4 * 4) = v;
                }
            }
        } else {
            for (int q = tid; q < 128 * 32; q += 128) {
                int r = q >> 5, c2 = q & 31;
                if (r < g.valid) {
                    float2 v = *(float2*)(stage + r * 68 + c2 * 2);
                    __half2 h = __floats2half2_rn(v.x, v.y);
                    *(__half2*)(g.outH + (size_t)r * g.ldo + g.n0 + slab * 64 + c2 * 2) = h;
                }
            }
        }
        __syncthreads();
    }
}

// ---------------- GEMM kernel wrappers ----------------
__global__ void __launch_bounds__(128, 2) k_g1_routed(const float* b1) {
    int t = blockIdx.x;
    if (t >= g_ntiles) return;
    int e = g_tile_e[t], rb = g_tile_row[t];
    int cnt = g_count[e], off = g_offset[e];
    GemmArgs a;
    a.A = g_x16; a.lda = Dm; a.gather = g_pair_token + off + rb; a.valid = min(128, cnt - rb);
    a.W = g_w116 + (size_t)e * Dm * Hh; a.ldw = Hh; a.n0 = blockIdx.y * 128;
    a.K = Dm; a.bias = b1 + e * Hh; a.rowScale = nullptr;
    a.outF = nullptr; a.outH = g_H16 + (size_t)(off + rb) * Hh; a.ldo = Hh; a.silu = true;
    gemm128(a);
}
__global__ void __launch_bounds__(128, 2) k_g2_routed(const float* b2) {
    int t = blockIdx.x;
    if (t >= g_ntiles) return;
    int e = g_tile_e[t], rb = g_tile_row[t];
    int cnt = g_count[e], off = g_offset[e];
    GemmArgs a;
    a.A = g_H16 + (size_t)(off + rb) * Hh; a.lda = Hh; a.gather = nullptr; a.valid = min(128, cnt - rb);
    a.W = g_w216 + (size_t)e * Hh * Dm; a.ldw = Dm; a.n0 = blockIdx.y * 128;
    a.K = Hh; a.bias = b2 + (size_t)e * Dm; a.rowScale = g_pair_w + off + rb;
    a.outF = g_pairout + (size_t)(off + rb) * Dm; a.outH = nullptr; a.ldo = Dm; a.silu = false;
    gemm128(a);
}
__global__ void __launch_bounds__(128, 2) k_g1_shared(const float* sb1) {
    int es = blockIdx.z, row0 = blockIdx.x * 128;
    GemmArgs a;
    a.A = g_x16 + (size_t)row0 * Dm; a.lda = Dm; a.gather = nullptr; a.valid = 128;
    a.W = g_sw116 + (size_t)es * Dm * HSn; a.ldw = HSn; a.n0 = blockIdx.y * 128;
    a.K = Dm; a.bias = sb1 + (size_t)es * HSn; a.rowScale = nullptr;
    a.outF = nullptr; a.outH = g_Hs16 + (size_t)es * Tn * HSn + (size_t)row0 * HSn; a.ldo = HSn; a.silu = true;
    gemm128(a);
}
__global__ void __launch_bounds__(128, 2) k_g2_shared(const float* sb2) {
    int es = blockIdx.z, row0 = blockIdx.x * 128;
    GemmArgs a;
    a.A = g_Hs16 + (size_t)es * Tn * HSn + (size_t)row0 * HSn; a.lda = HSn; a.gather = nullptr; a.valid = 128;
    a.W = g_sw216 + (size_t)es * HSn * Dm; a.ldw = Dm; a.n0 = blockIdx.y * 128;
    a.K = HSn; a.bias = sb2 + (size_t)es * Dm; a.rowScale = nullptr;
    a.outF = g_sharedout + (size_t)es * Tn * Dm + (size_t)row0 * Dm; a.outH = nullptr; a.ldo = Dm; a.silu = false;
    gemm128(a);
}

// ---------------- fp32 -> fp16 conversion ----------------
__global__ void __launch_bounds__(256) conv_kernel(const float* __restrict__ src, __half* __restrict__ dst, int n4) {
    for (int i = blockIdx.x * 256 + threadIdx.x; i < n4; i += gridDim.x * 256) {
        float4 v = *(const float4*)(src + (size_t)i * 4);
        __half2 h0 = __floats2half2_rn(v.x, v.y);
        __half2 h1 = __floats2half2_rn(v.z, v.w);
        uint32_t u0 = *(uint32_t*)&h0;
        uint32_t u1 = *(uint32_t*)&h1;
        *(uint2*)(dst + (size_t)i * 4) = make_uint2(u0, u1);
    }
}

// ---------------- routing bookkeeping ----------------
__global__ void zero_counts_kernel() {
    if (threadIdx.x < Ne) g_count[threadIdx.x] = 0;
}

__global__ void __launch_bounds__(256) router_kernel(
    const float* __restrict__ x, const float* __restrict__ rw, const float* __restrict__ rb)
{
    __shared__ float xs[64][33];
    __shared__ float ws[64][65];
    __shared__ float lg[32][65];
    int tid = threadIdx.x;
    int tbase = blockIdx.x * 32;
    int e = tid & 63, tg = tid >> 6;
    float acc[8];
#pragma unroll
    for (int i = 0; i < 8; i++) acc[i] = 0.0f;
    for (int d0 = 0; d0 < Dm; d0 += 64) {
#pragma unroll
        for (int q = 0; q < 8; q++) {
            int idx = tid + q * 256; int t = idx >> 6, dd = idx & 63;
            xs[dd][t] = x[(size_t)(tbase + t) * Dm + d0 + dd];
        }
#pragma unroll
        for (int q = 0; q < 16; q++) {
            int idx = tid + q * 256; int dd = idx >> 6, ee = idx & 63;
            ws[dd][ee] = rw[(size_t)(d0 + dd) * Ne + ee];
        }
        __syncthreads();
#pragma unroll
        for (int dd = 0; dd < 64; dd++) {
            float wv = ws[dd][e];
#pragma unroll
            for (int i = 0; i < 8; i++) acc[i] += xs[dd][tg + 4 * i] * wv;
        }
        __syncthreads();
    }
#pragma unroll
    for (int i = 0; i < 8; i++) lg[tg + 4 * i][e] = acc[i] + rb[e];
    __syncthreads();
    if (tid < 32) {
        int t = tid;
        float vals[TOPK]; int idxs[TOPK];
#pragma unroll
        for (int p = 0; p < TOPK; p++) {
            float best = -1e30f; int bi = 0;
            for (int ee = 0; ee < Ne; ee++) {
                float v = lg[t][ee];
                if (v > best) { best = v; bi = ee; }
            }
            vals[p] = best; idxs[p] = bi; lg[t][bi] = -1e30f;
        }
        float m = vals[0], wv[TOPK], s = 0.0f;
#pragma unroll
        for (int p = 0; p < TOPK; p++) { wv[p] = __expf(vals[p] - m); s += wv[p]; }
        float inv = 1.0f / s;
        int gt = tbase + t;
#pragma unroll
        for (int p = 0; p < TOPK; p++) {
            g_topw[gt * TOPK + p] = wv[p] * inv;
            g_topi[gt * TOPK + p] = idxs[p];
            atomicAdd(&g_count[idxs[p]], 1);
        }
    }
}

__global__ void scan_kernel() {
    if (threadIdx.x == 0) {
        int run = 0, nt = 0;
        for (int e = 0; e < Ne; e++) {
            g_offset[e] = run; g_cursor[e] = run;
            int c = g_count[e];
            int tiles = (c + 127) >> 7;
            for (int i = 0; i < tiles; i++) { g_tile_e[nt] = e; g_tile_row[nt] = i * 128; nt++; }
            run += c;
        }
        g_ntiles = nt;
    }
}

__global__ void fill_kernel() {
    int t = blockIdx.x * 256 + threadIdx.x;
    if (t < Tn) {
#pragma unroll
        for (int j = 0; j < TOPK; j++) {
            int e = g_topi[t * TOPK + j];
            int pos = atomicAdd(&g_cursor[e], 1);
            g_pair_token[pos] = t;
            g_pair_w[pos] = g_topw[t * TOPK + j];
            g_slot2pair[t * TOPK + j] = pos;
        }
    }
}

// ---------------- combine ----------------
__global__ void __launch_bounds__(256) combine_kernel(float* __restrict__ out) {
    int t = blockIdx.x, tid = threadIdx.x;
    __shared__ int sp[TOPK];
    if (tid < TOPK) sp[tid] = g_slot2pair[t * TOPK + tid];
    __syncthreads();
    float4 a = *(const float4*)(g_sharedout + (size_t)t * Dm + tid * 4);
    float4 b = *(const float4*)(g_sharedout + (size_t)Tn * Dm + (size_t)t * Dm + tid * 4);
    float4 acc;
    acc.x = a.x + b.x; acc.y = a.y + b.y; acc.z = a.z + b.z; acc.w = a.w + b.w;
#pragma unroll
    for (int j = 0; j < TOPK; j++) {
        float4 p = *(const float4*)(g_pairout + (size_t)sp[j] * Dm + tid * 4);
        acc.x += p.x; acc.y += p.y; acc.z += p.z; acc.w += p.w;
    }
    *(float4*)(out + (size_t)t * Dm + tid * 4) = acc;
}

// ---------------- launch ----------------
extern "C" void kernel_launch(void* const* d_in, const int* in_sizes, int n_in,
                              void* d_out, int out_size)
{
    const float* x   = (const float*)d_in[0];
    const float* rw  = (const float*)d_in[1];
    const float* rb  = (const float*)d_in[2];
    const float* w1  = (const float*)d_in[3];
    const float* b1  = (const float*)d_in[4];
    const float* w2  = (const float*)d_in[5];
    const float* b2  = (const float*)d_in[6];
    const float* sw1 = (const float*)d_in[7];
    const float* sb1 = (const float*)d_in[8];
    const float* sw2 = (const float*)d_in[9];
    const float* sb2 = (const float*)d_in[10];
    float* out = (float*)d_out;

    __half* x16  = nullptr; cudaGetSymbolAddress((void**)&x16,  g_x16);
    __half* w116 = nullptr; cudaGetSymbolAddress((void**)&w116, g_w116);
    __half* w216 = nullptr; cudaGetSymbolAddress((void**)&w216, g_w216);
    __half* s116 = nullptr; cudaGetSymbolAddress((void**)&s116, g_sw116);
    __half* s216 = nullptr; cudaGetSymbolAddress((void**)&s216, g_sw216);

    zero_counts_kernel<<<1, 64>>>();
    conv_kernel<<<1024, 256>>>(x,   x16,  Tn * Dm / 4);
    conv_kernel<<<2048, 256>>>(w1,  w116, Ne * Dm * Hh / 4);
    conv_kernel<<<2048, 256>>>(w2,  w216, Ne * Hh * Dm / 4);
    conv_kernel<<<2048, 256>>>(sw1, s116, ESn * Dm * HSn / 4);
    conv_kernel<<<2048, 256>>>(sw2, s216, ESn * HSn * Dm / 4);
    router_kernel<<<Tn / 32, 256>>>(x, rw, rb);
    scan_kernel<<<1, 32>>>();
    fill_kernel<<<(Tn + 255) / 256, 256>>>();
    k_g1_routed<<<dim3(MAXTILES, Hh / 128),  128>>>(b1);
    k_g2_routed<<<dim3(MAXTILES, Dm / 128),  128>>>(b2);
    k_g1_shared<<<dim3(Tn / 128, HSn / 128, ESn), 128>>>(sb1);
    k_g2_shared<<<dim3(Tn / 128, Dm / 128, ESn),  128>>>(sb2);
    combine_kernel<<<Tn, 256>>>(out);
}

// round 7
// speedup vs baseline: 2.7527x; 1.0150x over previous
#include <cuda_runtime.h>
#include <cuda_fp16.h>
#include <cstdint>
#include <math.h>

#define Tn   2048
#define Dm   1024
#define Ne   64
#define TOPK 8
#define Hh   256
#define ESn  2
#define HSn  2048
#define MAXP (Tn * TOPK)
#define MAXTILES 256

// ---------------- static scratch ----------------
__device__ float g_topw[MAXP];
__device__ int   g_topi[MAXP];
__device__ int   g_slot2pair[MAXP];
__device__ int   g_count[Ne];
__device__ int   g_offset[Ne];
__device__ int   g_cursor[Ne];
__device__ int   g_pair_token[MAXP];
__device__ float g_pair_w[MAXP];
__device__ int   g_ntiles;
__device__ int   g_tile_e[MAXTILES];
__device__ int   g_tile_row[MAXTILES];
__device__ __half g_pairout16[(size_t)MAXP * Dm];
__device__ __half g_sharedout16[(size_t)ESn * Tn * Dm];
__device__ __half g_H16[(size_t)MAXP * Hh];
__device__ __half g_Hs16[(size_t)ESn * Tn * HSn];

__device__ __forceinline__ uint32_t smem_u32(const void* p) {
    uint32_t a;
    asm("{ .reg .u64 t; cvta.to.shared.u64 t, %1; cvt.u32.u64 %0, t; }" : "=r"(a) : "l"(p));
    return a;
}
__device__ __forceinline__ float silu_f(float c) { return c / (1.0f + __expf(-c)); }

__device__ __forceinline__ void ldsm_x4(uint32_t* r, uint32_t addr) {
    asm volatile("ldmatrix.sync.aligned.m8n8.x4.shared.b16 {%0,%1,%2,%3}, [%4];"
        : "=r"(r[0]), "=r"(r[1]), "=r"(r[2]), "=r"(r[3]) : "r"(addr));
}
__device__ __forceinline__ void ldsm_x4_trans(uint32_t* r, uint32_t addr) {
    asm volatile("ldmatrix.sync.aligned.m8n8.x4.trans.shared.b16 {%0,%1,%2,%3}, [%4];"
        : "=r"(r[0]), "=r"(r[1]), "=r"(r[2]), "=r"(r[3]) : "r"(addr));
}
__device__ __forceinline__ void mma_fp16(float* d, const uint32_t* a, uint32_t b0, uint32_t b1) {
    asm volatile(
        "mma.sync.aligned.m16n8k16.row.col.f32.f16.f16.f32 "
        "{%0,%1,%2,%3}, {%4,%5,%6,%7}, {%8,%9}, {%0,%1,%2,%3};"
        : "+f"(d[0]), "+f"(d[1]), "+f"(d[2]), "+f"(d[3])
        : "r"(a[0]), "r"(a[1]), "r"(a[2]), "r"(a[3]), "r"(b0), "r"(b1));
}
__device__ __forceinline__ uint4 pack8h(float4 v0, float4 v1) {
    __half2 h0 = __floats2half2_rn(v0.x, v0.y);
    __half2 h1 = __floats2half2_rn(v0.z, v0.w);
    __half2 h2 = __floats2half2_rn(v1.x, v1.y);
    __half2 h3 = __floats2half2_rn(v1.z, v1.w);
    return make_uint4(*(uint32_t*)&h0, *(uint32_t*)&h1, *(uint32_t*)&h2, *(uint32_t*)&h3);
}

// smem layout (bytes):
//  [0,512)      rows_s (128 ints)
//  [512,1024)   scale_s (128 floats)
//  A0 @1024  (128 rows x 80B)       = 10240
//  A1 @11264
//  B0 @21504 (32 k-rows x 272B)     = 8704
//  B1 @30208  ... end 38912
//  stage (epilogue) reuses @1024: 128 x 68 floats = 34816
#define SMEM_TOT 38912
#define PA_B 80
#define PB_B 272

struct GemmArgs {
    const void* A; int lda; const int* gather; int valid;  // A fp32 or fp16 per template
    const float* W; int ldw; int n0;                       // W always fp32 source
    int K;
    const float* bias;
    const float* rowScale;   // nullable
    __half* outH;
    int ldo;
    bool silu;
};

template <bool A16>
__device__ void gemm128(const GemmArgs g) {
    __shared__ char smc[SMEM_TOT];
    int*   rows_s  = (int*)smc;
    float* scale_s = (float*)(smc + 512);
    float* stage   = (float*)(smc + 1024);

    const uint32_t sbase = smem_u32(smc);
    const uint32_t sA[2] = { sbase + 1024u, sbase + 11264u };
    const uint32_t sB[2] = { sbase + 21504u, sbase + 30208u };
    char* pAc[2] = { smc + 1024, smc + 11264 };
    char* pBc[2] = { smc + 21504, smc + 30208 };

    const int tid = threadIdx.x;
    const int lane = tid & 31, w = tid >> 5;
    const int mw = w & 1, nw = w >> 1;
    const int gg = lane >> 2, cc = lane & 3;
    const int arow = (lane & 7) + ((lane >> 3) & 1) * 8;
    const int kh = (lane >> 4) & 1;

    {
        bool v = tid < g.valid;
        rows_s[tid]  = g.gather ? (v ? g.gather[tid] : -1) : (v ? tid : -1);
        scale_s[tid] = (g.rowScale && v) ? g.rowScale[tid] : 1.0f;
    }
    float bias_r[8][2];
#pragma unroll
    for (int nb = 0; nb < 8; nb++) {
        int n = g.n0 + nw * 64 + nb * 8 + cc * 2;
        bias_r[nb][0] = g.bias[n];
        bias_r[nb][1] = g.bias[n + 1];
    }
    __syncthreads();

    float acc[4][8][4];
#pragma unroll
    for (int i = 0; i < 4; i++)
#pragma unroll
        for (int j = 0; j < 8; j++)
#pragma unroll
            for (int q = 0; q < 4; q++) acc[i][j][q] = 0.0f;

    const int nch = g.K >> 5;
    const float4 zf4 = make_float4(0.f, 0.f, 0.f, 0.f);
    const uint4  zu4 = make_uint4(0u, 0u, 0u, 0u);

    // prefetch registers
    uint4  paH[4];            // A fp16 path
    float4 paF[4][2];         // A fp32 path
    float4 pbF[4][2];         // W fp32 path

    const __half* A16p = (const __half*)g.A;
    const float*  A32p = (const float*)g.A;

    // ---- load chunk k0 into regs ----
    auto loadA = [&](int k0) {
#pragma unroll
        for (int i = 0; i < 4; i++) {
            int q = tid + i * 128; int r = q >> 2, c = q & 3;
            int gr = rows_s[r];
            if (A16) {
                paH[i] = (gr >= 0) ? *(const uint4*)(A16p + (size_t)gr * g.lda + k0 + c * 8) : zu4;
            } else {
                if (gr >= 0) {
                    paF[i][0] = *(const float4*)(A32p + (size_t)gr * g.lda + k0 + c * 8);
                    paF[i][1] = *(const float4*)(A32p + (size_t)gr * g.lda + k0 + c * 8 + 4);
                } else { paF[i][0] = zf4; paF[i][1] = zf4; }
            }
        }
    };
    auto loadB = [&](int k0) {
#pragma unroll
        for (int i = 0; i < 4; i++) {
            int q = tid + i * 128; int k = q >> 4, c = q & 15;
            pbF[i][0] = *(const float4*)(g.W + (size_t)(k0 + k) * g.ldw + g.n0 + c * 8);
            pbF[i][1] = *(const float4*)(g.W + (size_t)(k0 + k) * g.ldw + g.n0 + c * 8 + 4);
        }
    };
    auto storeA = [&](int buf) {
#pragma unroll
        for (int i = 0; i < 4; i++) {
            int q = tid + i * 128; int r = q >> 2, c = q & 3;
            uint4 v = A16 ? paH[i] : pack8h(paF[i][0], paF[i][1]);
            *(uint4*)(pAc[buf] + r * PA_B + c * 16) = v;
        }
    };
    auto storeB = [&](int buf) {
#pragma unroll
        for (int i = 0; i < 4; i++) {
            int q = tid + i * 128; int k = q >> 4, c = q & 15;
            *(uint4*)(pBc[buf] + k * PB_B + c * 16) = pack8h(pbF[i][0], pbF[i][1]);
        }
    };

    loadA(0); loadB(0);
    storeA(0); storeB(0);
    __syncthreads();

    for (int c = 0; c < nch; c++) {
        const int cur = c & 1, nxt = cur ^ 1;
        const bool more = (c + 1) < nch;
        if (more) { loadA((c + 1) << 5); loadB((c + 1) << 5); }

        const uint32_t Ab = sA[cur], Bb = sB[cur];
#pragma unroll
        for (int ks = 0; ks < 2; ks++) {
            uint32_t a[4][4], bf[8][2];
#pragma unroll
            for (int ma = 0; ma < 4; ma++) {
                uint32_t addr = Ab + (uint32_t)((mw * 64 + ma * 16 + arow) * PA_B + ks * 32 + kh * 16);
                ldsm_x4(a[ma], addr);
            }
#pragma unroll
            for (int p = 0; p < 4; p++) {
                uint32_t r4[4];
                uint32_t addr = Bb + (uint32_t)((ks * 16 + arow) * PB_B + (nw * 64 + p * 16 + kh * 8) * 2);
                ldsm_x4_trans(r4, addr);
                bf[2 * p][0] = r4[0]; bf[2 * p][1] = r4[1];
                bf[2 * p + 1][0] = r4[2]; bf[2 * p + 1][1] = r4[3];
            }
#pragma unroll
            for (int ma = 0; ma < 4; ma++)
#pragma unroll
                for (int nb = 0; nb < 8; nb++)
                    mma_fp16(acc[ma][nb], a[ma], bf[nb][0], bf[nb][1]);
        }
        if (more) { storeA(nxt); storeB(nxt); }
        __syncthreads();
    }

    // epilogue: two 64-col slabs via smem stage, fp16 output
#pragma unroll
    for (int slab = 0; slab < 2; slab++) {
        if (nw == slab) {
#pragma unroll
            for (int ma = 0; ma < 4; ma++) {
                int r0 = mw * 64 + ma * 16 + gg, r1 = r0 + 8;
                float s0 = scale_s[r0], s1 = scale_s[r1];
#pragma unroll
                for (int nb = 0; nb < 8; nb++) {
                    int col = nb * 8 + cc * 2;
                    float f0 = acc[ma][nb][0] + bias_r[nb][0];
                    float f1 = acc[ma][nb][1] + bias_r[nb][1];
                    float f2 = acc[ma][nb][2] + bias_r[nb][0];
                    float f3 = acc[ma][nb][3] + bias_r[nb][1];
                    if (g.silu) { f0 = silu_f(f0); f1 = silu_f(f1); f2 = silu_f(f2); f3 = silu_f(f3); }
                    *(float2*)(stage + r0 * 68 + col) = make_float2(f0 * s0, f1 * s0);
                    *(float2*)(stage + r1 * 68 + col) = make_float2(f2 * s1, f3 * s1);
                }
            }
        }
        __syncthreads();
        for (int q = tid; q < 128 * 16; q += 128) {
            int r = q >> 4, c4 = q & 15;
            if (r < g.valid) {
                float4 v = *(float4*)(stage + r * 68 + c4 * 4);
                __half2 h0 = __floats2half2_rn(v.x, v.y);
                __half2 h1 = __floats2half2_rn(v.z, v.w);
                *(uint2*)(g.outH + (size_t)r * g.ldo + g.n0 + slab * 64 + c4 * 4) =
                    make_uint2(*(uint32_t*)&h0, *(uint32_t*)&h1);
            }
        }
        __syncthreads();
    }
}

// ---------------- GEMM kernel wrappers ----------------
__global__ void __launch_bounds__(128, 2) k_g1_routed(const float* x, const float* w1, const float* b1) {
    int t = blockIdx.x;
    if (t >= g_ntiles) return;
    int e = g_tile_e[t], rb = g_tile_row[t];
    int cnt = g_count[e], off = g_offset[e];
    GemmArgs a;
    a.A = x; a.lda = Dm; a.gather = g_pair_token + off + rb; a.valid = min(128, cnt - rb);
    a.W = w1 + (size_t)e * Dm * Hh; a.ldw = Hh; a.n0 = blockIdx.y * 128;
    a.K = Dm; a.bias = b1 + e * Hh; a.rowScale = nullptr;
    a.outH = g_H16 + (size_t)(off + rb) * Hh; a.ldo = Hh; a.silu = true;
    gemm128<false>(a);
}
__global__ void __launch_bounds__(128, 2) k_g2_routed(const float* w2, const float* b2) {
    int t = blockIdx.x;
    if (t >= g_ntiles) return;
    int e = g_tile_e[t], rb = g_tile_row[t];
    int cnt = g_count[e], off = g_offset[e];
    GemmArgs a;
    a.A = g_H16 + (size_t)(off + rb) * Hh; a.lda = Hh; a.gather = nullptr; a.valid = min(128, cnt - rb);
    a.W = w2 + (size_t)e * Hh * Dm; a.ldw = Dm; a.n0 = blockIdx.y * 128;
    a.K = Hh; a.bias = b2 + (size_t)e * Dm; a.rowScale = g_pair_w + off + rb;
    a.outH = g_pairout16 + (size_t)(off + rb) * Dm; a.ldo = Dm; a.silu = false;
    gemm128<true>(a);
}
__global__ void __launch_bounds__(128, 2) k_g1_shared(const float* x, const float* sw1, const float* sb1) {
    int es = blockIdx.z, row0 = blockIdx.x * 128;
    GemmArgs a;
    a.A = x + (size_t)row0 * Dm; a.lda = Dm; a.gather = nullptr; a.valid = 128;
    a.W = sw1 + (size_t)es * Dm * HSn; a.ldw = HSn; a.n0 = blockIdx.y * 128;
    a.K = Dm; a.bias = sb1 + (size_t)es * HSn; a.rowScale = nullptr;
    a.outH = g_Hs16 + (size_t)es * Tn * HSn + (size_t)row0 * HSn; a.ldo = HSn; a.silu = true;
    gemm128<false>(a);
}
__global__ void __launch_bounds__(128, 2) k_g2_shared(const float* sw2, const float* sb2) {
    int es = blockIdx.z, row0 = blockIdx.x * 128;
    GemmArgs a;
    a.A = g_Hs16 + (size_t)es * Tn * HSn + (size_t)row0 * HSn; a.lda = HSn; a.gather = nullptr; a.valid = 128;
    a.W = sw2 + (size_t)es * HSn * Dm; a.ldw = Dm; a.n0 = blockIdx.y * 128;
    a.K = HSn; a.bias = sb2 + (size_t)es * Dm; a.rowScale = nullptr;
    a.outH = g_sharedout16 + (size_t)es * Tn * Dm + (size_t)row0 * Dm; a.ldo = Dm; a.silu = false;
    gemm128<true>(a);
}

// ---------------- routing bookkeeping ----------------
__global__ void zero_counts_kernel() {
    if (threadIdx.x < Ne) g_count[threadIdx.x] = 0;
}

__global__ void __launch_bounds__(256) router_kernel(
    const float* __restrict__ x, const float* __restrict__ rw, const float* __restrict__ rb)
{
    __shared__ float xs[64][33];
    __shared__ float ws[64][65];
    __shared__ float lg[32][65];
    int tid = threadIdx.x;
    int tbase = blockIdx.x * 32;
    int e = tid & 63, tg = tid >> 6;
    float acc[8];
#pragma unroll
    for (int i = 0; i < 8; i++) acc[i] = 0.0f;
    for (int d0 = 0; d0 < Dm; d0 += 64) {
#pragma unroll
        for (int q = 0; q < 8; q++) {
            int idx = tid + q * 256; int t = idx >> 6, dd = idx & 63;
            xs[dd][t] = x[(size_t)(tbase + t) * Dm + d0 + dd];
        }
#pragma unroll
        for (int q = 0; q < 16; q++) {
            int idx = tid + q * 256; int dd = idx >> 6, ee = idx & 63;
            ws[dd][ee] = rw[(size_t)(d0 + dd) * Ne + ee];
        }
        __syncthreads();
#pragma unroll
        for (int dd = 0; dd < 64; dd++) {
            float wv = ws[dd][e];
#pragma unroll
            for (int i = 0; i < 8; i++) acc[i] += xs[dd][tg + 4 * i] * wv;
        }
        __syncthreads();
    }
#pragma unroll
    for (int i = 0; i < 8; i++) lg[tg + 4 * i][e] = acc[i] + rb[e];
    __syncthreads();
    if (tid < 32) {
        int t = tid;
        float vals[TOPK]; int idxs[TOPK];
#pragma unroll
        for (int p = 0; p < TOPK; p++) {
            float best = -1e30f; int bi = 0;
            for (int ee = 0; ee < Ne; ee++) {
                float v = lg[t][ee];
                if (v > best) { best = v; bi = ee; }
            }
            vals[p] = best; idxs[p] = bi; lg[t][bi] = -1e30f;
        }
        float m = vals[0], wv[TOPK], s = 0.0f;
#pragma unroll
        for (int p = 0; p < TOPK; p++) { wv[p] = __expf(vals[p] - m); s += wv[p]; }
        float inv = 1.0f / s;
        int gt = tbase + t;
#pragma unroll
        for (int p = 0; p < TOPK; p++) {
            g_topw[gt * TOPK + p] = wv[p] * inv;
            g_topi[gt * TOPK + p] = idxs[p];
            atomicAdd(&g_count[idxs[p]], 1);
        }
    }
}

__global__ void scan_kernel() {
    if (threadIdx.x == 0) {
        int run = 0, nt = 0;
        for (int e = 0; e < Ne; e++) {
            g_offset[e] = run; g_cursor[e] = run;
            int c = g_count[e];
            int tiles = (c + 127) >> 7;
            for (int i = 0; i < tiles; i++) { g_tile_e[nt] = e; g_tile_row[nt] = i * 128; nt++; }
            run += c;
        }
        g_ntiles = nt;
    }
}

__global__ void fill_kernel() {
    int t = blockIdx.x * 256 + threadIdx.x;
    if (t < Tn) {
#pragma unroll
        for (int j = 0; j < TOPK; j++) {
            int e = g_topi[t * TOPK + j];
            int pos = atomicAdd(&g_cursor[e], 1);
            g_pair_token[pos] = t;
            g_pair_w[pos] = g_topw[t * TOPK + j];
            g_slot2pair[t * TOPK + j] = pos;
        }
    }
}

// ---------------- combine (fp16 inputs, fp32 accumulate) ----------------
__global__ void __launch_bounds__(256) combine_kernel(float* __restrict__ out) {
    int t = blockIdx.x, tid = threadIdx.x;
    __shared__ int sp[TOPK];
    if (tid < TOPK) sp[tid] = g_slot2pair[t * TOPK + tid];
    __syncthreads();
    // each thread: 4 consecutive halves (one uint2 = 4 halves)
    float acc0, acc1, acc2, acc3;
    {
        uint2 u = *(const uint2*)(g_sharedout16 + (size_t)t * Dm + tid * 4);
        __half2 h0 = *(__half2*)&u.x, h1 = *(__half2*)&u.y;
        float2 f0 = __half22float2(h0), f1 = __half22float2(h1);
        acc0 = f0.x; acc1 = f0.y; acc2 = f1.x; acc3 = f1.y;
    }
    {
        uint2 u = *(const uint2*)(g_sharedout16 + (size_t)Tn * Dm + (size_t)t * Dm + tid * 4);
        __half2 h0 = *(__half2*)&u.x, h1 = *(__half2*)&u.y;
        float2 f0 = __half22float2(h0), f1 = __half22float2(h1);
        acc0 += f0.x; acc1 += f0.y; acc2 += f1.x; acc3 += f1.y;
    }
#pragma unroll
    for (int j = 0; j < TOPK; j++) {
        uint2 u = *(const uint2*)(g_pairout16 + (size_t)sp[j] * Dm + tid * 4);
        __half2 h0 = *(__half2*)&u.x, h1 = *(__half2*)&u.y;
        float2 f0 = __half22float2(h0), f1 = __half22float2(h1);
        acc0 += f0.x; acc1 += f0.y; acc2 += f1.x; acc3 += f1.y;
    }
    *(float4*)(out + (size_t)t * Dm + tid * 4) = make_float4(acc0, acc1, acc2, acc3);
}

// ---------------- launch ----------------
extern "C" void kernel_launch(void* const* d_in, const int* in_sizes, int n_in,
                              void* d_out, int out_size)
{
    const float* x   = (const float*)d_in[0];
    const float* rw  = (const float*)d_in[1];
    const float* rb  = (const float*)d_in[2];
    const float* w1  = (const float*)d_in[3];
    const float* b1  = (const float*)d_in[4];
    const float* w2  = (const float*)d_in[5];
    const float* b2  = (const float*)d_in[6];
    const float* sw1 = (const float*)d_in[7];
    const float* sb1 = (const float*)d_in[8];
    const float* sw2 = (const float*)d_in[9];
    const float* sb2 = (const float*)d_in[10];
    float* out = (float*)d_out;

    zero_counts_kernel<<<1, 64>>>();
    router_kernel<<<Tn / 32, 256>>>(x, rw, rb);
    scan_kernel<<<1, 32>>>();
    fill_kernel<<<(Tn + 255) / 256, 256>>>();
    k_g1_routed<<<dim3(MAXTILES, Hh / 128),  128>>>(x, w1, b1);
    k_g2_routed<<<dim3(MAXTILES, Dm / 128),  128>>>(w2, b2);
    k_g1_shared<<<dim3(Tn / 128, HSn / 128, ESn), 128>>>(x, sw1, sb1);
    k_g2_shared<<<dim3(Tn / 128, Dm / 128, ESn),  128>>>(sw2, sb2);
    combine_kernel<<<Tn, 256>>>(out);
}

// round 8
// speedup vs baseline: 2.9199x; 1.0608x over previous
#include <cuda_runtime.h>
#include <cuda_fp16.h>
#include <cstdint>
#include <math.h>

#define Tn   2048
#define Dm   1024
#define Ne   64
#define TOPK 8
#define Hh   256
#define ESn  2
#define HSn  2048
#define MAXP (Tn * TOPK)
#define MAXTILES 256

// ---------------- static scratch ----------------
__device__ float g_topw[MAXP];
__device__ int   g_topi[MAXP];
__device__ int   g_slot2pair[MAXP];
__device__ int   g_count[Ne];
__device__ int   g_offset[Ne];
__device__ int   g_cursor[Ne];
__device__ int   g_pair_token[MAXP];
__device__ float g_pair_w[MAXP];
__device__ int   g_ntiles;
__device__ int   g_tile_e[MAXTILES];
__device__ int   g_tile_row[MAXTILES];
__device__ __half g_pairout16[(size_t)MAXP * Dm];
__device__ __half g_sharedout16[(size_t)ESn * Tn * Dm];
__device__ __half g_H16[(size_t)MAXP * Hh];
__device__ __half g_Hs16[(size_t)ESn * Tn * HSn];

__device__ __forceinline__ uint32_t smem_u32(const void* p) {
    uint32_t a;
    asm("{ .reg .u64 t; cvta.to.shared.u64 t, %1; cvt.u32.u64 %0, t; }" : "=r"(a) : "l"(p));
    return a;
}
__device__ __forceinline__ float silu_f(float c) { return c / (1.0f + __expf(-c)); }

__device__ __forceinline__ void ldsm_x4(uint32_t* r, uint32_t addr) {
    asm volatile("ldmatrix.sync.aligned.m8n8.x4.shared.b16 {%0,%1,%2,%3}, [%4];"
        : "=r"(r[0]), "=r"(r[1]), "=r"(r[2]), "=r"(r[3]) : "r"(addr));
}
__device__ __forceinline__ void ldsm_x4_trans(uint32_t* r, uint32_t addr) {
    asm volatile("ldmatrix.sync.aligned.m8n8.x4.trans.shared.b16 {%0,%1,%2,%3}, [%4];"
        : "=r"(r[0]), "=r"(r[1]), "=r"(r[2]), "=r"(r[3]) : "r"(addr));
}
__device__ __forceinline__ void mma_fp16(float* d, const uint32_t* a, uint32_t b0, uint32_t b1) {
    asm volatile(
        "mma.sync.aligned.m16n8k16.row.col.f32.f16.f16.f32 "
        "{%0,%1,%2,%3}, {%4,%5,%6,%7}, {%8,%9}, {%0,%1,%2,%3};"
        : "+f"(d[0]), "+f"(d[1]), "+f"(d[2]), "+f"(d[3])
        : "r"(a[0]), "r"(a[1]), "r"(a[2]), "r"(a[3]), "r"(b0), "r"(b1));
}
__device__ __forceinline__ uint4 pack8h(float4 v0, float4 v1) {
    __half2 h0 = __floats2half2_rn(v0.x, v0.y);
    __half2 h1 = __floats2half2_rn(v0.z, v0.w);
    __half2 h2 = __floats2half2_rn(v1.x, v1.y);
    __half2 h3 = __floats2half2_rn(v1.z, v1.w);
    return make_uint4(*(uint32_t*)&h0, *(uint32_t*)&h1, *(uint32_t*)&h2, *(uint32_t*)&h3);
}

// smem layout (bytes):
//  [0,512)      rows_s (128 ints)
//  [512,1024)   scale_s (128 floats)
//  A0 @1024  (128 rows x 80B)       = 10240
//  A1 @11264
//  B0 @21504 (32 k-rows x 272B)     = 8704
//  B1 @30208  ... end 38912
//  stage (epilogue) reuses @1024: 128 x 68 floats = 34816
#define SMEM_TOT 38912
#define PA_B 80
#define PB_B 272

struct GemmArgs {
    const void* A; int lda; const int* gather; int valid;  // A fp32 or fp16 per template
    const float* W; int ldw; int n0;                       // W always fp32 source
    int K;
    const float* bias;
    const float* rowScale;   // nullable
    __half* outH;
    int ldo;
    bool silu;
};

template <bool A16>
__device__ void gemm128(const GemmArgs g) {
    __shared__ char smc[SMEM_TOT];
    int*   rows_s  = (int*)smc;
    float* scale_s = (float*)(smc + 512);
    float* stage   = (float*)(smc + 1024);

    const uint32_t sbase = smem_u32(smc);
    const uint32_t sA[2] = { sbase + 1024u, sbase + 11264u };
    const uint32_t sB[2] = { sbase + 21504u, sbase + 30208u };
    char* pAc[2] = { smc + 1024, smc + 11264 };
    char* pBc[2] = { smc + 21504, smc + 30208 };

    const int tid = threadIdx.x;
    const int lane = tid & 31, w = tid >> 5;
    const int mw = w & 3, nw = w >> 2;          // 4 M-warps x 2 N-warps
    const int gg = lane >> 2, cc = lane & 3;
    const int arow = (lane & 7) + ((lane >> 3) & 1) * 8;
    const int kh = (lane >> 4) & 1;

    if (tid < 128) {
        bool v = tid < g.valid;
        rows_s[tid]  = g.gather ? (v ? g.gather[tid] : -1) : (v ? tid : -1);
        scale_s[tid] = (g.rowScale && v) ? g.rowScale[tid] : 1.0f;
    }
    __syncthreads();

    float acc[2][8][4];
#pragma unroll
    for (int i = 0; i < 2; i++)
#pragma unroll
        for (int j = 0; j < 8; j++)
#pragma unroll
            for (int q = 0; q < 4; q++) acc[i][j][q] = 0.0f;

    const int nch = g.K >> 5;
    const float4 zf4 = make_float4(0.f, 0.f, 0.f, 0.f);
    const uint4  zu4 = make_uint4(0u, 0u, 0u, 0u);

    // prefetch registers (per thread: A 8 elems x2 iters, B 8 elems x2 iters)
    uint4  paH[2];
    float4 paF[2][2];
    float4 pbF[2][2];

    const __half* A16p = (const __half*)g.A;
    const float*  A32p = (const float*)g.A;

    auto loadA = [&](int k0) {
#pragma unroll
        for (int i = 0; i < 2; i++) {
            int q = tid + i * 256; int r = q >> 2, c = q & 3;
            int gr = rows_s[r];
            if (A16) {
                paH[i] = (gr >= 0) ? *(const uint4*)(A16p + (size_t)gr * g.lda + k0 + c * 8) : zu4;
            } else {
                if (gr >= 0) {
                    paF[i][0] = *(const float4*)(A32p + (size_t)gr * g.lda + k0 + c * 8);
                    paF[i][1] = *(const float4*)(A32p + (size_t)gr * g.lda + k0 + c * 8 + 4);
                } else { paF[i][0] = zf4; paF[i][1] = zf4; }
            }
        }
    };
    auto loadB = [&](int k0) {
#pragma unroll
        for (int i = 0; i < 2; i++) {
            int q = tid + i * 256; int k = q >> 4, c = q & 15;
            pbF[i][0] = *(const float4*)(g.W + (size_t)(k0 + k) * g.ldw + g.n0 + c * 8);
            pbF[i][1] = *(const float4*)(g.W + (size_t)(k0 + k) * g.ldw + g.n0 + c * 8 + 4);
        }
    };
    auto storeA = [&](int buf) {
#pragma unroll
        for (int i = 0; i < 2; i++) {
            int q = tid + i * 256; int r = q >> 2, c = q & 3;
            uint4 v = A16 ? paH[i] : pack8h(paF[i][0], paF[i][1]);
            *(uint4*)(pAc[buf] + r * PA_B + c * 16) = v;
        }
    };
    auto storeB = [&](int buf) {
#pragma unroll
        for (int i = 0; i < 2; i++) {
            int q = tid + i * 256; int k = q >> 4, c = q & 15;
            *(uint4*)(pBc[buf] + k * PB_B + c * 16) = pack8h(pbF[i][0], pbF[i][1]);
        }
    };

    loadA(0); loadB(0);
    storeA(0); storeB(0);
    __syncthreads();

    for (int c = 0; c < nch; c++) {
        const int cur = c & 1, nxt = cur ^ 1;
        const bool more = (c + 1) < nch;
        if (more) { loadA((c + 1) << 5); loadB((c + 1) << 5); }

        const uint32_t Ab = sA[cur], Bb = sB[cur];
#pragma unroll
        for (int ks = 0; ks < 2; ks++) {
            uint32_t a[2][4], bf[8][2];
#pragma unroll
            for (int ma = 0; ma < 2; ma++) {
                uint32_t addr = Ab + (uint32_t)((mw * 32 + ma * 16 + arow) * PA_B + ks * 32 + kh * 16);
                ldsm_x4(a[ma], addr);
            }
#pragma unroll
            for (int p = 0; p < 4; p++) {
                uint32_t r4[4];
                uint32_t addr = Bb + (uint32_t)((ks * 16 + arow) * PB_B + (nw * 64 + p * 16 + kh * 8) * 2);
                ldsm_x4_trans(r4, addr);
                bf[2 * p][0] = r4[0]; bf[2 * p][1] = r4[1];
                bf[2 * p + 1][0] = r4[2]; bf[2 * p + 1][1] = r4[3];
            }
#pragma unroll
            for (int ma = 0; ma < 2; ma++)
#pragma unroll
                for (int nb = 0; nb < 8; nb++)
                    mma_fp16(acc[ma][nb], a[ma], bf[nb][0], bf[nb][1]);
        }
        if (more) { storeA(nxt); storeB(nxt); }
        __syncthreads();
    }

    // epilogue: two 64-col slabs via smem stage, fp16 output
#pragma unroll
    for (int slab = 0; slab < 2; slab++) {
        if (nw == slab) {
#pragma unroll
            for (int ma = 0; ma < 2; ma++) {
                int r0 = mw * 32 + ma * 16 + gg, r1 = r0 + 8;
                float s0 = scale_s[r0], s1 = scale_s[r1];
#pragma unroll
                for (int nb = 0; nb < 8; nb++) {
                    int col = nb * 8 + cc * 2;
                    int n = g.n0 + slab * 64 + col;
                    float bv0 = g.bias[n], bv1 = g.bias[n + 1];
                    float f0 = acc[ma][nb][0] + bv0;
                    float f1 = acc[ma][nb][1] + bv1;
                    float f2 = acc[ma][nb][2] + bv0;
                    float f3 = acc[ma][nb][3] + bv1;
                    if (g.silu) { f0 = silu_f(f0); f1 = silu_f(f1); f2 = silu_f(f2); f3 = silu_f(f3); }
                    *(float2*)(stage + r0 * 68 + col) = make_float2(f0 * s0, f1 * s0);
                    *(float2*)(stage + r1 * 68 + col) = make_float2(f2 * s1, f3 * s1);
                }
            }
        }
        __syncthreads();
        for (int q = tid; q < 128 * 16; q += 256) {
            int r = q >> 4, c4 = q & 15;
            if (r < g.valid) {
                float4 v = *(float4*)(stage + r * 68 + c4 * 4);
                __half2 h0 = __floats2half2_rn(v.x, v.y);
                __half2 h1 = __floats2half2_rn(v.z, v.w);
                *(uint2*)(g.outH + (size_t)r * g.ldo + g.n0 + slab * 64 + c4 * 4) =
                    make_uint2(*(uint32_t*)&h0, *(uint32_t*)&h1);
            }
        }
        __syncthreads();
    }
}

// ---------------- GEMM kernel wrappers ----------------
__global__ void __launch_bounds__(256, 2) k_g1_routed(const float* x, const float* w1, const float* b1) {
    int t = blockIdx.x;
    if (t >= g_ntiles) return;
    int e = g_tile_e[t], rb = g_tile_row[t];
    int cnt = g_count[e], off = g_offset[e];
    GemmArgs a;
    a.A = x; a.lda = Dm; a.gather = g_pair_token + off + rb; a.valid = min(128, cnt - rb);
    a.W = w1 + (size_t)e * Dm * Hh; a.ldw = Hh; a.n0 = blockIdx.y * 128;
    a.K = Dm; a.bias = b1 + e * Hh; a.rowScale = nullptr;
    a.outH = g_H16 + (size_t)(off + rb) * Hh; a.ldo = Hh; a.silu = true;
    gemm128<false>(a);
}
__global__ void __launch_bounds__(256, 2) k_g2_routed(const float* w2, const float* b2) {
    int t = blockIdx.x;
    if (t >= g_ntiles) return;
    int e = g_tile_e[t], rb = g_tile_row[t];
    int cnt = g_count[e], off = g_offset[e];
    GemmArgs a;
    a.A = g_H16 + (size_t)(off + rb) * Hh; a.lda = Hh; a.gather = nullptr; a.valid = min(128, cnt - rb);
    a.W = w2 + (size_t)e * Hh * Dm; a.ldw = Dm; a.n0 = blockIdx.y * 128;
    a.K = Hh; a.bias = b2 + (size_t)e * Dm; a.rowScale = g_pair_w + off + rb;
    a.outH = g_pairout16 + (size_t)(off + rb) * Dm; a.ldo = Dm; a.silu = false;
    gemm128<true>(a);
}
__global__ void __launch_bounds__(256, 2) k_g1_shared(const float* x, const float* sw1, const float* sb1) {
    int es = blockIdx.z, row0 = blockIdx.x * 128;
    GemmArgs a;
    a.A = x + (size_t)row0 * Dm; a.lda = Dm; a.gather = nullptr; a.valid = 128;
    a.W = sw1 + (size_t)es * Dm * HSn; a.ldw = HSn; a.n0 = blockIdx.y * 128;
    a.K = Dm; a.bias = sb1 + (size_t)es * HSn; a.rowScale = nullptr;
    a.outH = g_Hs16 + (size_t)es * Tn * HSn + (size_t)row0 * HSn; a.ldo = HSn; a.silu = true;
    gemm128<false>(a);
}
__global__ void __launch_bounds__(256, 2) k_g2_shared(const float* sw2, const float* sb2) {
    int es = blockIdx.z, row0 = blockIdx.x * 128;
    GemmArgs a;
    a.A = g_Hs16 + (size_t)es * Tn * HSn + (size_t)row0 * HSn; a.lda = HSn; a.gather = nullptr; a.valid = 128;
    a.W = sw2 + (size_t)es * HSn * Dm; a.ldw = Dm; a.n0 = blockIdx.y * 128;
    a.K = HSn; a.bias = sb2 + (size_t)es * Dm; a.rowScale = nullptr;
    a.outH = g_sharedout16 + (size_t)es * Tn * Dm + (size_t)row0 * Dm; a.ldo = Dm; a.silu = false;
    gemm128<true>(a);
}

// ---------------- routing bookkeeping ----------------
__global__ void zero_counts_kernel() {
    if (threadIdx.x < Ne) g_count[threadIdx.x] = 0;
}

__global__ void __launch_bounds__(256) router_kernel(
    const float* __restrict__ x, const float* __restrict__ rw, const float* __restrict__ rb)
{
    __shared__ float xs[64][33];
    __shared__ float ws[64][65];
    __shared__ float lg[32][65];
    int tid = threadIdx.x;
    int tbase = blockIdx.x * 32;
    int e = tid & 63, tg = tid >> 6;
    float acc[8];
#pragma unroll
    for (int i = 0; i < 8; i++) acc[i] = 0.0f;
    for (int d0 = 0; d0 < Dm; d0 += 64) {
#pragma unroll
        for (int q = 0; q < 8; q++) {
            int idx = tid + q * 256; int t = idx >> 6, dd = idx & 63;
            xs[dd][t] = x[(size_t)(tbase + t) * Dm + d0 + dd];
        }
#pragma unroll
        for (int q = 0; q < 16; q++) {
            int idx = tid + q * 256; int dd = idx >> 6, ee = idx & 63;
            ws[dd][ee] = rw[(size_t)(d0 + dd) * Ne + ee];
        }
        __syncthreads();
#pragma unroll
        for (int dd = 0; dd < 64; dd++) {
            float wv = ws[dd][e];
#pragma unroll
            for (int i = 0; i < 8; i++) acc[i] += xs[dd][tg + 4 * i] * wv;
        }
        __syncthreads();
    }
#pragma unroll
    for (int i = 0; i < 8; i++) lg[tg + 4 * i][e] = acc[i] + rb[e];
    __syncthreads();
    if (tid < 32) {
        int t = tid;
        float vals[TOPK]; int idxs[TOPK];
#pragma unroll
        for (int p = 0; p < TOPK; p++) {
            float best = -1e30f; int bi = 0;
            for (int ee = 0; ee < Ne; ee++) {
                float v = lg[t][ee];
                if (v > best) { best = v; bi = ee; }
            }
            vals[p] = best; idxs[p] = bi; lg[t][bi] = -1e30f;
        }
        float m = vals[0], wv[TOPK], s = 0.0f;
#pragma unroll
        for (int p = 0; p < TOPK; p++) { wv[p] = __expf(vals[p] - m); s += wv[p]; }
        float inv = 1.0f / s;
        int gt = tbase + t;
#pragma unroll
        for (int p = 0; p < TOPK; p++) {
            g_topw[gt * TOPK + p] = wv[p] * inv;
            g_topi[gt * TOPK + p] = idxs[p];
            atomicAdd(&g_count[idxs[p]], 1);
        }
    }
}

__global__ void scan_kernel() {
    if (threadIdx.x == 0) {
        int run = 0, nt = 0;
        for (int e = 0; e < Ne; e++) {
            g_offset[e] = run; g_cursor[e] = run;
            int c = g_count[e];
            int tiles = (c + 127) >> 7;
            for (int i = 0; i < tiles; i++) { g_tile_e[nt] = e; g_tile_row[nt] = i * 128; nt++; }
            run += c;
        }
        g_ntiles = nt;
    }
}

__global__ void fill_kernel() {
    int t = blockIdx.x * 256 + threadIdx.x;
    if (t < Tn) {
#pragma unroll
        for (int j = 0; j < TOPK; j++) {
            int e = g_topi[t * TOPK + j];
            int pos = atomicAdd(&g_cursor[e], 1);
            g_pair_token[pos] = t;
            g_pair_w[pos] = g_topw[t * TOPK + j];
            g_slot2pair[t * TOPK + j] = pos;
        }
    }
}

// ---------------- combine (fp16 inputs, fp32 accumulate) ----------------
__global__ void __launch_bounds__(256) combine_kernel(float* __restrict__ out) {
    int t = blockIdx.x, tid = threadIdx.x;
    __shared__ int sp[TOPK];
    if (tid < TOPK) sp[tid] = g_slot2pair[t * TOPK + tid];
    __syncthreads();
    float acc0, acc1, acc2, acc3;
    {
        uint2 u = *(const uint2*)(g_sharedout16 + (size_t)t * Dm + tid * 4);
        __half2 h0 = *(__half2*)&u.x, h1 = *(__half2*)&u.y;
        float2 f0 = __half22float2(h0), f1 = __half22float2(h1);
        acc0 = f0.x; acc1 = f0.y; acc2 = f1.x; acc3 = f1.y;
    }
    {
        uint2 u = *(const uint2*)(g_sharedout16 + (size_t)Tn * Dm + (size_t)t * Dm + tid * 4);
        __half2 h0 = *(__half2*)&u.x, h1 = *(__half2*)&u.y;
        float2 f0 = __half22float2(h0), f1 = __half22float2(h1);
        acc0 += f0.x; acc1 += f0.y; acc2 += f1.x; acc3 += f1.y;
    }
#pragma unroll
    for (int j = 0; j < TOPK; j++) {
        uint2 u = *(const uint2*)(g_pairout16 + (size_t)sp[j] * Dm + tid * 4);
        __half2 h0 = *(__half2*)&u.x, h1 = *(__half2*)&u.y;
        float2 f0 = __half22float2(h0), f1 = __half22float2(h1);
        acc0 += f0.x; acc1 += f0.y; acc2 += f1.x; acc3 += f1.y;
    }
    *(float4*)(out + (size_t)t * Dm + tid * 4) = make_float4(acc0, acc1, acc2, acc3);
}

// ---------------- launch ----------------
extern "C" void kernel_launch(void* const* d_in, const int* in_sizes, int n_in,
                              void* d_out, int out_size)
{
    const float* x   = (const float*)d_in[0];
    const float* rw  = (const float*)d_in[1];
    const float* rb  = (const float*)d_in[2];
    const float* w1  = (const float*)d_in[3];
    const float* b1  = (const float*)d_in[4];
    const float* w2  = (const float*)d_in[5];
    const float* b2  = (const float*)d_in[6];
    const float* sw1 = (const float*)d_in[7];
    const float* sb1 = (const float*)d_in[8];
    const float* sw2 = (const float*)d_in[9];
    const float* sb2 = (const float*)d_in[10];
    float* out = (float*)d_out;

    zero_counts_kernel<<<1, 64>>>();
    router_kernel<<<Tn / 32, 256>>>(x, rw, rb);
    scan_kernel<<<1, 32>>>();
    fill_kernel<<<(Tn + 255) / 256, 256>>>();
    k_g1_routed<<<dim3(MAXTILES, Hh / 128),  256>>>(x, w1, b1);
    k_g2_routed<<<dim3(MAXTILES, Dm / 128),  256>>>(w2, b2);
    k_g1_shared<<<dim3(Tn / 128, HSn / 128, ESn), 256>>>(x, sw1, sb1);
    k_g2_shared<<<dim3(Tn / 128, Dm / 128, ESn),  256>>>(sw2, sb2);
    combine_kernel<<<Tn, 256>>>(out);
}

// round 9
// speedup vs baseline: 3.6214x; 1.2402x over previous
#include <cuda_runtime.h>
#include <cuda_fp16.h>
#include <cstdint>
#include <math.h>

#define Tn   2048
#define Dm   1024
#define Ne   64
#define TOPK 8
#define Hh   256
#define ESn  2
#define HSn  2048
#define MAXP (Tn * TOPK)
#define MAXTILES 256

// ---------------- static scratch ----------------
__device__ float g_topw[MAXP];
__device__ int   g_topi[MAXP];
__device__ int   g_slot2pair[MAXP];
__device__ int   g_count[Ne];
__device__ int   g_offset[Ne];
__device__ int   g_cursor[Ne];
__device__ int   g_pair_token[MAXP];
__device__ float g_pair_w[MAXP];
__device__ int   g_ntiles;
__device__ int   g_tile_e[MAXTILES];
__device__ int   g_tile_row[MAXTILES];
__device__ __half g_pairout16[(size_t)MAXP * Dm];
__device__ __half g_sharedout16[(size_t)ESn * Tn * Dm];
__device__ __half g_H16[(size_t)MAXP * Hh];
__device__ __half g_Hs16[(size_t)ESn * Tn * HSn];
// fp16 operand copies
__device__ __half g_x16[(size_t)Tn * Dm];
__device__ __half g_w116[(size_t)Ne * Dm * Hh];
__device__ __half g_w216[(size_t)Ne * Hh * Dm];
__device__ __half g_sw116[(size_t)ESn * Dm * HSn];
__device__ __half g_sw216[(size_t)ESn * HSn * Dm];

__device__ __forceinline__ uint32_t smem_u32(const void* p) {
    uint32_t a;
    asm("{ .reg .u64 t; cvta.to.shared.u64 t, %1; cvt.u32.u64 %0, t; }" : "=r"(a) : "l"(p));
    return a;
}
__device__ __forceinline__ float silu_f(float c) { return c / (1.0f + __expf(-c)); }

__device__ __forceinline__ void ldsm_x4(uint32_t* r, uint32_t addr) {
    asm volatile("ldmatrix.sync.aligned.m8n8.x4.shared.b16 {%0,%1,%2,%3}, [%4];"
        : "=r"(r[0]), "=r"(r[1]), "=r"(r[2]), "=r"(r[3]) : "r"(addr));
}
__device__ __forceinline__ void ldsm_x4_trans(uint32_t* r, uint32_t addr) {
    asm volatile("ldmatrix.sync.aligned.m8n8.x4.trans.shared.b16 {%0,%1,%2,%3}, [%4];"
        : "=r"(r[0]), "=r"(r[1]), "=r"(r[2]), "=r"(r[3]) : "r"(addr));
}
__device__ __forceinline__ void mma_fp16(float* d, const uint32_t* a, uint32_t b0, uint32_t b1) {
    asm volatile(
        "mma.sync.aligned.m16n8k16.row.col.f32.f16.f16.f32 "
        "{%0,%1,%2,%3}, {%4,%5,%6,%7}, {%8,%9}, {%0,%1,%2,%3};"
        : "+f"(d[0]), "+f"(d[1]), "+f"(d[2]), "+f"(d[3])
        : "r"(a[0]), "r"(a[1]), "r"(a[2]), "r"(a[3]), "r"(b0), "r"(b1));
}
__device__ __forceinline__ void cp16(uint32_t dst, const void* src, uint32_t sz) {
    asm volatile("cp.async.cg.shared.global [%0], [%1], 16, %2;"
        :: "r"(dst), "l"(src), "r"(sz) : "memory");
}
#define CP_COMMIT() asm volatile("cp.async.commit_group;" ::: "memory")
#define CP_WAIT(n)  asm volatile("cp.async.wait_group %0;" :: "n"(n) : "memory")

// pipeline geometry
#define NSTAGE 4
#define PA_B 80
#define PB_B 272
#define STG_A 10240                // 128 rows x 80B
#define STG_B 8704                 // 32 rows x 272B
#define STG_BYTES (STG_A + STG_B)  // 18944
#define SMEM_DYN (1024 + NSTAGE * STG_BYTES)   // 76800

struct GemmArgs {
    const __half* A; int lda; const int* gather; int valid;
    const __half* W; int ldw; int n0;
    int K;
    const float* bias;
    const float* rowScale;   // nullable
    __half* outH;
    int ldo;
    bool silu;
};

__device__ void gemm128(const GemmArgs g) {
    extern __shared__ char smc[];
    int*   rows_s  = (int*)smc;
    float* scale_s = (float*)(smc + 512);
    float* stage   = (float*)(smc + 1024);
    const uint32_t sbase = smem_u32(smc);

    const int tid = threadIdx.x;
    const int lane = tid & 31, w = tid >> 5;
    const int mw = w & 3, nw = w >> 2;          // 4 M-warps x 2 N-warps
    const int gg = lane >> 2, cc = lane & 3;
    const int arow = (lane & 7) + ((lane >> 3) & 1) * 8;
    const int kh = (lane >> 4) & 1;

    if (tid < 128) {
        bool v = tid < g.valid;
        rows_s[tid]  = g.gather ? (v ? g.gather[tid] : -1) : (v ? tid : -1);
        scale_s[tid] = (g.rowScale && v) ? g.rowScale[tid] : 1.0f;
    }
    __syncthreads();

    // per-thread producer constants (fixed across chunks)
    const __half* asrc[2]; uint32_t aoff[2], asz[2];
    const __half* bsrc[2]; uint32_t boff[2];
#pragma unroll
    for (int i = 0; i < 2; i++) {
        int idx = tid + i * 256;
        int r = idx >> 2, c = idx & 3;
        int gr = rows_s[r];
        asrc[i] = g.A + (gr >= 0 ? (size_t)gr * g.lda : 0) + c * 8;
        asz[i]  = (gr >= 0) ? 16u : 0u;
        aoff[i] = (uint32_t)(r * PA_B + c * 16);
        int k = idx >> 4, bc = idx & 15;
        bsrc[i] = g.W + (size_t)k * g.ldw + g.n0 + bc * 8;
        boff[i] = (uint32_t)(STG_A + k * PB_B + bc * 16);
    }

    float acc[2][8][4];
#pragma unroll
    for (int i = 0; i < 2; i++)
#pragma unroll
        for (int j = 0; j < 8; j++)
#pragma unroll
            for (int q = 0; q < 4; q++) acc[i][j][q] = 0.0f;

    const int nch = g.K >> 5;

    auto issue = [&](int chunk) {
        uint32_t sb = sbase + 1024u + (uint32_t)(chunk & (NSTAGE - 1)) * STG_BYTES;
        int k0 = chunk << 5;
        size_t bstep = (size_t)k0 * g.ldw;
#pragma unroll
        for (int i = 0; i < 2; i++) cp16(sb + aoff[i], asrc[i] + k0, asz[i]);
#pragma unroll
        for (int i = 0; i < 2; i++) cp16(sb + boff[i], bsrc[i] + bstep, 16u);
    };

    // prologue: 3 stages in flight
    issue(0); CP_COMMIT();
    issue(1); CP_COMMIT();
    issue(2); CP_COMMIT();

    for (int c = 0; c < nch; c++) {
        CP_WAIT(2);
        __syncthreads();
        const uint32_t sb = sbase + 1024u + (uint32_t)(c & (NSTAGE - 1)) * STG_BYTES;
        const uint32_t Ab = sb, Bb = sb + STG_A;
#pragma unroll
        for (int ks = 0; ks < 2; ks++) {
            uint32_t a[2][4], bf[8][2];
#pragma unroll
            for (int ma = 0; ma < 2; ma++) {
                uint32_t addr = Ab + (uint32_t)((mw * 32 + ma * 16 + arow) * PA_B + ks * 32 + kh * 16);
                ldsm_x4(a[ma], addr);
            }
#pragma unroll
            for (int p = 0; p < 4; p++) {
                uint32_t r4[4];
                uint32_t addr = Bb + (uint32_t)((ks * 16 + arow) * PB_B + (nw * 64 + p * 16 + kh * 8) * 2);
                ldsm_x4_trans(r4, addr);
                bf[2 * p][0] = r4[0]; bf[2 * p][1] = r4[1];
                bf[2 * p + 1][0] = r4[2]; bf[2 * p + 1][1] = r4[3];
            }
#pragma unroll
            for (int ma = 0; ma < 2; ma++)
#pragma unroll
                for (int nb = 0; nb < 8; nb++)
                    mma_fp16(acc[ma][nb], a[ma], bf[nb][0], bf[nb][1]);
        }
        if (c + 3 < nch) issue(c + 3);
        CP_COMMIT();
    }
    CP_WAIT(0);
    __syncthreads();

    // epilogue: two 64-col slabs via smem stage, fp16 output
#pragma unroll
    for (int slab = 0; slab < 2; slab++) {
        if (nw == slab) {
#pragma unroll
            for (int ma = 0; ma < 2; ma++) {
                int r0 = mw * 32 + ma * 16 + gg, r1 = r0 + 8;
                float s0 = scale_s[r0], s1 = scale_s[r1];
#pragma unroll
                for (int nb = 0; nb < 8; nb++) {
                    int col = nb * 8 + cc * 2;
                    int n = g.n0 + slab * 64 + col;
                    float bv0 = g.bias[n], bv1 = g.bias[n + 1];
                    float f0 = acc[ma][nb][0] + bv0;
                    float f1 = acc[ma][nb][1] + bv1;
                    float f2 = acc[ma][nb][2] + bv0;
                    float f3 = acc[ma][nb][3] + bv1;
                    if (g.silu) { f0 = silu_f(f0); f1 = silu_f(f1); f2 = silu_f(f2); f3 = silu_f(f3); }
                    *(float2*)(stage + r0 * 68 + col) = make_float2(f0 * s0, f1 * s0);
                    *(float2*)(stage + r1 * 68 + col) = make_float2(f2 * s1, f3 * s1);
                }
            }
        }
        __syncthreads();
        for (int q = tid; q < 128 * 16; q += 256) {
            int r = q >> 4, c4 = q & 15;
            if (r < g.valid) {
                float4 v = *(float4*)(stage + r * 68 + c4 * 4);
                __half2 h0 = __floats2half2_rn(v.x, v.y);
                __half2 h1 = __floats2half2_rn(v.z, v.w);
                *(uint2*)(g.outH + (size_t)r * g.ldo + g.n0 + slab * 64 + c4 * 4) =
                    make_uint2(*(uint32_t*)&h0, *(uint32_t*)&h1);
            }
        }
        __syncthreads();
    }
}

// ---------------- GEMM kernel wrappers ----------------
__global__ void __launch_bounds__(256, 2) k_g1_routed(const float* b1) {
    int t = blockIdx.x;
    if (t >= g_ntiles) return;
    int e = g_tile_e[t], rb = g_tile_row[t];
    int cnt = g_count[e], off = g_offset[e];
    GemmArgs a;
    a.A = g_x16; a.lda = Dm; a.gather = g_pair_token + off + rb; a.valid = min(128, cnt - rb);
    a.W = g_w116 + (size_t)e * Dm * Hh; a.ldw = Hh; a.n0 = blockIdx.y * 128;
    a.K = Dm; a.bias = b1 + e * Hh; a.rowScale = nullptr;
    a.outH = g_H16 + (size_t)(off + rb) * Hh; a.ldo = Hh; a.silu = true;
    gemm128(a);
}
__global__ void __launch_bounds__(256, 2) k_g2_routed(const float* b2) {
    int t = blockIdx.x;
    if (t >= g_ntiles) return;
    int e = g_tile_e[t], rb = g_tile_row[t];
    int cnt = g_count[e], off = g_offset[e];
    GemmArgs a;
    a.A = g_H16 + (size_t)(off + rb) * Hh; a.lda = Hh; a.gather = nullptr; a.valid = min(128, cnt - rb);
    a.W = g_w216 + (size_t)e * Hh * Dm; a.ldw = Dm; a.n0 = blockIdx.y * 128;
    a.K = Hh; a.bias = b2 + (size_t)e * Dm; a.rowScale = g_pair_w + off + rb;
    a.outH = g_pairout16 + (size_t)(off + rb) * Dm; a.ldo = Dm; a.silu = false;
    gemm128(a);
}
__global__ void __launch_bounds__(256, 2) k_g1_shared(const float* sb1) {
    int es = blockIdx.z, row0 = blockIdx.x * 128;
    GemmArgs a;
    a.A = g_x16 + (size_t)row0 * Dm; a.lda = Dm; a.gather = nullptr; a.valid = 128;
    a.W = g_sw116 + (size_t)es * Dm * HSn; a.ldw = HSn; a.n0 = blockIdx.y * 128;
    a.K = Dm; a.bias = sb1 + (size_t)es * HSn; a.rowScale = nullptr;
    a.outH = g_Hs16 + (size_t)es * Tn * HSn + (size_t)row0 * HSn; a.ldo = HSn; a.silu = true;
    gemm128(a);
}
__global__ void __launch_bounds__(256, 2) k_g2_shared(const float* sb2) {
    int es = blockIdx.z, row0 = blockIdx.x * 128;
    GemmArgs a;
    a.A = g_Hs16 + (size_t)es * Tn * HSn + (size_t)row0 * HSn; a.lda = HSn; a.gather = nullptr; a.valid = 128;
    a.W = g_sw216 + (size_t)es * HSn * Dm; a.ldw = Dm; a.n0 = blockIdx.y * 128;
    a.K = HSn; a.bias = sb2 + (size_t)es * Dm; a.rowScale = nullptr;
    a.outH = g_sharedout16 + (size_t)es * Tn * Dm + (size_t)row0 * Dm; a.ldo = Dm; a.silu = false;
    gemm128(a);
}

// ---------------- fp32 -> fp16 conversion ----------------
__global__ void __launch_bounds__(256) conv_kernel(const float* __restrict__ src, __half* __restrict__ dst, int n4) {
    for (int i = blockIdx.x * 256 + threadIdx.x; i < n4; i += gridDim.x * 256) {
        float4 v = *(const float4*)(src + (size_t)i * 4);
        __half2 h0 = __floats2half2_rn(v.x, v.y);
        __half2 h1 = __floats2half2_rn(v.z, v.w);
        uint32_t u0 = *(uint32_t*)&h0;
        uint32_t u1 = *(uint32_t*)&h1;
        *(uint2*)(dst + (size_t)i * 4) = make_uint2(u0, u1);
    }
}

// ---------------- routing bookkeeping ----------------
__global__ void zero_counts_kernel() {
    if (threadIdx.x < Ne) g_count[threadIdx.x] = 0;
}

__global__ void __launch_bounds__(256) router_kernel(
    const float* __restrict__ x, const float* __restrict__ rw, const float* __restrict__ rb)
{
    __shared__ float xs[64][33];
    __shared__ float ws[64][65];
    __shared__ float lg[32][65];
    int tid = threadIdx.x;
    int tbase = blockIdx.x * 32;
    int e = tid & 63, tg = tid >> 6;
    float acc[8];
#pragma unroll
    for (int i = 0; i < 8; i++) acc[i] = 0.0f;
    for (int d0 = 0; d0 < Dm; d0 += 64) {
#pragma unroll
        for (int q = 0; q < 8; q++) {
            int idx = tid + q * 256; int t = idx >> 6, dd = idx & 63;
            xs[dd][t] = x[(size_t)(tbase + t) * Dm + d0 + dd];
        }
#pragma unroll
        for (int q = 0; q < 16; q++) {
            int idx = tid + q * 256; int dd = idx >> 6, ee = idx & 63;
            ws[dd][ee] = rw[(size_t)(d0 + dd) * Ne + ee];
        }
        __syncthreads();
#pragma unroll
        for (int dd = 0; dd < 64; dd++) {
            float wv = ws[dd][e];
#pragma unroll
            for (int i = 0; i < 8; i++) acc[i] += xs[dd][tg + 4 * i] * wv;
        }
        __syncthreads();
    }
#pragma unroll
    for (int i = 0; i < 8; i++) lg[tg + 4 * i][e] = acc[i] + rb[e];
    __syncthreads();
    if (tid < 32) {
        int t = tid;
        float vals[TOPK]; int idxs[TOPK];
#pragma unroll
        for (int p = 0; p < TOPK; p++) {
            float best = -1e30f; int bi = 0;
            for (int ee = 0; ee < Ne; ee++) {
                float v = lg[t][ee];
                if (v > best) { best = v; bi = ee; }
            }
            vals[p] = best; idxs[p] = bi; lg[t][bi] = -1e30f;
        }
        float m = vals[0], wv[TOPK], s = 0.0f;
#pragma unroll
        for (int p = 0; p < TOPK; p++) { wv[p] = __expf(vals[p] - m); s += wv[p]; }
        float inv = 1.0f / s;
        int gt = tbase + t;
#pragma unroll
        for (int p = 0; p < TOPK; p++) {
            g_topw[gt * TOPK + p] = wv[p] * inv;
            g_topi[gt * TOPK + p] = idxs[p];
            atomicAdd(&g_count[idxs[p]], 1);
        }
    }
}

__global__ void scan_kernel() {
    if (threadIdx.x == 0) {
        int run = 0, nt = 0;
        for (int e = 0; e < Ne; e++) {
            g_offset[e] = run; g_cursor[e] = run;
            int c = g_count[e];
            int tiles = (c + 127) >> 7;
            for (int i = 0; i < tiles; i++) { g_tile_e[nt] = e; g_tile_row[nt] = i * 128; nt++; }
            run += c;
        }
        g_ntiles = nt;
    }
}

__global__ void fill_kernel() {
    int t = blockIdx.x * 256 + threadIdx.x;
    if (t < Tn) {
#pragma unroll
        for (int j = 0; j < TOPK; j++) {
            int e = g_topi[t * TOPK + j];
            int pos = atomicAdd(&g_cursor[e], 1);
            g_pair_token[pos] = t;
            g_pair_w[pos] = g_topw[t * TOPK + j];
            g_slot2pair[t * TOPK + j] = pos;
        }
    }
}

// ---------------- combine (fp16 inputs, fp32 accumulate) ----------------
__global__ void __launch_bounds__(256) combine_kernel(float* __restrict__ out) {
    int t = blockIdx.x, tid = threadIdx.x;
    __shared__ int sp[TOPK];
    if (tid < TOPK) sp[tid] = g_slot2pair[t * TOPK + tid];
    __syncthreads();
    float acc0, acc1, acc2, acc3;
    {
        uint2 u = *(const uint2*)(g_sharedout16 + (size_t)t * Dm + tid * 4);
        __half2 h0 = *(__half2*)&u.x, h1 = *(__half2*)&u.y;
        float2 f0 = __half22float2(h0), f1 = __half22float2(h1);
        acc0 = f0.x; acc1 = f0.y; acc2 = f1.x; acc3 = f1.y;
    }
    {
        uint2 u = *(const uint2*)(g_sharedout16 + (size_t)Tn * Dm + (size_t)t * Dm + tid * 4);
        __half2 h0 = *(__half2*)&u.x, h1 = *(__half2*)&u.y;
        float2 f0 = __half22float2(h0), f1 = __half22float2(h1);
        acc0 += f0.x; acc1 += f0.y; acc2 += f1.x; acc3 += f1.y;
    }
#pragma unroll
    for (int j = 0; j < TOPK; j++) {
        uint2 u = *(const uint2*)(g_pairout16 + (size_t)sp[j] * Dm + tid * 4);
        __half2 h0 = *(__half2*)&u.x, h1 = *(__half2*)&u.y;
        float2 f0 = __half22float2(h0), f1 = __half22float2(h1);
        acc0 += f0.x; acc1 += f0.y; acc2 += f1.x; acc3 += f1.y;
    }
    *(float4*)(out + (size_t)t * Dm + tid * 4) = make_float4(acc0, acc1, acc2, acc3);
}

// ---------------- launch ----------------
extern "C" void kernel_launch(void* const* d_in, const int* in_sizes, int n_in,
                              void* d_out, int out_size)
{
    const float* x   = (const float*)d_in[0];
    const float* rw  = (const float*)d_in[1];
    const float* rb  = (const float*)d_in[2];
    const float* w1  = (const float*)d_in[3];
    const float* b1  = (const float*)d_in[4];
    const float* w2  = (const float*)d_in[5];
    const float* b2  = (const float*)d_in[6];
    const float* sw1 = (const float*)d_in[7];
    const float* sb1 = (const float*)d_in[8];
    const float* sw2 = (const float*)d_in[9];
    const float* sb2 = (const float*)d_in[10];
    float* out = (float*)d_out;

    cudaFuncSetAttribute(k_g1_routed, cudaFuncAttributeMaxDynamicSharedMemorySize, SMEM_DYN);
    cudaFuncSetAttribute(k_g2_routed, cudaFuncAttributeMaxDynamicSharedMemorySize, SMEM_DYN);
    cudaFuncSetAttribute(k_g1_shared, cudaFuncAttributeMaxDynamicSharedMemorySize, SMEM_DYN);
    cudaFuncSetAttribute(k_g2_shared, cudaFuncAttributeMaxDynamicSharedMemorySize, SMEM_DYN);

    __half* x16  = nullptr; cudaGetSymbolAddress((void**)&x16,  g_x16);
    __half* w116 = nullptr; cudaGetSymbolAddress((void**)&w116, g_w116);
    __half* w216 = nullptr; cudaGetSymbolAddress((void**)&w216, g_w216);
    __half* s116 = nullptr; cudaGetSymbolAddress((void**)&s116, g_sw116);
    __half* s216 = nullptr; cudaGetSymbolAddress((void**)&s216, g_sw216);

    zero_counts_kernel<<<1, 64>>>();
    conv_kernel<<<1024, 256>>>(x,   x16,  Tn * Dm / 4);
    conv_kernel<<<2048, 256>>>(w1,  w116, Ne * Dm * Hh / 4);
    conv_kernel<<<2048, 256>>>(w2,  w216, Ne * Hh * Dm / 4);
    conv_kernel<<<2048, 256>>>(sw1, s116, ESn * Dm * HSn / 4);
    conv_kernel<<<2048, 256>>>(sw2, s216, ESn * HSn * Dm / 4);
    router_kernel<<<Tn / 32, 256>>>(x, rw, rb);
    scan_kernel<<<1, 32>>>();
    fill_kernel<<<(Tn + 255) / 256, 256>>>();
    k_g1_routed<<<dim3(MAXTILES, Hh / 128),  256, SMEM_DYN>>>(b1);
    k_g2_routed<<<dim3(MAXTILES, Dm / 128),  256, SMEM_DYN>>>(b2);
    k_g1_shared<<<dim3(Tn / 128, HSn / 128, ESn), 256, SMEM_DYN>>>(sb1);
    k_g2_shared<<<dim3(Tn / 128, Dm / 128, ESn),  256, SMEM_DYN>>>(sb2);
    combine_kernel<<<Tn, 256>>>(out);
}

// round 12
// speedup vs baseline: 3.8462x; 1.0621x over previous
#include <cuda_runtime.h>
#include <cuda_fp16.h>
#include <cstdint>
#include <math.h>

#define Tn   2048
#define Dm   1024
#define Ne   64
#define TOPK 8
#define Hh   256
#define ESn  2
#define HSn  2048
#define MAXP (Tn * TOPK)
#define MAXTILES 256

// ---------------- static scratch ----------------
__device__ float g_topw[MAXP];
__device__ int   g_topi[MAXP];
__device__ int   g_slot2pair[MAXP];
__device__ int   g_count[Ne];
__device__ int   g_offset[Ne];
__device__ int   g_cursor[Ne];
__device__ int   g_pair_token[MAXP];
__device__ float g_pair_w[MAXP];
__device__ int   g_ntiles;
__device__ int   g_tile_e[MAXTILES];
__device__ int   g_tile_row[MAXTILES];
__device__ __half g_pairout16[(size_t)MAXP * Dm];
__device__ __half g_sharedout16[(size_t)ESn * Tn * Dm];
__device__ __half g_H16[(size_t)MAXP * Hh];
__device__ __half g_Hs16[(size_t)ESn * Tn * HSn];
// fp16 operand copies
__device__ __half g_x16[(size_t)Tn * Dm];
__device__ __half g_w116[(size_t)Ne * Dm * Hh];
__device__ __half g_w216[(size_t)Ne * Hh * Dm];
__device__ __half g_sw116[(size_t)ESn * Dm * HSn];
__device__ __half g_sw216[(size_t)ESn * HSn * Dm];

__device__ __forceinline__ uint32_t smem_u32(const void* p) {
    uint32_t a;
    asm("{ .reg .u64 t; cvta.to.shared.u64 t, %1; cvt.u32.u64 %0, t; }" : "=r"(a) : "l"(p));
    return a;
}
__device__ __forceinline__ float silu_f(float c) { return c / (1.0f + __expf(-c)); }

__device__ __forceinline__ void ldsm_x4(uint32_t* r, uint32_t addr) {
    asm volatile("ldmatrix.sync.aligned.m8n8.x4.shared.b16 {%0,%1,%2,%3}, [%4];"
        : "=r"(r[0]), "=r"(r[1]), "=r"(r[2]), "=r"(r[3]) : "r"(addr));
}
__device__ __forceinline__ void ldsm_x4_trans(uint32_t* r, uint32_t addr) {
    asm volatile("ldmatrix.sync.aligned.m8n8.x4.trans.shared.b16 {%0,%1,%2,%3}, [%4];"
        : "=r"(r[0]), "=r"(r[1]), "=r"(r[2]), "=r"(r[3]) : "r"(addr));
}
__device__ __forceinline__ void mma_fp16(float* d, const uint32_t* a, uint32_t b0, uint32_t b1) {
    asm volatile(
        "mma.sync.aligned.m16n8k16.row.col.f32.f16.f16.f32 "
        "{%0,%1,%2,%3}, {%4,%5,%6,%7}, {%8,%9}, {%0,%1,%2,%3};"
        : "+f"(d[0]), "+f"(d[1]), "+f"(d[2]), "+f"(d[3])
        : "r"(a[0]), "r"(a[1]), "r"(a[2]), "r"(a[3]), "r"(b0), "r"(b1));
}
__device__ __forceinline__ void cp16(uint32_t dst, const void* src, uint32_t sz) {
    asm volatile("cp.async.cg.shared.global [%0], [%1], 16, %2;"
        :: "r"(dst), "l"(src), "r"(sz) : "memory");
}
#define CP_COMMIT() asm volatile("cp.async.commit_group;" ::: "memory")
#define CP_WAIT(n)  asm volatile("cp.async.wait_group %0;" :: "n"(n) : "memory")

// pipeline geometry: K-chunk = 64
#define NSTAGE 3
#define PA_B 144                   // 128B row + 16B pad (16-aligned)
#define PB_B 272                   // 256B row + 16B pad
#define STG_A 18432                // 128 rows x 144B
#define STG_B 17408                // 64 k-rows x 272B
#define STG_BYTES (STG_A + STG_B)  // 35840
#define SMEM_DYN (1024 + NSTAGE * STG_BYTES)   // 108544

struct GemmArgs {
    const __half* A; int lda; const int* gather; int valid;
    const __half* W; int ldw; int n0;
    int K;
    const float* bias;
    const float* rowScale;   // nullable
    __half* outH;
    int ldo;
    bool silu;
};

__device__ __forceinline__ void gemm128(const GemmArgs g) {
    extern __shared__ char smc[];
    int*   rows_s  = (int*)smc;
    float* scale_s = (float*)(smc + 512);
    float* stage   = (float*)(smc + 1024);
    const uint32_t sbase = smem_u32(smc);

    const int tid = threadIdx.x;
    const int lane = tid & 31, w = tid >> 5;
    const int mw = w & 3, nw = w >> 2;          // 4 M-warps x 2 N-warps
    const int gg = lane >> 2, cc = lane & 3;
    const int arow = (lane & 7) + ((lane >> 3) & 1) * 8;
    const int kh = (lane >> 4) & 1;

    if (tid < 128) {
        bool v = tid < g.valid;
        rows_s[tid]  = g.gather ? (v ? g.gather[tid] : -1) : (v ? tid : -1);
        scale_s[tid] = (g.rowScale && v) ? g.rowScale[tid] : 1.0f;
    }
    __syncthreads();

    // per-thread producer constants: 4 A-slots + 4 B-slots of 16B each
    const __half* asrc[4]; uint32_t aoff[4], asz[4];
    const __half* bsrc[4]; uint32_t boff[4];
#pragma unroll
    for (int i = 0; i < 4; i++) {
        int idx = tid + i * 256;
        int r = idx >> 3, c = idx & 7;                 // A: 128 rows x 8 x16B
        int gr = rows_s[r];
        asrc[i] = g.A + (gr >= 0 ? (size_t)gr * g.lda : 0) + c * 8;
        asz[i]  = (gr >= 0) ? 16u : 0u;
        aoff[i] = (uint32_t)(r * PA_B + c * 16);
        int k = idx >> 4, bc = idx & 15;               // B: 64 k-rows x 16 x16B
        bsrc[i] = g.W + (size_t)k * g.ldw + g.n0 + bc * 8;
        boff[i] = (uint32_t)(STG_A + k * PB_B + bc * 16);
    }

    float acc[2][8][4];
#pragma unroll
    for (int i = 0; i < 2; i++)
#pragma unroll
        for (int j = 0; j < 8; j++)
#pragma unroll
            for (int q = 0; q < 4; q++) acc[i][j][q] = 0.0f;

    const int nch = g.K >> 6;

    // issue chunk's loads into explicit stage slot st (0..NSTAGE-1)
    auto issue = [&](int chunk, int st) {
        uint32_t sb = sbase + 1024u + (uint32_t)st * STG_BYTES;
        int k0 = chunk << 6;
        size_t bstep = (size_t)k0 * g.ldw;
#pragma unroll
        for (int i = 0; i < 4; i++) cp16(sb + aoff[i], asrc[i] + k0, asz[i]);
#pragma unroll
        for (int i = 0; i < 4; i++) cp16(sb + boff[i], bsrc[i] + bstep, 16u);
    };

    // prologue: 2 stages in flight
    issue(0, 0); CP_COMMIT();
    if (nch > 1) issue(1, 1);
    CP_COMMIT();

    int stcur = 0;                 // stage of chunk c
    int stp = (nch > 2) ? 2 : 0;   // stage for chunk c+2
    for (int c = 0; c < nch; c++) {
        CP_WAIT(1);
        __syncthreads();
        const uint32_t sb = sbase + 1024u + (uint32_t)stcur * STG_BYTES;
        if (++stcur == NSTAGE) stcur = 0;
        const uint32_t Ab = sb, Bb = sb + STG_A;
#pragma unroll
        for (int ks = 0; ks < 4; ks++) {
            uint32_t a[2][4], bf[8][2];
#pragma unroll
            for (int ma = 0; ma < 2; ma++) {
                uint32_t addr = Ab + (uint32_t)((mw * 32 + ma * 16 + arow) * PA_B + ks * 32 + kh * 16);
                ldsm_x4(a[ma], addr);
            }
#pragma unroll
            for (int p = 0; p < 4; p++) {
                uint32_t r4[4];
                uint32_t addr = Bb + (uint32_t)((ks * 16 + arow) * PB_B + (nw * 64 + p * 16 + kh * 8) * 2);
                ldsm_x4_trans(r4, addr);
                bf[2 * p][0] = r4[0]; bf[2 * p][1] = r4[1];
                bf[2 * p + 1][0] = r4[2]; bf[2 * p + 1][1] = r4[3];
            }
#pragma unroll
            for (int ma = 0; ma < 2; ma++)
#pragma unroll
                for (int nb = 0; nb < 8; nb++)
                    mma_fp16(acc[ma][nb], a[ma], bf[nb][0], bf[nb][1]);
        }
        if (c + 2 < nch) {
            issue(c + 2, stp);
            if (++stp == NSTAGE) stp = 0;
        }
        CP_COMMIT();
    }
    CP_WAIT(0);
    __syncthreads();

    // epilogue: two 64-col slabs via smem stage, fp16 output
#pragma unroll
    for (int slab = 0; slab < 2; slab++) {
        if (nw == slab) {
#pragma unroll
            for (int ma = 0; ma < 2; ma++) {
                int r0 = mw * 32 + ma * 16 + gg, r1 = r0 + 8;
                float s0 = scale_s[r0], s1 = scale_s[r1];
#pragma unroll
                for (int nb = 0; nb < 8; nb++) {
                    int col = nb * 8 + cc * 2;
                    int n = g.n0 + slab * 64 + col;
                    float bv0 = g.bias[n], bv1 = g.bias[n + 1];
                    float f0 = acc[ma][nb][0] + bv0;
                    float f1 = acc[ma][nb][1] + bv1;
                    float f2 = acc[ma][nb][2] + bv0;
                    float f3 = acc[ma][nb][3] + bv1;
                    if (g.silu) { f0 = silu_f(f0); f1 = silu_f(f1); f2 = silu_f(f2); f3 = silu_f(f3); }
                    *(float2*)(stage + r0 * 68 + col) = make_float2(f0 * s0, f1 * s0);
                    *(float2*)(stage + r1 * 68 + col) = make_float2(f2 * s1, f3 * s1);
                }
            }
        }
        __syncthreads();
        for (int q = tid; q < 128 * 16; q += 256) {
            int r = q >> 4, c4 = q & 15;
            if (r < g.valid) {
                float4 v = *(float4*)(stage + r * 68 + c4 * 4);
                __half2 h0 = __floats2half2_rn(v.x, v.y);
                __half2 h1 = __floats2half2_rn(v.z, v.w);
                *(uint2*)(g.outH + (size_t)r * g.ldo + g.n0 + slab * 64 + c4 * 4) =
                    make_uint2(*(uint32_t*)&h0, *(uint32_t*)&h1);
            }
        }
        __syncthreads();
    }
}

// ---------------- merged phase kernels ----------------
// phase1: blocks [0,512) = shared g1 (es x 16 row x 16 n), [512,1024) = routed g1 (256 tiles x 2 n)
__global__ void __launch_bounds__(256, 2) phase1_kernel(const float* b1, const float* sb1) {
    int bx = blockIdx.x;
    GemmArgs a;
    if (bx < 512) {
        int es = bx >> 8, idx = bx & 255;
        int row0 = (idx & 15) * 128, n0 = (idx >> 4) * 128;
        a.A = g_x16 + (size_t)row0 * Dm; a.lda = Dm; a.gather = nullptr; a.valid = 128;
        a.W = g_sw116 + (size_t)es * Dm * HSn; a.ldw = HSn; a.n0 = n0;
        a.K = Dm; a.bias = sb1 + (size_t)es * HSn; a.rowScale = nullptr;
        a.outH = g_Hs16 + (size_t)es * Tn * HSn + (size_t)row0 * HSn; a.ldo = HSn; a.silu = true;
        gemm128(a);
    } else {
        int q = bx - 512;                 // [0,512)
        int t = q & 255, ny = q >> 8;     // ny in {0,1}
        if (t >= g_ntiles) return;
        int e = g_tile_e[t], rb = g_tile_row[t];
        int cnt = g_count[e], off = g_offset[e];
        a.A = g_x16; a.lda = Dm; a.gather = g_pair_token + off + rb; a.valid = min(128, cnt - rb);
        a.W = g_w116 + (size_t)e * Dm * Hh; a.ldw = Hh; a.n0 = ny * 128;
        a.K = Dm; a.bias = b1 + e * Hh; a.rowScale = nullptr;
        a.outH = g_H16 + (size_t)(off + rb) * Hh; a.ldo = Hh; a.silu = true;
        gemm128(a);
    }
}
// phase2: blocks [0,256) = shared g2 (K=2048, longest first), [256,2304) = routed g2 (256 tiles x 8 n)
__global__ void __launch_bounds__(256, 2) phase2_kernel(const float* b2, const float* sb2) {
    int bx = blockIdx.x;
    GemmArgs a;
    if (bx < 256) {
        int es = bx >> 7, idx = bx & 127;
        int row0 = (idx & 15) * 128, n0 = (idx >> 4) * 128;
        a.A = g_Hs16 + (size_t)es * Tn * HSn + (size_t)row0 * HSn; a.lda = HSn; a.gather = nullptr; a.valid = 128;
        a.W = g_sw216 + (size_t)es * HSn * Dm; a.ldw = Dm; a.n0 = n0;
        a.K = HSn; a.bias = sb2 + (size_t)es * Dm; a.rowScale = nullptr;
        a.outH = g_sharedout16 + (size_t)es * Tn * Dm + (size_t)row0 * Dm; a.ldo = Dm; a.silu = false;
        gemm128(a);
    } else {
        int q = bx - 256;                 // [0,2048)
        int t = q & 255, ny = q >> 8;     // ny in {0..7}
        if (t >= g_ntiles) return;
        int e = g_tile_e[t], rb = g_tile_row[t];
        int cnt = g_count[e], off = g_offset[e];
        a.A = g_H16 + (size_t)(off + rb) * Hh; a.lda = Hh; a.gather = nullptr; a.valid = min(128, cnt - rb);
        a.W = g_w216 + (size_t)e * Hh * Dm; a.ldw = Dm; a.n0 = ny * 128;
        a.K = Hh; a.bias = b2 + (size_t)e * Dm; a.rowScale = g_pair_w + off + rb;
        a.outH = g_pairout16 + (size_t)(off + rb) * Dm; a.ldo = Dm; a.silu = false;
        gemm128(a);
    }
}

// ---------------- fp32 -> fp16 conversion ----------------
__global__ void __launch_bounds__(256) conv_kernel(const float* __restrict__ src, __half* __restrict__ dst, int n4) {
    for (int i = blockIdx.x * 256 + threadIdx.x; i < n4; i += gridDim.x * 256) {
        float4 v = *(const float4*)(src + (size_t)i * 4);
        __half2 h0 = __floats2half2_rn(v.x, v.y);
        __half2 h1 = __floats2half2_rn(v.z, v.w);
        uint32_t u0 = *(uint32_t*)&h0;
        uint32_t u1 = *(uint32_t*)&h1;
        *(uint2*)(dst + (size_t)i * 4) = make_uint2(u0, u1);
    }
}

// ---------------- routing bookkeeping ----------------
__global__ void zero_counts_kernel() {
    if (threadIdx.x < Ne) g_count[threadIdx.x] = 0;
}

__global__ void __launch_bounds__(256) router_kernel(
    const float* __restrict__ x, const float* __restrict__ rw, const float* __restrict__ rb)
{
    __shared__ float xs[64][33];
    __shared__ float ws[64][65];
    __shared__ float lg[32][65];
    int tid = threadIdx.x;
    int tbase = blockIdx.x * 32;
    int e = tid & 63, tg = tid >> 6;
    float acc[8];
#pragma unroll
    for (int i = 0; i < 8; i++) acc[i] = 0.0f;
    for (int d0 = 0; d0 < Dm; d0 += 64) {
#pragma unroll
        for (int q = 0; q < 8; q++) {
            int idx = tid + q * 256; int t = idx >> 6, dd = idx & 63;
            xs[dd][t] = x[(size_t)(tbase + t) * Dm + d0 + dd];
        }
#pragma unroll
        for (int q = 0; q < 16; q++) {
            int idx = tid + q * 256; int dd = idx >> 6, ee = idx & 63;
            ws[dd][ee] = rw[(size_t)(d0 + dd) * Ne + ee];
        }
        __syncthreads();
#pragma unroll
        for (int dd = 0; dd < 64; dd++) {
            float wv = ws[dd][e];
#pragma unroll
            for (int i = 0; i < 8; i++) acc[i] += xs[dd][tg + 4 * i] * wv;
        }
        __syncthreads();
    }
#pragma unroll
    for (int i = 0; i < 8; i++) lg[tg + 4 * i][e] = acc[i] + rb[e];
    __syncthreads();
    if (tid < 32) {
        int t = tid;
        float vals[TOPK]; int idxs[TOPK];
#pragma unroll
        for (int p = 0; p < TOPK; p++) {
            float best = -1e30f; int bi = 0;
            for (int ee = 0; ee < Ne; ee++) {
                float v = lg[t][ee];
                if (v > best) { best = v; bi = ee; }
            }
            vals[p] = best; idxs[p] = bi; lg[t][bi] = -1e30f;
        }
        float m = vals[0], wv[TOPK], s = 0.0f;
#pragma unroll
        for (int p = 0; p < TOPK; p++) { wv[p] = __expf(vals[p] - m); s += wv[p]; }
        float inv = 1.0f / s;
        int gt = tbase + t;
#pragma unroll
        for (int p = 0; p < TOPK; p++) {
            g_topw[gt * TOPK + p] = wv[p] * inv;
            g_topi[gt * TOPK + p] = idxs[p];
            atomicAdd(&g_count[idxs[p]], 1);
        }
    }
}

__global__ void scan_kernel() {
    if (threadIdx.x == 0) {
        int run = 0, nt = 0;
        for (int e = 0; e < Ne; e++) {
            g_offset[e] = run; g_cursor[e] = run;
            int c = g_count[e];
            int tiles = (c + 127) >> 7;
            for (int i = 0; i < tiles; i++) { g_tile_e[nt] = e; g_tile_row[nt] = i * 128; nt++; }
            run += c;
        }
        g_ntiles = nt;
    }
}

__global__ void fill_kernel() {
    int t = blockIdx.x * 256 + threadIdx.x;
    if (t < Tn) {
#pragma unroll
        for (int j = 0; j < TOPK; j++) {
            int e = g_topi[t * TOPK + j];
            int pos = atomicAdd(&g_cursor[e], 1);
            g_pair_token[pos] = t;
            g_pair_w[pos] = g_topw[t * TOPK + j];
            g_slot2pair[t * TOPK + j] = pos;
        }
    }
}

// ---------------- combine (fp16 inputs, fp32 accumulate) ----------------
__global__ void __launch_bounds__(256) combine_kernel(float* __restrict__ out) {
    int t = blockIdx.x, tid = threadIdx.x;
    __shared__ int sp[TOPK];
    if (tid < TOPK) sp[tid] = g_slot2pair[t * TOPK + tid];
    __syncthreads();
    float acc0, acc1, acc2, acc3;
    {
        uint2 u = *(const uint2*)(g_sharedout16 + (size_t)t * Dm + tid * 4);
        __half2 h0 = *(__half2*)&u.x, h1 = *(__half2*)&u.y;
        float2 f0 = __half22float2(h0), f1 = __half22float2(h1);
        acc0 = f0.x; acc1 = f0.y; acc2 = f1.x; acc3 = f1.y;
    }
    {
        uint2 u = *(const uint2*)(g_sharedout16 + (size_t)Tn * Dm + (size_t)t * Dm + tid * 4);
        __half2 h0 = *(__half2*)&u.x, h1 = *(__half2*)&u.y;
        float2 f0 = __half22float2(h0), f1 = __half22float2(h1);
        acc0 += f0.x; acc1 += f0.y; acc2 += f1.x; acc3 += f1.y;
    }
#pragma unroll
    for (int j = 0; j < TOPK; j++) {
        uint2 u = *(const uint2*)(g_pairout16 + (size_t)sp[j] * Dm + tid * 4);
        __half2 h0 = *(__half2*)&u.x, h1 = *(__half2*)&u.y;
        float2 f0 = __half22float2(h0), f1 = __half22float2(h1);
        acc0 += f0.x; acc1 += f0.y; acc2 += f1.x; acc3 += f1.y;
    }
    *(float4*)(out + (size_t)t * Dm + tid * 4) = make_float4(acc0, acc1, acc2, acc3);
}

// ---------------- launch ----------------
extern "C" void kernel_launch(void* const* d_in, const int* in_sizes, int n_in,
                              void* d_out, int out_size)
{
    const float* x   = (const float*)d_in[0];
    const float* rw  = (const float*)d_in[1];
    const float* rb  = (const float*)d_in[2];
    const float* w1  = (const float*)d_in[3];
    const float* b1  = (const float*)d_in[4];
    const float* w2  = (const float*)d_in[5];
    const float* b2  = (const float*)d_in[6];
    const float* sw1 = (const float*)d_in[7];
    const float* sb1 = (const float*)d_in[8];
    const float* sw2 = (const float*)d_in[9];
    const float* sb2 = (const float*)d_in[10];
    float* out = (float*)d_out;

    cudaFuncSetAttribute(phase1_kernel, cudaFuncAttributeMaxDynamicSharedMemorySize, SMEM_DYN);
    cudaFuncSetAttribute(phase2_kernel, cudaFuncAttributeMaxDynamicSharedMemorySize, SMEM_DYN);

    __half* x16  = nullptr; cudaGetSymbolAddress((void**)&x16,  g_x16);
    __half* w116 = nullptr; cudaGetSymbolAddress((void**)&w116, g_w116);
    __half* w216 = nullptr; cudaGetSymbolAddress((void**)&w216, g_w216);
    __half* s116 = nullptr; cudaGetSymbolAddress((void**)&s116, g_sw116);
    __half* s216 = nullptr; cudaGetSymbolAddress((void**)&s216, g_sw216);

    zero_counts_kernel<<<1, 64>>>();
    router_kernel<<<Tn / 32, 256>>>(x, rw, rb);
    scan_kernel<<<1, 32>>>();
    fill_kernel<<<(Tn + 255) / 256, 256>>>();
    conv_kernel<<<1024, 256>>>(x,   x16,  Tn * Dm / 4);
    conv_kernel<<<2048, 256>>>(w1,  w116, Ne * Dm * Hh / 4);
    conv_kernel<<<2048, 256>>>(w2,  w216, Ne * Hh * Dm / 4);
    conv_kernel<<<2048, 256>>>(sw1, s116, ESn * Dm * HSn / 4);
    conv_kernel<<<2048, 256>>>(sw2, s216, ESn * HSn * Dm / 4);
    phase1_kernel<<<1024, 256, SMEM_DYN>>>(b1, sb1);
    phase2_kernel<<<2304, 256, SMEM_DYN>>>(b2, sb2);
    combine_kernel<<<Tn, 256>>>(out);
}

// round 13
// speedup vs baseline: 4.2455x; 1.1038x over previous
#include <cuda_runtime.h>
#include <cuda_fp16.h>
#include <cstdint>
#include <math.h>

#define Tn   2048
#define Dm   1024
#define Ne   64
#define TOPK 8
#define Hh   256
#define ESn  2
#define HSn  2048
#define MAXP (Tn * TOPK)
#define MAXTILES 256

// ---------------- static scratch ----------------
__device__ float g_topw[MAXP];
__device__ int   g_topi[MAXP];
__device__ int   g_slot2pair[MAXP];
__device__ int   g_count[Ne];
__device__ int   g_offset[Ne];
__device__ int   g_cursor[Ne];
__device__ int   g_pair_token[MAXP];
__device__ float g_pair_w[MAXP];
__device__ int   g_ntiles;
__device__ int   g_tile_e[MAXTILES];
__device__ int   g_tile_row[MAXTILES];
__device__ __half g_pairout16[(size_t)MAXP * Dm];
__device__ __half g_sharedout16[(size_t)ESn * Tn * Dm];
__device__ __half g_H16[(size_t)MAXP * Hh];
__device__ __half g_Hs16[(size_t)ESn * Tn * HSn];
// fp16 operand copies
__device__ __half g_x16[(size_t)Tn * Dm];
__device__ __half g_w116[(size_t)Ne * Dm * Hh];
__device__ __half g_w216[(size_t)Ne * Hh * Dm];
__device__ __half g_sw116[(size_t)ESn * Dm * HSn];
__device__ __half g_sw216[(size_t)ESn * HSn * Dm];

__device__ __forceinline__ uint32_t smem_u32(const void* p) {
    uint32_t a;
    asm("{ .reg .u64 t; cvta.to.shared.u64 t, %1; cvt.u32.u64 %0, t; }" : "=r"(a) : "l"(p));
    return a;
}
__device__ __forceinline__ float silu_f(float c) { return c / (1.0f + __expf(-c)); }

__device__ __forceinline__ void ldsm_x4(uint32_t* r, uint32_t addr) {
    asm volatile("ldmatrix.sync.aligned.m8n8.x4.shared.b16 {%0,%1,%2,%3}, [%4];"
        : "=r"(r[0]), "=r"(r[1]), "=r"(r[2]), "=r"(r[3]) : "r"(addr));
}
__device__ __forceinline__ void ldsm_x4_trans(uint32_t* r, uint32_t addr) {
    asm volatile("ldmatrix.sync.aligned.m8n8.x4.trans.shared.b16 {%0,%1,%2,%3}, [%4];"
        : "=r"(r[0]), "=r"(r[1]), "=r"(r[2]), "=r"(r[3]) : "r"(addr));
}
__device__ __forceinline__ void mma_fp16(float* d, const uint32_t* a, uint32_t b0, uint32_t b1) {
    asm volatile(
        "mma.sync.aligned.m16n8k16.row.col.f32.f16.f16.f32 "
        "{%0,%1,%2,%3}, {%4,%5,%6,%7}, {%8,%9}, {%0,%1,%2,%3};"
        : "+f"(d[0]), "+f"(d[1]), "+f"(d[2]), "+f"(d[3])
        : "r"(a[0]), "r"(a[1]), "r"(a[2]), "r"(a[3]), "r"(b0), "r"(b1));
}
__device__ __forceinline__ void cp16(uint32_t dst, const void* src, uint32_t sz) {
    asm volatile("cp.async.cg.shared.global [%0], [%1], 16, %2;"
        :: "r"(dst), "l"(src), "r"(sz) : "memory");
}
#define CP_COMMIT() asm volatile("cp.async.commit_group;" ::: "memory")
#define CP_WAIT(n)  asm volatile("cp.async.wait_group %0;" :: "n"(n) : "memory")

// pipeline geometry: K-chunk = 64
#define NSTAGE 3
#define PA_B 144
#define PB_B 272
#define STG_A 18432
#define STG_B 17408
#define STG_BYTES (STG_A + STG_B)
#define SMEM_DYN (1024 + NSTAGE * STG_BYTES)   // 108544

struct GemmArgs {
    const __half* A; int lda; const int* gather; int valid;
    const __half* W; int ldw; int n0;
    int K;
    const float* bias;
    const float* rowScale;   // nullable
    __half* outH;
    int ldo;
    bool silu;
};

__device__ __forceinline__ void gemm128(const GemmArgs g) {
    extern __shared__ char smc[];
    int*   rows_s  = (int*)smc;
    float* scale_s = (float*)(smc + 512);
    const uint32_t sbase = smem_u32(smc);

    const int tid = threadIdx.x;
    const int lane = tid & 31, w = tid >> 5;
    const int mw = w & 3, nw = w >> 2;
    const int gg = lane >> 2, cc = lane & 3;
    const int arow = (lane & 7) + ((lane >> 3) & 1) * 8;
    const int kh = (lane >> 4) & 1;

    if (tid < 128) {
        bool v = tid < g.valid;
        rows_s[tid]  = g.gather ? (v ? g.gather[tid] : -1) : (v ? tid : -1);
        scale_s[tid] = (g.rowScale && v) ? g.rowScale[tid] : 1.0f;
    }
    __syncthreads();

    const __half* asrc[4]; uint32_t aoff[4], asz[4];
    const __half* bsrc[4]; uint32_t boff[4];
#pragma unroll
    for (int i = 0; i < 4; i++) {
        int idx = tid + i * 256;
        int r = idx >> 3, c = idx & 7;
        int gr = rows_s[r];
        asrc[i] = g.A + (gr >= 0 ? (size_t)gr * g.lda : 0) + c * 8;
        asz[i]  = (gr >= 0) ? 16u : 0u;
        aoff[i] = (uint32_t)(r * PA_B + c * 16);
        int k = idx >> 4, bc = idx & 15;
        bsrc[i] = g.W + (size_t)k * g.ldw + g.n0 + bc * 8;
        boff[i] = (uint32_t)(STG_A + k * PB_B + bc * 16);
    }

    float acc[2][8][4];
#pragma unroll
    for (int i = 0; i < 2; i++)
#pragma unroll
        for (int j = 0; j < 8; j++)
#pragma unroll
            for (int q = 0; q < 4; q++) acc[i][j][q] = 0.0f;

    const int nch = g.K >> 6;

    auto issue = [&](int chunk, int st) {
        uint32_t sb = sbase + 1024u + (uint32_t)st * STG_BYTES;
        int k0 = chunk << 6;
        size_t bstep = (size_t)k0 * g.ldw;
#pragma unroll
        for (int i = 0; i < 4; i++) cp16(sb + aoff[i], asrc[i] + k0, asz[i]);
#pragma unroll
        for (int i = 0; i < 4; i++) cp16(sb + boff[i], bsrc[i] + bstep, 16u);
    };

    issue(0, 0); CP_COMMIT();
    if (nch > 1) issue(1, 1);
    CP_COMMIT();

    int stcur = 0;
    int stp = (nch > 2) ? 2 : 0;
    for (int c = 0; c < nch; c++) {
        CP_WAIT(1);
        __syncthreads();
        const uint32_t sb = sbase + 1024u + (uint32_t)stcur * STG_BYTES;
        if (++stcur == NSTAGE) stcur = 0;
        // prefetch chunk c+2 first so its LDGs overlap this chunk's MMAs
        if (c + 2 < nch) {
            issue(c + 2, stp);
            if (++stp == NSTAGE) stp = 0;
        }
        CP_COMMIT();
        const uint32_t Ab = sb, Bb = sb + STG_A;
#pragma unroll
        for (int ks = 0; ks < 4; ks++) {
            uint32_t a[2][4], bf[8][2];
#pragma unroll
            for (int ma = 0; ma < 2; ma++) {
                uint32_t addr = Ab + (uint32_t)((mw * 32 + ma * 16 + arow) * PA_B + ks * 32 + kh * 16);
                ldsm_x4(a[ma], addr);
            }
#pragma unroll
            for (int p = 0; p < 4; p++) {
                uint32_t r4[4];
                uint32_t addr = Bb + (uint32_t)((ks * 16 + arow) * PB_B + (nw * 64 + p * 16 + kh * 8) * 2);
                ldsm_x4_trans(r4, addr);
                bf[2 * p][0] = r4[0]; bf[2 * p][1] = r4[1];
                bf[2 * p + 1][0] = r4[2]; bf[2 * p + 1][1] = r4[3];
            }
#pragma unroll
            for (int ma = 0; ma < 2; ma++)
#pragma unroll
                for (int nb = 0; nb < 8; nb++)
                    mma_fp16(acc[ma][nb], a[ma], bf[nb][0], bf[nb][1]);
        }
    }
    CP_WAIT(0);

    // direct register epilogue: bias + silu + rowScale + fp16 STG (no smem stage)
#pragma unroll
    for (int ma = 0; ma < 2; ma++) {
        int r0 = mw * 32 + ma * 16 + gg, r1 = r0 + 8;
        float s0 = scale_s[r0], s1 = scale_s[r1];
        bool v0 = r0 < g.valid, v1 = r1 < g.valid;
#pragma unroll
        for (int nb = 0; nb < 8; nb++) {
            int n = g.n0 + nw * 64 + nb * 8 + cc * 2;
            float bv0 = g.bias[n], bv1 = g.bias[n + 1];
            float f0 = acc[ma][nb][0] + bv0;
            float f1 = acc[ma][nb][1] + bv1;
            float f2 = acc[ma][nb][2] + bv0;
            float f3 = acc[ma][nb][3] + bv1;
            if (g.silu) { f0 = silu_f(f0); f1 = silu_f(f1); f2 = silu_f(f2); f3 = silu_f(f3); }
            if (v0) {
                __half2 h = __floats2half2_rn(f0 * s0, f1 * s0);
                *(__half2*)(g.outH + (size_t)r0 * g.ldo + n) = h;
            }
            if (v1) {
                __half2 h = __floats2half2_rn(f2 * s1, f3 * s1);
                *(__half2*)(g.outH + (size_t)r1 * g.ldo + n) = h;
            }
        }
    }
}

// ---------------- merged phase kernels ----------------
__global__ void __launch_bounds__(256, 2) phase1_kernel(const float* b1, const float* sb1) {
    int bx = blockIdx.x;
    GemmArgs a;
    if (bx < 512) {
        int es = bx >> 8, idx = bx & 255;
        int row0 = (idx & 15) * 128, n0 = (idx >> 4) * 128;
        a.A = g_x16 + (size_t)row0 * Dm; a.lda = Dm; a.gather = nullptr; a.valid = 128;
        a.W = g_sw116 + (size_t)es * Dm * HSn; a.ldw = HSn; a.n0 = n0;
        a.K = Dm; a.bias = sb1 + (size_t)es * HSn; a.rowScale = nullptr;
        a.outH = g_Hs16 + (size_t)es * Tn * HSn + (size_t)row0 * HSn; a.ldo = HSn; a.silu = true;
        gemm128(a);
    } else {
        int q = bx - 512;
        int t = q & 255, ny = q >> 8;     // ny in {0,1}
        if (t >= g_ntiles) return;
        int e = g_tile_e[t], rb = g_tile_row[t];
        int cnt = g_count[e], off = g_offset[e];
        a.A = g_x16; a.lda = Dm; a.gather = g_pair_token + off + rb; a.valid = min(128, cnt - rb);
        a.W = g_w116 + (size_t)e * Dm * Hh; a.ldw = Hh; a.n0 = ny * 128;
        a.K = Dm; a.bias = b1 + e * Hh; a.rowScale = nullptr;
        a.outH = g_H16 + (size_t)(off + rb) * Hh; a.ldo = Hh; a.silu = true;
        gemm128(a);
    }
}
__global__ void __launch_bounds__(256, 2) phase2_kernel(const float* b2, const float* sb2) {
    int bx = blockIdx.x;
    GemmArgs a;
    if (bx < 256) {
        int es = bx >> 7, idx = bx & 127;
        int row0 = (idx & 15) * 128, n0 = (idx >> 4) * 128;
        a.A = g_Hs16 + (size_t)es * Tn * HSn + (size_t)row0 * HSn; a.lda = HSn; a.gather = nullptr; a.valid = 128;
        a.W = g_sw216 + (size_t)es * HSn * Dm; a.ldw = Dm; a.n0 = n0;
        a.K = HSn; a.bias = sb2 + (size_t)es * Dm; a.rowScale = nullptr;
        a.outH = g_sharedout16 + (size_t)es * Tn * Dm + (size_t)row0 * Dm; a.ldo = Dm; a.silu = false;
        gemm128(a);
    } else {
        int q = bx - 256;
        int t = q & 255, ny = q >> 8;     // ny in {0..7}
        if (t >= g_ntiles) return;
        int e = g_tile_e[t], rb = g_tile_row[t];
        int cnt = g_count[e], off = g_offset[e];
        a.A = g_H16 + (size_t)(off + rb) * Hh; a.lda = Hh; a.gather = nullptr; a.valid = min(128, cnt - rb);
        a.W = g_w216 + (size_t)e * Hh * Dm; a.ldw = Dm; a.n0 = ny * 128;
        a.K = Hh; a.bias = b2 + (size_t)e * Dm; a.rowScale = g_pair_w + off + rb;
        a.outH = g_pairout16 + (size_t)(off + rb) * Dm; a.ldo = Dm; a.silu = false;
        gemm128(a);
    }
}

// ---------------- fp32 -> fp16 conversion ----------------
__global__ void __launch_bounds__(256) conv_kernel(const float* __restrict__ src, __half* __restrict__ dst, int n4) {
    for (int i = blockIdx.x * 256 + threadIdx.x; i < n4; i += gridDim.x * 256) {
        float4 v = *(const float4*)(src + (size_t)i * 4);
        __half2 h0 = __floats2half2_rn(v.x, v.y);
        __half2 h1 = __floats2half2_rn(v.z, v.w);
        uint32_t u0 = *(uint32_t*)&h0;
        uint32_t u1 = *(uint32_t*)&h1;
        *(uint2*)(dst + (size_t)i * 4) = make_uint2(u0, u1);
    }
}

// ---------------- routing bookkeeping ----------------
__global__ void zero_counts_kernel() {
    if (threadIdx.x < Ne) g_count[threadIdx.x] = 0;
}

__global__ void __launch_bounds__(256) router_kernel(
    const float* __restrict__ x, const float* __restrict__ rw, const float* __restrict__ rb)
{
    __shared__ float xs[64][33];
    __shared__ float ws[64][65];
    __shared__ float lg[32][65];
    int tid = threadIdx.x;
    int tbase = blockIdx.x * 32;
    int e = tid & 63, tg = tid >> 6;
    float acc[8];
#pragma unroll
    for (int i = 0; i < 8; i++) acc[i] = 0.0f;
    for (int d0 = 0; d0 < Dm; d0 += 64) {
#pragma unroll
        for (int q = 0; q < 8; q++) {
            int idx = tid + q * 256; int t = idx >> 6, dd = idx & 63;
            xs[dd][t] = x[(size_t)(tbase + t) * Dm + d0 + dd];
        }
#pragma unroll
        for (int q = 0; q < 16; q++) {
            int idx = tid + q * 256; int dd = idx >> 6, ee = idx & 63;
            ws[dd][ee] = rw[(size_t)(d0 + dd) * Ne + ee];
        }
        __syncthreads();
#pragma unroll
        for (int dd = 0; dd < 64; dd++) {
            float wv = ws[dd][e];
#pragma unroll
            for (int i = 0; i < 8; i++) acc[i] += xs[dd][tg + 4 * i] * wv;
        }
        __syncthreads();
    }
#pragma unroll
    for (int i = 0; i < 8; i++) lg[tg + 4 * i][e] = acc[i] + rb[e];
    __syncthreads();
    if (tid < 32) {
        int t = tid;
        float vals[TOPK]; int idxs[TOPK];
#pragma unroll
        for (int p = 0; p < TOPK; p++) {
            float best = -1e30f; int bi = 0;
            for (int ee = 0; ee < Ne; ee++) {
                float v = lg[t][ee];
                if (v > best) { best = v; bi = ee; }
            }
            vals[p] = best; idxs[p] = bi; lg[t][bi] = -1e30f;
        }
        float m = vals[0], wv[TOPK], s = 0.0f;
#pragma unroll
        for (int p = 0; p < TOPK; p++) { wv[p] = __expf(vals[p] - m); s += wv[p]; }
        float inv = 1.0f / s;
        int gt = tbase + t;
#pragma unroll
        for (int p = 0; p < TOPK; p++) {
            g_topw[gt * TOPK + p] = wv[p] * inv;
            g_topi[gt * TOPK + p] = idxs[p];
            atomicAdd(&g_count[idxs[p]], 1);
        }
    }
}

__global__ void scan_kernel() {
    if (threadIdx.x == 0) {
        int run = 0, nt = 0;
        for (int e = 0; e < Ne; e++) {
            g_offset[e] = run; g_cursor[e] = run;
            int c = g_count[e];
            int tiles = (c + 127) >> 7;
            for (int i = 0; i < tiles; i++) { g_tile_e[nt] = e; g_tile_row[nt] = i * 128; nt++; }
            run += c;
        }
        g_ntiles = nt;
    }
}

// one thread per (token, slot) pair
__global__ void fill_kernel() {
    int idx = blockIdx.x * 256 + threadIdx.x;
    if (idx < MAXP) {
        int e = g_topi[idx];
        int pos = atomicAdd(&g_cursor[e], 1);
        g_pair_token[pos] = idx >> 3;        // token
        g_pair_w[pos] = g_topw[idx];
        g_slot2pair[idx] = pos;
    }
}

// ---------------- combine (fp16 inputs, fp32 accumulate) ----------------
__global__ void __launch_bounds__(256) combine_kernel(float* __restrict__ out) {
    int t = blockIdx.x, tid = threadIdx.x;
    __shared__ int sp[TOPK];
    if (tid < TOPK) sp[tid] = g_slot2pair[t * TOPK + tid];
    __syncthreads();
    float acc0, acc1, acc2, acc3;
    {
        uint2 u = *(const uint2*)(g_sharedout16 + (size_t)t * Dm + tid * 4);
        __half2 h0 = *(__half2*)&u.x, h1 = *(__half2*)&u.y;
        float2 f0 = __half22float2(h0), f1 = __half22float2(h1);
        acc0 = f0.x; acc1 = f0.y; acc2 = f1.x; acc3 = f1.y;
    }
    {
        uint2 u = *(const uint2*)(g_sharedout16 + (size_t)Tn * Dm + (size_t)t * Dm + tid * 4);
        __half2 h0 = *(__half2*)&u.x, h1 = *(__half2*)&u.y;
        float2 f0 = __half22float2(h0), f1 = __half22float2(h1);
        acc0 += f0.x; acc1 += f0.y; acc2 += f1.x; acc3 += f1.y;
    }
#pragma unroll
    for (int j = 0; j < TOPK; j++) {
        uint2 u = *(const uint2*)(g_pairout16 + (size_t)sp[j] * Dm + tid * 4);
        __half2 h0 = *(__half2*)&u.x, h1 = *(__half2*)&u.y;
        float2 f0 = __half22float2(h0), f1 = __half22float2(h1);
        acc0 += f0.x; acc1 += f0.y; acc2 += f1.x; acc3 += f1.y;
    }
    *(float4*)(out + (size_t)t * Dm + tid * 4) = make_float4(acc0, acc1, acc2, acc3);
}

// ---------------- launch ----------------
extern "C" void kernel_launch(void* const* d_in, const int* in_sizes, int n_in,
                              void* d_out, int out_size)
{
    const float* x   = (const float*)d_in[0];
    const float* rw  = (const float*)d_in[1];
    const float* rb  = (const float*)d_in[2];
    const float* w1  = (const float*)d_in[3];
    const float* b1  = (const float*)d_in[4];
    const float* w2  = (const float*)d_in[5];
    const float* b2  = (const float*)d_in[6];
    const float* sw1 = (const float*)d_in[7];
    const float* sb1 = (const float*)d_in[8];
    const float* sw2 = (const float*)d_in[9];
    const float* sb2 = (const float*)d_in[10];
    float* out = (float*)d_out;

    cudaFuncSetAttribute(phase1_kernel, cudaFuncAttributeMaxDynamicSharedMemorySize, SMEM_DYN);
    cudaFuncSetAttribute(phase2_kernel, cudaFuncAttributeMaxDynamicSharedMemorySize, SMEM_DYN);

    __half* x16  = nullptr; cudaGetSymbolAddress((void**)&x16,  g_x16);
    __half* w116 = nullptr; cudaGetSymbolAddress((void**)&w116, g_w116);
    __half* w216 = nullptr; cudaGetSymbolAddress((void**)&w216, g_w216);
    __half* s116 = nullptr; cudaGetSymbolAddress((void**)&s116, g_sw116);
    __half* s216 = nullptr; cudaGetSymbolAddress((void**)&s216, g_sw216);

    // static side streams + events (created on first, uncaptured, call)
    static cudaStream_t sA = nullptr, sB = nullptr;
    static cudaEvent_t evRoot = nullptr, evA = nullptr, evB = nullptr;
    if (!sA) {
        cudaStreamCreateWithFlags(&sA, cudaStreamNonBlocking);
        cudaStreamCreateWithFlags(&sB, cudaStreamNonBlocking);
        cudaEventCreateWithFlags(&evRoot, cudaEventDisableTiming);
        cudaEventCreateWithFlags(&evA, cudaEventDisableTiming);
        cudaEventCreateWithFlags(&evB, cudaEventDisableTiming);
    }

    // fork side streams off the main (capturing) stream
    cudaEventRecord(evRoot, 0);
    cudaStreamWaitEvent(sA, evRoot, 0);
    cudaStreamWaitEvent(sB, evRoot, 0);

    // main stream: routing chain (reads fp32 x)
    zero_counts_kernel<<<1, 64>>>();
    router_kernel<<<Tn / 32, 256>>>(x, rw, rb);
    scan_kernel<<<1, 32>>>();
    fill_kernel<<<MAXP / 256, 256>>>();

    // stream A: operands needed by phase1
    conv_kernel<<<1024, 256, 0, sA>>>(x,   x16,  Tn * Dm / 4);
    conv_kernel<<<2048, 256, 0, sA>>>(w1,  w116, Ne * Dm * Hh / 4);
    conv_kernel<<<2048, 256, 0, sA>>>(sw1, s116, ESn * Dm * HSn / 4);
    cudaEventRecord(evA, sA);

    // stream B: operands needed by phase2 (overlaps phase1)
    conv_kernel<<<2048, 256, 0, sB>>>(w2,  w216, Ne * Hh * Dm / 4);
    conv_kernel<<<2048, 256, 0, sB>>>(sw2, s216, ESn * HSn * Dm / 4);
    cudaEventRecord(evB, sB);

    // phase1 depends on routing chain (main) + stream A
    cudaStreamWaitEvent(0, evA, 0);
    phase1_kernel<<<1024, 256, SMEM_DYN>>>(b1, sb1);

    // phase2 depends on phase1 (main) + stream B
    cudaStreamWaitEvent(0, evB, 0);
    phase2_kernel<<<2304, 256, SMEM_DYN>>>(b2, sb2);

    combine_kernel<<<Tn, 256>>>(out);
}

// round 14
// speedup vs baseline: 4.7632x; 1.1219x over previous
#include <cuda_runtime.h>
#include <cuda_fp16.h>
#include <cstdint>
#include <math.h>

#define Tn   2048
#define Dm   1024
#define Ne   64
#define TOPK 8
#define Hh   256
#define ESn  2
#define HSn  2048
#define MAXP (Tn * TOPK)
#define MAXTILES 256

// ---------------- static scratch ----------------
__device__ float g_topw[MAXP];
__device__ int   g_topi[MAXP];
__device__ int   g_slot2pair[MAXP];
__device__ int   g_count[Ne];
__device__ int   g_offset[Ne];
__device__ int   g_cursor[Ne];
__device__ int   g_pair_token[MAXP];
__device__ float g_pair_w[MAXP];
__device__ int   g_ntiles;
__device__ int   g_tile_e[MAXTILES];
__device__ int   g_tile_row[MAXTILES];
__device__ __half g_pairout16[(size_t)MAXP * Dm];
__device__ __half g_sharedout16[(size_t)ESn * Tn * Dm];
__device__ __half g_H16[(size_t)MAXP * Hh];
__device__ __half g_Hs16[(size_t)ESn * Tn * HSn];
// fp16 operand copies
__device__ __half g_x16[(size_t)Tn * Dm];
__device__ __half g_w116[(size_t)Ne * Dm * Hh];
__device__ __half g_w216[(size_t)Ne * Hh * Dm];
__device__ __half g_sw116[(size_t)ESn * Dm * HSn];
__device__ __half g_sw216[(size_t)ESn * HSn * Dm];

__device__ __forceinline__ uint32_t smem_u32(const void* p) {
    uint32_t a;
    asm("{ .reg .u64 t; cvta.to.shared.u64 t, %1; cvt.u32.u64 %0, t; }" : "=r"(a) : "l"(p));
    return a;
}
__device__ __forceinline__ float silu_f(float c) { return c / (1.0f + __expf(-c)); }

__device__ __forceinline__ void ldsm_x4(uint32_t* r, uint32_t addr) {
    asm volatile("ldmatrix.sync.aligned.m8n8.x4.shared.b16 {%0,%1,%2,%3}, [%4];"
        : "=r"(r[0]), "=r"(r[1]), "=r"(r[2]), "=r"(r[3]) : "r"(addr));
}
__device__ __forceinline__ void ldsm_x4_trans(uint32_t* r, uint32_t addr) {
    asm volatile("ldmatrix.sync.aligned.m8n8.x4.trans.shared.b16 {%0,%1,%2,%3}, [%4];"
        : "=r"(r[0]), "=r"(r[1]), "=r"(r[2]), "=r"(r[3]) : "r"(addr));
}
__device__ __forceinline__ void mma_fp16(float* d, const uint32_t* a, uint32_t b0, uint32_t b1) {
    asm volatile(
        "mma.sync.aligned.m16n8k16.row.col.f32.f16.f16.f32 "
        "{%0,%1,%2,%3}, {%4,%5,%6,%7}, {%8,%9}, {%0,%1,%2,%3};"
        : "+f"(d[0]), "+f"(d[1]), "+f"(d[2]), "+f"(d[3])
        : "r"(a[0]), "r"(a[1]), "r"(a[2]), "r"(a[3]), "r"(b0), "r"(b1));
}
__device__ __forceinline__ void cp16(uint32_t dst, const void* src, uint32_t sz) {
    asm volatile("cp.async.cg.shared.global [%0], [%1], 16, %2;"
        :: "r"(dst), "l"(src), "r"(sz) : "memory");
}
#define CP_COMMIT() asm volatile("cp.async.commit_group;" ::: "memory")
#define CP_WAIT(n)  asm volatile("cp.async.wait_group %0;" :: "n"(n) : "memory")

// pipeline geometry: K-chunk = 64
#define NSTAGE 3
#define PA_B 144
#define PB_B 272
#define STG_A 18432
#define STG_B 17408
#define STG_BYTES (STG_A + STG_B)
#define SMEM_DYN (1024 + NSTAGE * STG_BYTES)   // 108544

struct GemmArgs {
    const __half* A; int lda; const int* gather; int valid;
    const __half* W; int ldw; int n0;
    int K;
    const float* bias;
    const float* rowScale;   // nullable
    __half* outH;
    int ldo;
    bool silu;
};

__device__ __forceinline__ void gemm128(const GemmArgs g) {
    extern __shared__ char smc[];
    int*   rows_s  = (int*)smc;
    float* scale_s = (float*)(smc + 512);
    const uint32_t sbase = smem_u32(smc);

    const int tid = threadIdx.x;
    const int lane = tid & 31, w = tid >> 5;
    const int mw = w & 3, nw = w >> 2;
    const int gg = lane >> 2, cc = lane & 3;
    const int arow = (lane & 7) + ((lane >> 3) & 1) * 8;
    const int kh = (lane >> 4) & 1;

    if (tid < 128) {
        bool v = tid < g.valid;
        rows_s[tid]  = g.gather ? (v ? g.gather[tid] : -1) : (v ? tid : -1);
        scale_s[tid] = (g.rowScale && v) ? g.rowScale[tid] : 1.0f;
    }
    __syncthreads();

    const __half* asrc[4]; uint32_t aoff[4], asz[4];
    const __half* bsrc[4]; uint32_t boff[4];
#pragma unroll
    for (int i = 0; i < 4; i++) {
        int idx = tid + i * 256;
        int r = idx >> 3, c = idx & 7;
        int gr = rows_s[r];
        asrc[i] = g.A + (gr >= 0 ? (size_t)gr * g.lda : 0) + c * 8;
        asz[i]  = (gr >= 0) ? 16u : 0u;
        aoff[i] = (uint32_t)(r * PA_B + c * 16);
        int k = idx >> 4, bc = idx & 15;
        bsrc[i] = g.W + (size_t)k * g.ldw + g.n0 + bc * 8;
        boff[i] = (uint32_t)(STG_A + k * PB_B + bc * 16);
    }

    float acc[2][8][4];
#pragma unroll
    for (int i = 0; i < 2; i++)
#pragma unroll
        for (int j = 0; j < 8; j++)
#pragma unroll
            for (int q = 0; q < 4; q++) acc[i][j][q] = 0.0f;

    const int nch = g.K >> 6;

    auto issue = [&](int chunk, int st) {
        uint32_t sb = sbase + 1024u + (uint32_t)st * STG_BYTES;
        int k0 = chunk << 6;
        size_t bstep = (size_t)k0 * g.ldw;
#pragma unroll
        for (int i = 0; i < 4; i++) cp16(sb + aoff[i], asrc[i] + k0, asz[i]);
#pragma unroll
        for (int i = 0; i < 4; i++) cp16(sb + boff[i], bsrc[i] + bstep, 16u);
    };

    issue(0, 0); CP_COMMIT();
    if (nch > 1) issue(1, 1);
    CP_COMMIT();

    int stcur = 0;
    int stp = (nch > 2) ? 2 : 0;
    for (int c = 0; c < nch; c++) {
        CP_WAIT(1);
        __syncthreads();
        const uint32_t sb = sbase + 1024u + (uint32_t)stcur * STG_BYTES;
        if (++stcur == NSTAGE) stcur = 0;
        if (c + 2 < nch) {
            issue(c + 2, stp);
            if (++stp == NSTAGE) stp = 0;
        }
        CP_COMMIT();
        const uint32_t Ab = sb, Bb = sb + STG_A;
#pragma unroll
        for (int ks = 0; ks < 4; ks++) {
            uint32_t a[2][4], bf[8][2];
#pragma unroll
            for (int ma = 0; ma < 2; ma++) {
                uint32_t addr = Ab + (uint32_t)((mw * 32 + ma * 16 + arow) * PA_B + ks * 32 + kh * 16);
                ldsm_x4(a[ma], addr);
            }
#pragma unroll
            for (int p = 0; p < 4; p++) {
                uint32_t r4[4];
                uint32_t addr = Bb + (uint32_t)((ks * 16 + arow) * PB_B + (nw * 64 + p * 16 + kh * 8) * 2);
                ldsm_x4_trans(r4, addr);
                bf[2 * p][0] = r4[0]; bf[2 * p][1] = r4[1];
                bf[2 * p + 1][0] = r4[2]; bf[2 * p + 1][1] = r4[3];
            }
#pragma unroll
            for (int ma = 0; ma < 2; ma++)
#pragma unroll
                for (int nb = 0; nb < 8; nb++)
                    mma_fp16(acc[ma][nb], a[ma], bf[nb][0], bf[nb][1]);
        }
    }
    CP_WAIT(0);

    // direct register epilogue
#pragma unroll
    for (int ma = 0; ma < 2; ma++) {
        int r0 = mw * 32 + ma * 16 + gg, r1 = r0 + 8;
        float s0 = scale_s[r0], s1 = scale_s[r1];
        bool v0 = r0 < g.valid, v1 = r1 < g.valid;
#pragma unroll
        for (int nb = 0; nb < 8; nb++) {
            int n = g.n0 + nw * 64 + nb * 8 + cc * 2;
            float bv0 = g.bias[n], bv1 = g.bias[n + 1];
            float f0 = acc[ma][nb][0] + bv0;
            float f1 = acc[ma][nb][1] + bv1;
            float f2 = acc[ma][nb][2] + bv0;
            float f3 = acc[ma][nb][3] + bv1;
            if (g.silu) { f0 = silu_f(f0); f1 = silu_f(f1); f2 = silu_f(f2); f3 = silu_f(f3); }
            if (v0) {
                __half2 h = __floats2half2_rn(f0 * s0, f1 * s0);
                *(__half2*)(g.outH + (size_t)r0 * g.ldo + n) = h;
            }
            if (v1) {
                __half2 h = __floats2half2_rn(f2 * s1, f3 * s1);
                *(__half2*)(g.outH + (size_t)r1 * g.ldo + n) = h;
            }
        }
    }
}

// ---------------- GEMM kernels ----------------
__global__ void __launch_bounds__(256, 2) shared_g1_kernel(const float* sb1) {
    int bx = blockIdx.x;            // 512 blocks
    int es = bx >> 8, idx = bx & 255;
    int row0 = (idx & 15) * 128, n0 = (idx >> 4) * 128;
    GemmArgs a;
    a.A = g_x16 + (size_t)row0 * Dm; a.lda = Dm; a.gather = nullptr; a.valid = 128;
    a.W = g_sw116 + (size_t)es * Dm * HSn; a.ldw = HSn; a.n0 = n0;
    a.K = Dm; a.bias = sb1 + (size_t)es * HSn; a.rowScale = nullptr;
    a.outH = g_Hs16 + (size_t)es * Tn * HSn + (size_t)row0 * HSn; a.ldo = HSn; a.silu = true;
    gemm128(a);
}
__global__ void __launch_bounds__(256, 2) routed_g1_kernel(const float* b1) {
    int q = blockIdx.x;             // 512 blocks
    int t = q & 255, ny = q >> 8;   // ny in {0,1}
    if (t >= g_ntiles) return;
    int e = g_tile_e[t], rb = g_tile_row[t];
    int cnt = g_count[e], off = g_offset[e];
    GemmArgs a;
    a.A = g_x16; a.lda = Dm; a.gather = g_pair_token + off + rb; a.valid = min(128, cnt - rb);
    a.W = g_w116 + (size_t)e * Dm * Hh; a.ldw = Hh; a.n0 = ny * 128;
    a.K = Dm; a.bias = b1 + e * Hh; a.rowScale = nullptr;
    a.outH = g_H16 + (size_t)(off + rb) * Hh; a.ldo = Hh; a.silu = true;
    gemm128(a);
}
__global__ void __launch_bounds__(256, 2) phase2_kernel(const float* b2, const float* sb2) {
    int bx = blockIdx.x;
    GemmArgs a;
    if (bx < 256) {
        int es = bx >> 7, idx = bx & 127;
        int row0 = (idx & 15) * 128, n0 = (idx >> 4) * 128;
        a.A = g_Hs16 + (size_t)es * Tn * HSn + (size_t)row0 * HSn; a.lda = HSn; a.gather = nullptr; a.valid = 128;
        a.W = g_sw216 + (size_t)es * HSn * Dm; a.ldw = Dm; a.n0 = n0;
        a.K = HSn; a.bias = sb2 + (size_t)es * Dm; a.rowScale = nullptr;
        a.outH = g_sharedout16 + (size_t)es * Tn * Dm + (size_t)row0 * Dm; a.ldo = Dm; a.silu = false;
        gemm128(a);
    } else {
        int q = bx - 256;
        int t = q & 255, ny = q >> 8;   // ny in {0..7}
        if (t >= g_ntiles) return;
        int e = g_tile_e[t], rb = g_tile_row[t];
        int cnt = g_count[e], off = g_offset[e];
        a.A = g_H16 + (size_t)(off + rb) * Hh; a.lda = Hh; a.gather = nullptr; a.valid = min(128, cnt - rb);
        a.W = g_w216 + (size_t)e * Hh * Dm; a.ldw = Dm; a.n0 = ny * 128;
        a.K = Hh; a.bias = b2 + (size_t)e * Dm; a.rowScale = g_pair_w + off + rb;
        a.outH = g_pairout16 + (size_t)(off + rb) * Dm; a.ldo = Dm; a.silu = false;
        gemm128(a);
    }
}

// ---------------- fp32 -> fp16 conversion ----------------
__global__ void __launch_bounds__(256) conv_kernel(const float* __restrict__ src, __half* __restrict__ dst, int n4) {
    for (int i = blockIdx.x * 256 + threadIdx.x; i < n4; i += gridDim.x * 256) {
        float4 v = *(const float4*)(src + (size_t)i * 4);
        __half2 h0 = __floats2half2_rn(v.x, v.y);
        __half2 h1 = __floats2half2_rn(v.z, v.w);
        uint32_t u0 = *(uint32_t*)&h0;
        uint32_t u1 = *(uint32_t*)&h1;
        *(uint2*)(dst + (size_t)i * 4) = make_uint2(u0, u1);
    }
}

// ---------------- routing bookkeeping ----------------
__global__ void zero_counts_kernel() {
    if (threadIdx.x < Ne) g_count[threadIdx.x] = 0;
}

__global__ void __launch_bounds__(256) router_kernel(
    const float* __restrict__ x, const float* __restrict__ rw, const float* __restrict__ rb)
{
    __shared__ float xs[64][33];
    __shared__ float ws[64][65];
    __shared__ float lg[32][65];
    int tid = threadIdx.x;
    int tbase = blockIdx.x * 32;
    int e = tid & 63, tg = tid >> 6;
    float acc[8];
#pragma unroll
    for (int i = 0; i < 8; i++) acc[i] = 0.0f;
    for (int d0 = 0; d0 < Dm; d0 += 64) {
#pragma unroll
        for (int q = 0; q < 8; q++) {
            int idx = tid + q * 256; int t = idx >> 6, dd = idx & 63;
            xs[dd][t] = x[(size_t)(tbase + t) * Dm + d0 + dd];
        }
#pragma unroll
        for (int q = 0; q < 16; q++) {
            int idx = tid + q * 256; int dd = idx >> 6, ee = idx & 63;
            ws[dd][ee] = rw[(size_t)(d0 + dd) * Ne + ee];
        }
        __syncthreads();
#pragma unroll
        for (int dd = 0; dd < 64; dd++) {
            float wv = ws[dd][e];
#pragma unroll
            for (int i = 0; i < 8; i++) acc[i] += xs[dd][tg + 4 * i] * wv;
        }
        __syncthreads();
    }
#pragma unroll
    for (int i = 0; i < 8; i++) lg[tg + 4 * i][e] = acc[i] + rb[e];
    __syncthreads();
    if (tid < 32) {
        int t = tid;
        float vals[TOPK]; int idxs[TOPK];
#pragma unroll
        for (int p = 0; p < TOPK; p++) {
            float best = -1e30f; int bi = 0;
            for (int ee = 0; ee < Ne; ee++) {
                float v = lg[t][ee];
                if (v > best) { best = v; bi = ee; }
            }
            vals[p] = best; idxs[p] = bi; lg[t][bi] = -1e30f;
        }
        float m = vals[0], wv[TOPK], s = 0.0f;
#pragma unroll
        for (int p = 0; p < TOPK; p++) { wv[p] = __expf(vals[p] - m); s += wv[p]; }
        float inv = 1.0f / s;
        int gt = tbase + t;
#pragma unroll
        for (int p = 0; p < TOPK; p++) {
            g_topw[gt * TOPK + p] = wv[p] * inv;
            g_topi[gt * TOPK + p] = idxs[p];
            atomicAdd(&g_count[idxs[p]], 1);
        }
    }
}

__global__ void scan_kernel() {
    if (threadIdx.x == 0) {
        int run = 0, nt = 0;
        for (int e = 0; e < Ne; e++) {
            g_offset[e] = run; g_cursor[e] = run;
            int c = g_count[e];
            int tiles = (c + 127) >> 7;
            for (int i = 0; i < tiles; i++) { g_tile_e[nt] = e; g_tile_row[nt] = i * 128; nt++; }
            run += c;
        }
        g_ntiles = nt;
    }
}

// one thread per (token, slot) pair
__global__ void fill_kernel() {
    int idx = blockIdx.x * 256 + threadIdx.x;
    if (idx < MAXP) {
        int e = g_topi[idx];
        int pos = atomicAdd(&g_cursor[e], 1);
        g_pair_token[pos] = idx >> 3;
        g_pair_w[pos] = g_topw[idx];
        g_slot2pair[idx] = pos;
    }
}

// ---------------- combine ----------------
__global__ void __launch_bounds__(256) combine_kernel(float* __restrict__ out) {
    int t = blockIdx.x, tid = threadIdx.x;
    __shared__ int sp[TOPK];
    if (tid < TOPK) sp[tid] = g_slot2pair[t * TOPK + tid];
    __syncthreads();
    float acc0, acc1, acc2, acc3;
    {
        uint2 u = *(const uint2*)(g_sharedout16 + (size_t)t * Dm + tid * 4);
        __half2 h0 = *(__half2*)&u.x, h1 = *(__half2*)&u.y;
        float2 f0 = __half22float2(h0), f1 = __half22float2(h1);
        acc0 = f0.x; acc1 = f0.y; acc2 = f1.x; acc3 = f1.y;
    }
    {
        uint2 u = *(const uint2*)(g_sharedout16 + (size_t)Tn * Dm + (size_t)t * Dm + tid * 4);
        __half2 h0 = *(__half2*)&u.x, h1 = *(__half2*)&u.y;
        float2 f0 = __half22float2(h0), f1 = __half22float2(h1);
        acc0 += f0.x; acc1 += f0.y; acc2 += f1.x; acc3 += f1.y;
    }
#pragma unroll
    for (int j = 0; j < TOPK; j++) {
        uint2 u = *(const uint2*)(g_pairout16 + (size_t)sp[j] * Dm + tid * 4);
        __half2 h0 = *(__half2*)&u.x, h1 = *(__half2*)&u.y;
        float2 f0 = __half22float2(h0), f1 = __half22float2(h1);
        acc0 += f0.x; acc1 += f0.y; acc2 += f1.x; acc3 += f1.y;
    }
    *(float4*)(out + (size_t)t * Dm + tid * 4) = make_float4(acc0, acc1, acc2, acc3);
}

// ---------------- launch ----------------
extern "C" void kernel_launch(void* const* d_in, const int* in_sizes, int n_in,
                              void* d_out, int out_size)
{
    const float* x   = (const float*)d_in[0];
    const float* rw  = (const float*)d_in[1];
    const float* rb  = (const float*)d_in[2];
    const float* w1  = (const float*)d_in[3];
    const float* b1  = (const float*)d_in[4];
    const float* w2  = (const float*)d_in[5];
    const float* b2  = (const float*)d_in[6];
    const float* sw1 = (const float*)d_in[7];
    const float* sb1 = (const float*)d_in[8];
    const float* sw2 = (const float*)d_in[9];
    const float* sb2 = (const float*)d_in[10];
    float* out = (float*)d_out;

    cudaFuncSetAttribute(shared_g1_kernel, cudaFuncAttributeMaxDynamicSharedMemorySize, SMEM_DYN);
    cudaFuncSetAttribute(routed_g1_kernel, cudaFuncAttributeMaxDynamicSharedMemorySize, SMEM_DYN);
    cudaFuncSetAttribute(phase2_kernel,    cudaFuncAttributeMaxDynamicSharedMemorySize, SMEM_DYN);

    __half* x16  = nullptr; cudaGetSymbolAddress((void**)&x16,  g_x16);
    __half* w116 = nullptr; cudaGetSymbolAddress((void**)&w116, g_w116);
    __half* w216 = nullptr; cudaGetSymbolAddress((void**)&w216, g_w216);
    __half* s116 = nullptr; cudaGetSymbolAddress((void**)&s116, g_sw116);
    __half* s216 = nullptr; cudaGetSymbolAddress((void**)&s216, g_sw216);

    static cudaStream_t sA = nullptr, sB = nullptr, sC = nullptr;
    static cudaEvent_t evRoot = nullptr, evA = nullptr, evB = nullptr, evC = nullptr, evSG1 = nullptr;
    if (!sA) {
        cudaStreamCreateWithFlags(&sA, cudaStreamNonBlocking);
        cudaStreamCreateWithFlags(&sB, cudaStreamNonBlocking);
        cudaStreamCreateWithFlags(&sC, cudaStreamNonBlocking);
        cudaEventCreateWithFlags(&evRoot, cudaEventDisableTiming);
        cudaEventCreateWithFlags(&evA, cudaEventDisableTiming);
        cudaEventCreateWithFlags(&evB, cudaEventDisableTiming);
        cudaEventCreateWithFlags(&evC, cudaEventDisableTiming);
        cudaEventCreateWithFlags(&evSG1, cudaEventDisableTiming);
    }

    // fork
    cudaEventRecord(evRoot, 0);
    cudaStreamWaitEvent(sA, evRoot, 0);
    cudaStreamWaitEvent(sB, evRoot, 0);
    cudaStreamWaitEvent(sC, evRoot, 0);

    // main stream: routing chain
    zero_counts_kernel<<<1, 64>>>();
    router_kernel<<<Tn / 32, 256>>>(x, rw, rb);
    scan_kernel<<<1, 32>>>();
    fill_kernel<<<MAXP / 256, 256>>>();

    // stream A: operands for shared_g1 (small, fast) then shared_g1 itself
    conv_kernel<<<1024, 256, 0, sA>>>(x,   x16,  Tn * Dm / 4);
    conv_kernel<<<1024, 256, 0, sA>>>(sw1, s116, ESn * Dm * HSn / 4);
    shared_g1_kernel<<<512, 256, SMEM_DYN, sA>>>(sb1);
    cudaEventRecord(evSG1, sA);

    // stream B: w1 conversion (gates routed_g1)
    conv_kernel<<<2048, 256, 0, sB>>>(w1, w116, Ne * Dm * Hh / 4);
    cudaEventRecord(evB, sB);

    // stream C: phase2 weight conversions (overlap g1 work)
    conv_kernel<<<2048, 256, 0, sC>>>(w2,  w216, Ne * Hh * Dm / 4);
    conv_kernel<<<2048, 256, 0, sC>>>(sw2, s216, ESn * HSn * Dm / 4);
    cudaEventRecord(evC, sC);

    // routed_g1 on main: after routing chain (program order) + w116
    cudaStreamWaitEvent(0, evB, 0);
    routed_g1_kernel<<<512, 256, SMEM_DYN>>>(b1);

    // phase2: after routed_g1 (program order) + shared_g1 + w2/sw2 conv
    cudaStreamWaitEvent(0, evSG1, 0);
    cudaStreamWaitEvent(0, evC, 0);
    phase2_kernel<<<2304, 256, SMEM_DYN>>>(b2, sb2);

    combine_kernel<<<Tn, 256>>>(out);
}

// round 15
// speedup vs baseline: 5.0486x; 1.0599x over previous
#include <cuda_runtime.h>
#include <cuda_fp16.h>
#include <cstdint>
#include <math.h>

#define Tn   2048
#define Dm   1024
#define Ne   64
#define TOPK 8
#define Hh   256
#define ESn  2
#define HSn  2048
#define MAXP (Tn * TOPK)
#define MAXTILES 256

// ---------------- static scratch ----------------
__device__ float g_topw[MAXP];
__device__ int   g_topi[MAXP];
__device__ int   g_slot2pair[MAXP];
__device__ int   g_count[Ne];
__device__ int   g_offset[Ne];
__device__ int   g_cursor[Ne];
__device__ int   g_pair_token[MAXP];
__device__ float g_pair_w[MAXP];
__device__ int   g_ntiles;
__device__ int   g_tile_e[MAXTILES];
__device__ int   g_tile_row[MAXTILES];
__device__ __half g_pairout16[(size_t)MAXP * Dm];
__device__ __half g_sharedout16[(size_t)ESn * Tn * Dm];
__device__ __half g_H16[(size_t)MAXP * Hh];
__device__ __half g_Hs16[(size_t)ESn * Tn * HSn];
// fp16 operand copies
__device__ __half g_x16[(size_t)Tn * Dm];
__device__ __half g_w116[(size_t)Ne * Dm * Hh];
__device__ __half g_w216[(size_t)Ne * Hh * Dm];
__device__ __half g_sw116[(size_t)ESn * Dm * HSn];
__device__ __half g_sw216[(size_t)ESn * HSn * Dm];

__device__ __forceinline__ uint32_t smem_u32(const void* p) {
    uint32_t a;
    asm("{ .reg .u64 t; cvta.to.shared.u64 t, %1; cvt.u32.u64 %0, t; }" : "=r"(a) : "l"(p));
    return a;
}
__device__ __forceinline__ float silu_f(float c) { return c / (1.0f + __expf(-c)); }

__device__ __forceinline__ void ldsm_x4(uint32_t* r, uint32_t addr) {
    asm volatile("ldmatrix.sync.aligned.m8n8.x4.shared.b16 {%0,%1,%2,%3}, [%4];"
        : "=r"(r[0]), "=r"(r[1]), "=r"(r[2]), "=r"(r[3]) : "r"(addr));
}
__device__ __forceinline__ void ldsm_x4_trans(uint32_t* r, uint32_t addr) {
    asm volatile("ldmatrix.sync.aligned.m8n8.x4.trans.shared.b16 {%0,%1,%2,%3}, [%4];"
        : "=r"(r[0]), "=r"(r[1]), "=r"(r[2]), "=r"(r[3]) : "r"(addr));
}
__device__ __forceinline__ void mma_fp16(float* d, const uint32_t* a, uint32_t b0, uint32_t b1) {
    asm volatile(
        "mma.sync.aligned.m16n8k16.row.col.f32.f16.f16.f32 "
        "{%0,%1,%2,%3}, {%4,%5,%6,%7}, {%8,%9}, {%0,%1,%2,%3};"
        : "+f"(d[0]), "+f"(d[1]), "+f"(d[2]), "+f"(d[3])
        : "r"(a[0]), "r"(a[1]), "r"(a[2]), "r"(a[3]), "r"(b0), "r"(b1));
}
__device__ __forceinline__ void cp16(uint32_t dst, const void* src, uint32_t sz) {
    asm volatile("cp.async.cg.shared.global [%0], [%1], 16, %2;"
        :: "r"(dst), "l"(src), "r"(sz) : "memory");
}
#define CP_COMMIT() asm volatile("cp.async.commit_group;" ::: "memory")
#define CP_WAIT(n)  asm volatile("cp.async.wait_group %0;" :: "n"(n) : "memory")

// pipeline geometry: K-chunk = 64
#define NSTAGE 3
#define PA_B 144
#define PB_B 272
#define STG_A 18432
#define STG_B 17408
#define STG_BYTES (STG_A + STG_B)
#define SMEM_DYN (1024 + NSTAGE * STG_BYTES)   // 108544

struct GemmArgs {
    const __half* A; int lda; const int* gather; int valid;
    const __half* W; int ldw; int n0;
    int K;
    const float* bias;
    const float* rowScale;   // nullable
    __half* outH;
    int ldo;
    bool silu;
};

__device__ __forceinline__ void gemm128(const GemmArgs g) {
    extern __shared__ char smc[];
    int*   rows_s  = (int*)smc;
    float* scale_s = (float*)(smc + 512);
    const uint32_t sbase = smem_u32(smc);

    const int tid = threadIdx.x;
    const int lane = tid & 31, w = tid >> 5;
    const int mw = w & 3, nw = w >> 2;
    const int gg = lane >> 2, cc = lane & 3;
    const int arow = (lane & 7) + ((lane >> 3) & 1) * 8;
    const int kh = (lane >> 4) & 1;

    if (tid < 128) {
        bool v = tid < g.valid;
        rows_s[tid]  = g.gather ? (v ? g.gather[tid] : -1) : (v ? tid : -1);
        scale_s[tid] = (g.rowScale && v) ? g.rowScale[tid] : 1.0f;
    }
    __syncthreads();

    const __half* asrc[4]; uint32_t aoff[4], asz[4];
    const __half* bsrc[4]; uint32_t boff[4];
#pragma unroll
    for (int i = 0; i < 4; i++) {
        int idx = tid + i * 256;
        int r = idx >> 3, c = idx & 7;
        int gr = rows_s[r];
        asrc[i] = g.A + (gr >= 0 ? (size_t)gr * g.lda : 0) + c * 8;
        asz[i]  = (gr >= 0) ? 16u : 0u;
        aoff[i] = (uint32_t)(r * PA_B + c * 16);
        int k = idx >> 4, bc = idx & 15;
        bsrc[i] = g.W + (size_t)k * g.ldw + g.n0 + bc * 8;
        boff[i] = (uint32_t)(STG_A + k * PB_B + bc * 16);
    }

    float acc[2][8][4];
#pragma unroll
    for (int i = 0; i < 2; i++)
#pragma unroll
        for (int j = 0; j < 8; j++)
#pragma unroll
            for (int q = 0; q < 4; q++) acc[i][j][q] = 0.0f;

    const int nch = g.K >> 6;

    auto issue = [&](int chunk, int st) {
        uint32_t sb = sbase + 1024u + (uint32_t)st * STG_BYTES;
        int k0 = chunk << 6;
        size_t bstep = (size_t)k0 * g.ldw;
#pragma unroll
        for (int i = 0; i < 4; i++) cp16(sb + aoff[i], asrc[i] + k0, asz[i]);
#pragma unroll
        for (int i = 0; i < 4; i++) cp16(sb + boff[i], bsrc[i] + bstep, 16u);
    };

    issue(0, 0); CP_COMMIT();
    if (nch > 1) issue(1, 1);
    CP_COMMIT();

    int stcur = 0;
    int stp = (nch > 2) ? 2 : 0;
    for (int c = 0; c < nch; c++) {
        CP_WAIT(1);
        __syncthreads();
        const uint32_t sb = sbase + 1024u + (uint32_t)stcur * STG_BYTES;
        if (++stcur == NSTAGE) stcur = 0;
        if (c + 2 < nch) {
            issue(c + 2, stp);
            if (++stp == NSTAGE) stp = 0;
        }
        CP_COMMIT();
        const uint32_t Ab = sb, Bb = sb + STG_A;
#pragma unroll
        for (int ks = 0; ks < 4; ks++) {
            uint32_t a[2][4], bf[8][2];
#pragma unroll
            for (int ma = 0; ma < 2; ma++) {
                uint32_t addr = Ab + (uint32_t)((mw * 32 + ma * 16 + arow) * PA_B + ks * 32 + kh * 16);
                ldsm_x4(a[ma], addr);
            }
#pragma unroll
            for (int p = 0; p < 4; p++) {
                uint32_t r4[4];
                uint32_t addr = Bb + (uint32_t)((ks * 16 + arow) * PB_B + (nw * 64 + p * 16 + kh * 8) * 2);
                ldsm_x4_trans(r4, addr);
                bf[2 * p][0] = r4[0]; bf[2 * p][1] = r4[1];
                bf[2 * p + 1][0] = r4[2]; bf[2 * p + 1][1] = r4[3];
            }
#pragma unroll
            for (int ma = 0; ma < 2; ma++)
#pragma unroll
                for (int nb = 0; nb < 8; nb++)
                    mma_fp16(acc[ma][nb], a[ma], bf[nb][0], bf[nb][1]);
        }
    }
    CP_WAIT(0);

    // direct register epilogue
#pragma unroll
    for (int ma = 0; ma < 2; ma++) {
        int r0 = mw * 32 + ma * 16 + gg, r1 = r0 + 8;
        float s0 = scale_s[r0], s1 = scale_s[r1];
        bool v0 = r0 < g.valid, v1 = r1 < g.valid;
#pragma unroll
        for (int nb = 0; nb < 8; nb++) {
            int n = g.n0 + nw * 64 + nb * 8 + cc * 2;
            float bv0 = g.bias[n], bv1 = g.bias[n + 1];
            float f0 = acc[ma][nb][0] + bv0;
            float f1 = acc[ma][nb][1] + bv1;
            float f2 = acc[ma][nb][2] + bv0;
            float f3 = acc[ma][nb][3] + bv1;
            if (g.silu) { f0 = silu_f(f0); f1 = silu_f(f1); f2 = silu_f(f2); f3 = silu_f(f3); }
            if (v0) {
                __half2 h = __floats2half2_rn(f0 * s0, f1 * s0);
                *(__half2*)(g.outH + (size_t)r0 * g.ldo + n) = h;
            }
            if (v1) {
                __half2 h = __floats2half2_rn(f2 * s1, f3 * s1);
                *(__half2*)(g.outH + (size_t)r1 * g.ldo + n) = h;
            }
        }
    }
}

// ---------------- GEMM kernels ----------------
__global__ void __launch_bounds__(256, 2) shared_g1_kernel(const float* sb1) {
    int bx = blockIdx.x;            // 512 blocks
    int es = bx >> 8, idx = bx & 255;
    int row0 = (idx & 15) * 128, n0 = (idx >> 4) * 128;
    GemmArgs a;
    a.A = g_x16 + (size_t)row0 * Dm; a.lda = Dm; a.gather = nullptr; a.valid = 128;
    a.W = g_sw116 + (size_t)es * Dm * HSn; a.ldw = HSn; a.n0 = n0;
    a.K = Dm; a.bias = sb1 + (size_t)es * HSn; a.rowScale = nullptr;
    a.outH = g_Hs16 + (size_t)es * Tn * HSn + (size_t)row0 * HSn; a.ldo = HSn; a.silu = true;
    gemm128(a);
}
__global__ void __launch_bounds__(256, 2) routed_g1_kernel(const float* b1) {
    int q = blockIdx.x;             // 512 blocks
    int t = q & 255, ny = q >> 8;   // ny in {0,1}
    if (t >= g_ntiles) return;
    int e = g_tile_e[t], rb = g_tile_row[t];
    int cnt = g_count[e], off = g_offset[e];
    GemmArgs a;
    a.A = g_x16; a.lda = Dm; a.gather = g_pair_token + off + rb; a.valid = min(128, cnt - rb);
    a.W = g_w116 + (size_t)e * Dm * Hh; a.ldw = Hh; a.n0 = ny * 128;
    a.K = Dm; a.bias = b1 + e * Hh; a.rowScale = nullptr;
    a.outH = g_H16 + (size_t)(off + rb) * Hh; a.ldo = Hh; a.silu = true;
    gemm128(a);
}
__global__ void __launch_bounds__(256, 2) shared_g2_kernel(const float* sb2) {
    int bx = blockIdx.x;            // 256 blocks
    int es = bx >> 7, idx = bx & 127;
    int row0 = (idx & 15) * 128, n0 = (idx >> 4) * 128;
    GemmArgs a;
    a.A = g_Hs16 + (size_t)es * Tn * HSn + (size_t)row0 * HSn; a.lda = HSn; a.gather = nullptr; a.valid = 128;
    a.W = g_sw216 + (size_t)es * HSn * Dm; a.ldw = Dm; a.n0 = n0;
    a.K = HSn; a.bias = sb2 + (size_t)es * Dm; a.rowScale = nullptr;
    a.outH = g_sharedout16 + (size_t)es * Tn * Dm + (size_t)row0 * Dm; a.ldo = Dm; a.silu = false;
    gemm128(a);
}
__global__ void __launch_bounds__(256, 2) routed_g2_kernel(const float* b2) {
    int q = blockIdx.x;             // 2048 blocks
    int t = q & 255, ny = q >> 8;   // ny in {0..7}
    if (t >= g_ntiles) return;
    int e = g_tile_e[t], rb = g_tile_row[t];
    int cnt = g_count[e], off = g_offset[e];
    GemmArgs a;
    a.A = g_H16 + (size_t)(off + rb) * Hh; a.lda = Hh; a.gather = nullptr; a.valid = min(128, cnt - rb);
    a.W = g_w216 + (size_t)e * Hh * Dm; a.ldw = Dm; a.n0 = ny * 128;
    a.K = Hh; a.bias = b2 + (size_t)e * Dm; a.rowScale = g_pair_w + off + rb;
    a.outH = g_pairout16 + (size_t)(off + rb) * Dm; a.ldo = Dm; a.silu = false;
    gemm128(a);
}

// ---------------- fp32 -> fp16 conversion ----------------
__global__ void __launch_bounds__(256) conv_kernel(const float* __restrict__ src, __half* __restrict__ dst, int n4) {
    for (int i = blockIdx.x * 256 + threadIdx.x; i < n4; i += gridDim.x * 256) {
        float4 v = *(const float4*)(src + (size_t)i * 4);
        __half2 h0 = __floats2half2_rn(v.x, v.y);
        __half2 h1 = __floats2half2_rn(v.z, v.w);
        uint32_t u0 = *(uint32_t*)&h0;
        uint32_t u1 = *(uint32_t*)&h1;
        *(uint2*)(dst + (size_t)i * 4) = make_uint2(u0, u1);
    }
}

// ---------------- routing bookkeeping ----------------
__global__ void zero_counts_kernel() {
    if (threadIdx.x < Ne) g_count[threadIdx.x] = 0;
}

__global__ void __launch_bounds__(256) router_kernel(
    const float* __restrict__ x, const float* __restrict__ rw, const float* __restrict__ rb)
{
    __shared__ float xs[64][33];
    __shared__ float ws[64][65];
    __shared__ float lg[32][65];
    int tid = threadIdx.x;
    int tbase = blockIdx.x * 32;
    int e = tid & 63, tg = tid >> 6;
    float acc[8];
#pragma unroll
    for (int i = 0; i < 8; i++) acc[i] = 0.0f;
    for (int d0 = 0; d0 < Dm; d0 += 64) {
#pragma unroll
        for (int q = 0; q < 8; q++) {
            int idx = tid + q * 256; int t = idx >> 6, dd = idx & 63;
            xs[dd][t] = x[(size_t)(tbase + t) * Dm + d0 + dd];
        }
#pragma unroll
        for (int q = 0; q < 16; q++) {
            int idx = tid + q * 256; int dd = idx >> 6, ee = idx & 63;
            ws[dd][ee] = rw[(size_t)(d0 + dd) * Ne + ee];
        }
        __syncthreads();
#pragma unroll
        for (int dd = 0; dd < 64; dd++) {
            float wv = ws[dd][e];
#pragma unroll
            for (int i = 0; i < 8; i++) acc[i] += xs[dd][tg + 4 * i] * wv;
        }
        __syncthreads();
    }
#pragma unroll
    for (int i = 0; i < 8; i++) lg[tg + 4 * i][e] = acc[i] + rb[e];
    __syncthreads();
    if (tid < 32) {
        int t = tid;
        float vals[TOPK]; int idxs[TOPK];
#pragma unroll
        for (int p = 0; p < TOPK; p++) {
            float best = -1e30f; int bi = 0;
            for (int ee = 0; ee < Ne; ee++) {
                float v = lg[t][ee];
                if (v > best) { best = v; bi = ee; }
            }
            vals[p] = best; idxs[p] = bi; lg[t][bi] = -1e30f;
        }
        float m = vals[0], wv[TOPK], s = 0.0f;
#pragma unroll
        for (int p = 0; p < TOPK; p++) { wv[p] = __expf(vals[p] - m); s += wv[p]; }
        float inv = 1.0f / s;
        int gt = tbase + t;
#pragma unroll
        for (int p = 0; p < TOPK; p++) {
            g_topw[gt * TOPK + p] = wv[p] * inv;
            g_topi[gt * TOPK + p] = idxs[p];
            atomicAdd(&g_count[idxs[p]], 1);
        }
    }
}

__global__ void scan_kernel() {
    if (threadIdx.x == 0) {
        int run = 0, nt = 0;
        for (int e = 0; e < Ne; e++) {
            g_offset[e] = run; g_cursor[e] = run;
            int c = g_count[e];
            int tiles = (c + 127) >> 7;
            for (int i = 0; i < tiles; i++) { g_tile_e[nt] = e; g_tile_row[nt] = i * 128; nt++; }
            run += c;
        }
        g_ntiles = nt;
    }
}

// one thread per (token, slot) pair
__global__ void fill_kernel() {
    int idx = blockIdx.x * 256 + threadIdx.x;
    if (idx < MAXP) {
        int e = g_topi[idx];
        int pos = atomicAdd(&g_cursor[e], 1);
        g_pair_token[pos] = idx >> 3;
        g_pair_w[pos] = g_topw[idx];
        g_slot2pair[idx] = pos;
    }
}

// ---------------- combine ----------------
__global__ void __launch_bounds__(256) combine_kernel(float* __restrict__ out) {
    int t = blockIdx.x, tid = threadIdx.x;
    __shared__ int sp[TOPK];
    if (tid < TOPK) sp[tid] = g_slot2pair[t * TOPK + tid];
    __syncthreads();
    float acc0, acc1, acc2, acc3;
    {
        uint2 u = *(const uint2*)(g_sharedout16 + (size_t)t * Dm + tid * 4);
        __half2 h0 = *(__half2*)&u.x, h1 = *(__half2*)&u.y;
        float2 f0 = __half22float2(h0), f1 = __half22float2(h1);
        acc0 = f0.x; acc1 = f0.y; acc2 = f1.x; acc3 = f1.y;
    }
    {
        uint2 u = *(const uint2*)(g_sharedout16 + (size_t)Tn * Dm + (size_t)t * Dm + tid * 4);
        __half2 h0 = *(__half2*)&u.x, h1 = *(__half2*)&u.y;
        float2 f0 = __half22float2(h0), f1 = __half22float2(h1);
        acc0 += f0.x; acc1 += f0.y; acc2 += f1.x; acc3 += f1.y;
    }
#pragma unroll
    for (int j = 0; j < TOPK; j++) {
        uint2 u = *(const uint2*)(g_pairout16 + (size_t)sp[j] * Dm + tid * 4);
        __half2 h0 = *(__half2*)&u.x, h1 = *(__half2*)&u.y;
        float2 f0 = __half22float2(h0), f1 = __half22float2(h1);
        acc0 += f0.x; acc1 += f0.y; acc2 += f1.x; acc3 += f1.y;
    }
    *(float4*)(out + (size_t)t * Dm + tid * 4) = make_float4(acc0, acc1, acc2, acc3);
}

// ---------------- launch ----------------
extern "C" void kernel_launch(void* const* d_in, const int* in_sizes, int n_in,
                              void* d_out, int out_size)
{
    const float* x   = (const float*)d_in[0];
    const float* rw  = (const float*)d_in[1];
    const float* rb  = (const float*)d_in[2];
    const float* w1  = (const float*)d_in[3];
    const float* b1  = (const float*)d_in[4];
    const float* w2  = (const float*)d_in[5];
    const float* b2  = (const float*)d_in[6];
    const float* sw1 = (const float*)d_in[7];
    const float* sb1 = (const float*)d_in[8];
    const float* sw2 = (const float*)d_in[9];
    const float* sb2 = (const float*)d_in[10];
    float* out = (float*)d_out;

    cudaFuncSetAttribute(shared_g1_kernel, cudaFuncAttributeMaxDynamicSharedMemorySize, SMEM_DYN);
    cudaFuncSetAttribute(routed_g1_kernel, cudaFuncAttributeMaxDynamicSharedMemorySize, SMEM_DYN);
    cudaFuncSetAttribute(shared_g2_kernel, cudaFuncAttributeMaxDynamicSharedMemorySize, SMEM_DYN);
    cudaFuncSetAttribute(routed_g2_kernel, cudaFuncAttributeMaxDynamicSharedMemorySize, SMEM_DYN);

    __half* x16  = nullptr; cudaGetSymbolAddress((void**)&x16,  g_x16);
    __half* w116 = nullptr; cudaGetSymbolAddress((void**)&w116, g_w116);
    __half* w216 = nullptr; cudaGetSymbolAddress((void**)&w216, g_w216);
    __half* s116 = nullptr; cudaGetSymbolAddress((void**)&s116, g_sw116);
    __half* s216 = nullptr; cudaGetSymbolAddress((void**)&s216, g_sw216);

    static cudaStream_t sA = nullptr, sB = nullptr, sC = nullptr;
    static cudaEvent_t evRoot = nullptr, evB = nullptr, evC = nullptr, evSG2 = nullptr;
    if (!sA) {
        cudaStreamCreateWithFlags(&sA, cudaStreamNonBlocking);
        cudaStreamCreateWithFlags(&sB, cudaStreamNonBlocking);
        cudaStreamCreateWithFlags(&sC, cudaStreamNonBlocking);
        cudaEventCreateWithFlags(&evRoot, cudaEventDisableTiming);
        cudaEventCreateWithFlags(&evB, cudaEventDisableTiming);
        cudaEventCreateWithFlags(&evC, cudaEventDisableTiming);
        cudaEventCreateWithFlags(&evSG2, cudaEventDisableTiming);
    }

    // fork
    cudaEventRecord(evRoot, 0);
    cudaStreamWaitEvent(sA, evRoot, 0);
    cudaStreamWaitEvent(sB, evRoot, 0);
    cudaStreamWaitEvent(sC, evRoot, 0);

    // main stream: routing chain
    zero_counts_kernel<<<1, 64>>>();
    router_kernel<<<Tn / 32, 256>>>(x, rw, rb);
    scan_kernel<<<1, 32>>>();
    fill_kernel<<<MAXP / 256, 256>>>();

    // stream B: w1 conversion (gates routed_g1)
    conv_kernel<<<2048, 256, 0, sB>>>(w1, w116, Ne * Dm * Hh / 4);
    cudaEventRecord(evB, sB);

    // stream C: g2 weight conversions (overlap g1 work)
    conv_kernel<<<2048, 256, 0, sC>>>(w2,  w216, Ne * Hh * Dm / 4);
    conv_kernel<<<2048, 256, 0, sC>>>(sw2, s216, ESn * HSn * Dm / 4);
    cudaEventRecord(evC, sC);

    // stream A: shared chain (x, sw1 conv -> shared_g1 -> shared_g2)
    conv_kernel<<<1024, 256, 0, sA>>>(x,   x16,  Tn * Dm / 4);
    conv_kernel<<<1024, 256, 0, sA>>>(sw1, s116, ESn * Dm * HSn / 4);
    shared_g1_kernel<<<512, 256, SMEM_DYN, sA>>>(sb1);
    cudaStreamWaitEvent(sA, evC, 0);
    shared_g2_kernel<<<256, 256, SMEM_DYN, sA>>>(sb2);
    cudaEventRecord(evSG2, sA);

    // main: routed chain (needs routing bookkeeping + x16 via shared-stream order? no — x16 produced on sA)
    // routed_g1 needs x16: x conv completes early on sA; synchronize via evB? It needs its own event.
    // Use evB for w116 and rely on an explicit event for x16:
    // (x16 conv is first op on sA; shared_g1 on sA also needs it. For main we add a dedicated event.)
    cudaStreamWaitEvent(0, evB, 0);
    // x16-ready event: recorded on sA right after x conv. Need it declared; reuse evRoot is wrong.
    // NOTE: evX recorded below in setup order — see static block addition.
    {
        static cudaEvent_t evX = nullptr;
        if (!evX) cudaEventCreateWithFlags(&evX, cudaEventDisableTiming);
        // Re-record each call: event was recorded on sA after x conv? We must record it there.
        // Simplest correct ordering: main waits on the x-conv via an event recorded right after it.
        // To keep capture-safe ordering we record evX on sA *now* — it captures all sA work queued so far
        // (x conv, sw1 conv). sw1 conv adds ~5 us to routed_g1 start; acceptable.
        cudaEventRecord(evX, sA);
        cudaStreamWaitEvent(0, evX, 0);
    }
    routed_g1_kernel<<<512, 256, SMEM_DYN>>>(b1);
    cudaStreamWaitEvent(0, evC, 0);
    routed_g2_kernel<<<2048, 256, SMEM_DYN>>>(b2);

    // combine: after routed chain (program order) + shared chain
    cudaStreamWaitEvent(0, evSG2, 0);
    combine_kernel<<<Tn, 256>>>(out);
}